// round 10
// baseline (speedup 1.0000x reference)
#include <cuda_runtime.h>
#include <cuda_bf16.h>
#include <math.h>
#include <stdint.h>

#define B_   2
#define S_   2048
#define H_   2048
#define NH_  32
#define NKV_ 8
#define D_   64
#define QKVF ((NH_ + 2 * NKV_) * D_)   // 3072
#define GQA_ (NH_ / NKV_)              // 4

typedef __nv_bfloat16 bf16;

// ---------------------------------------------------------------------------
// Device scratch
// ---------------------------------------------------------------------------
__device__ float g_qkv[(size_t)B_ * S_ * QKVF];
__device__ bf16 g_hid_hi[(size_t)B_ * S_ * H_];
__device__ bf16 g_hid_lo[(size_t)B_ * S_ * H_];
__device__ bf16 g_wqkv_hi[(size_t)QKVF * H_];   // transposed [N][K]
__device__ bf16 g_wqkv_lo[(size_t)QKVF * H_];
__device__ bf16 g_wo_hi[(size_t)H_ * H_];       // transposed [N][K]
__device__ bf16 g_wo_lo[(size_t)H_ * H_];
__device__ bf16 g_q_hi[(size_t)B_ * NH_ * S_ * D_];
__device__ bf16 g_q_lo[(size_t)B_ * NH_ * S_ * D_];
__device__ bf16 g_k_hi[(size_t)B_ * NKV_ * S_ * D_];
__device__ bf16 g_k_lo[(size_t)B_ * NKV_ * S_ * D_];
__device__ bf16 g_vt_hi[(size_t)B_ * NKV_ * D_ * S_];
__device__ bf16 g_vt_lo[(size_t)B_ * NKV_ * D_ * S_];
__device__ bf16 g_ctx_hi[(size_t)B_ * S_ * NH_ * D_];
__device__ bf16 g_ctx_lo[(size_t)B_ * S_ * NH_ * D_];

// ---------------------------------------------------------------------------
// Helpers
// ---------------------------------------------------------------------------
__device__ __forceinline__ uint32_t smem_u32(const void* p) {
    return (uint32_t)__cvta_generic_to_shared(p);
}
__device__ __forceinline__ void cp_async16_sa(uint32_t sa, const void* g) {
    asm volatile("cp.async.cg.shared.global [%0], [%1], 16;\n" :: "r"(sa), "l"(g));
}
__device__ __forceinline__ void cp_commit() {
    asm volatile("cp.async.commit_group;\n");
}
__device__ __forceinline__ uint32_t pack2(float x, float y) {
    uint32_t r;
    asm("cvt.rn.bf16x2.f32 %0, %1, %2;" : "=r"(r) : "f"(y), "f"(x));
    return r;
}
__device__ __forceinline__ void split2(float x, float y, uint32_t& hi, uint32_t& lo) {
    hi = pack2(x, y);
    float hx = __uint_as_float(hi << 16);
    float hy = __uint_as_float(hi & 0xFFFF0000u);
    lo = pack2(x - hx, y - hy);
}
__device__ __forceinline__ void mma_bf16(float* c, const uint32_t* a,
                                         uint32_t b0, uint32_t b1) {
    asm volatile(
        "mma.sync.aligned.m16n8k16.row.col.f32.bf16.bf16.f32 "
        "{%0,%1,%2,%3},{%4,%5,%6,%7},{%8,%9},{%0,%1,%2,%3};"
        : "+f"(c[0]), "+f"(c[1]), "+f"(c[2]), "+f"(c[3])
        : "r"(a[0]), "r"(a[1]), "r"(a[2]), "r"(a[3]), "r"(b0), "r"(b1));
}
__device__ __forceinline__ void ldsm_x4(uint32_t addr, uint32_t* r) {
    asm volatile("ldmatrix.sync.aligned.m8n8.x4.shared.b16 {%0,%1,%2,%3}, [%4];"
                 : "=r"(r[0]), "=r"(r[1]), "=r"(r[2]), "=r"(r[3]) : "r"(addr));
}

// ---------------------------------------------------------------------------
// Pre-pass kernels
// ---------------------------------------------------------------------------
__global__ void split_kernel(const float* __restrict__ src,
                             uint2* __restrict__ hi, uint2* __restrict__ lo,
                             int n4) {
    int i = blockIdx.x * blockDim.x + threadIdx.x;
    if (i >= n4) return;
    float4 v = reinterpret_cast<const float4*>(src)[i];
    uint32_t h0, l0, h1, l1;
    split2(v.x, v.y, h0, l0);
    split2(v.z, v.w, h1, l1);
    hi[i] = make_uint2(h0, h1);
    lo[i] = make_uint2(l0, l1);
}

__global__ void split_transpose_kernel(const float* __restrict__ src,
                                       bf16* __restrict__ dhi, bf16* __restrict__ dlo,
                                       int K, int N) {
    __shared__ float t[32][33];
    const int n0 = blockIdx.x * 32, k0 = blockIdx.y * 32;
    const int tx = threadIdx.x, ty = threadIdx.y;
#pragma unroll
    for (int r = 0; r < 4; r++)
        t[ty + 8 * r][tx] = src[(size_t)(k0 + ty + 8 * r) * N + n0 + tx];
    __syncthreads();
#pragma unroll
    for (int r = 0; r < 4; r++) {
        float x = t[tx][ty + 8 * r];
        bf16 h = __float2bfloat16(x);
        float hf = __bfloat162float(h);
        size_t off = (size_t)(n0 + ty + 8 * r) * K + k0 + tx;
        dhi[off] = h;
        dlo[off] = __float2bfloat16(x - hf);
    }
}

// ---------------------------------------------------------------------------
// bf16x3 GEMM (unchanged from R9 passing version)
// ---------------------------------------------------------------------------
#define PW 20
#define TILE_W (128 * PW)
#define GSMEM (2 * 4 * TILE_W * 4)   // 81920 B

__global__ __launch_bounds__(256, 2)
void gemm_bf16x3(const bf16* __restrict__ Ahi, const bf16* __restrict__ Alo,
                 const bf16* __restrict__ Bhi, const bf16* __restrict__ Blo,
                 float* __restrict__ C, int M, int N, int K) {
    extern __shared__ uint32_t sw[];
    const uint32_t sbase = smem_u32(sw);

    const int tid  = threadIdx.x;
    const int wid  = tid >> 5;
    const int lane = tid & 31;
    const int g  = lane >> 2;
    const int tg = lane & 3;
    const int wm = (wid & 3) * 32;
    const int wn = (wid >> 2) * 64;

    const bf16* gptr[4] = {
        Ahi + (size_t)blockIdx.y * 128 * K,
        Alo + (size_t)blockIdx.y * 128 * K,
        Bhi + (size_t)blockIdx.x * 128 * K,
        Blo + (size_t)blockIdx.x * 128 * K
    };

    const uint32_t a_off = (uint32_t)(((wm + (lane & 15)) * PW + (lane >> 4) * 4) * 4);
    const uint32_t b_off = (uint32_t)(((wn + ((lane >> 4) << 3) + (lane & 7)) * PW
                                       + ((lane >> 3) & 1) * 4) * 4);

    float acc[2][8][4];
#pragma unroll
    for (int mi = 0; mi < 2; mi++)
#pragma unroll
        for (int ni = 0; ni < 8; ni++)
#pragma unroll
            for (int r = 0; r < 4; r++) acc[mi][ni][r] = 0.f;

#define GEMM_LOAD(st, k0)                                                     \
    {                                                                          \
        uint32_t s0 = sbase + (st) * (4 * TILE_W) * 4;                         \
        _Pragma("unroll")                                                      \
        for (int j = 0; j < 8; j++) {                                          \
            int idx = tid + j * 256;                                           \
            int arr = j >> 1;                                                  \
            int r = (idx >> 2) & 127, c = idx & 3;                             \
            cp_async16_sa(s0 + (arr * TILE_W + r * PW + c * 4) * 4,            \
                          gptr[arr] + (size_t)r * K + (k0) + c * 8);           \
        }                                                                      \
        cp_commit();                                                           \
    }

    const int NIT = K / 32;
    GEMM_LOAD(0, 0);

    for (int it = 0; it < NIT; ++it) {
        const int st = it & 1;
        asm volatile("cp.async.wait_group 0;\n" ::: "memory");
        __syncthreads();
        if (it + 1 < NIT) GEMM_LOAD(st ^ 1, (it + 1) * 32);

        const uint32_t sA_h = sbase + (st * 4 * TILE_W) * 4;
        const uint32_t sA_l = sA_h + TILE_W * 4;
        const uint32_t sB_h = sA_h + 2 * TILE_W * 4;
        const uint32_t sB_l = sA_h + 3 * TILE_W * 4;

#pragma unroll
        for (int ch = 0; ch < 2; ch++) {
            const uint32_t kb = (uint32_t)(ch * 8 * 4);
            uint32_t ah[2][4], al[2][4];
#pragma unroll
            for (int mi = 0; mi < 2; mi++) {
                ldsm_x4(sA_h + a_off + (uint32_t)(mi * 16 * PW * 4) + kb, ah[mi]);
                ldsm_x4(sA_l + a_off + (uint32_t)(mi * 16 * PW * 4) + kb, al[mi]);
            }
#pragma unroll
            for (int p = 0; p < 4; p++) {
                uint32_t bh[4], bl[4];
                ldsm_x4(sB_h + b_off + (uint32_t)(p * 16 * PW * 4) + kb, bh);
                ldsm_x4(sB_l + b_off + (uint32_t)(p * 16 * PW * 4) + kb, bl);
#pragma unroll
                for (int s = 0; s < 2; s++) {
                    const int ni = 2 * p + s;
#pragma unroll
                    for (int mi = 0; mi < 2; mi++) {
                        mma_bf16(acc[mi][ni], ah[mi], bh[2 * s], bh[2 * s + 1]);
                        mma_bf16(acc[mi][ni], al[mi], bh[2 * s], bh[2 * s + 1]);
                        mma_bf16(acc[mi][ni], ah[mi], bl[2 * s], bl[2 * s + 1]);
                    }
                }
            }
        }
    }

#pragma unroll
    for (int mi = 0; mi < 2; mi++) {
        const int row = blockIdx.y * 128 + wm + mi * 16 + g;
#pragma unroll
        for (int ni = 0; ni < 8; ni++) {
            const int col = blockIdx.x * 128 + wn + ni * 8 + 2 * tg;
            *reinterpret_cast<float2*>(C + (size_t)row * N + col) =
                make_float2(acc[mi][ni][0], acc[mi][ni][1]);
            *reinterpret_cast<float2*>(C + (size_t)(row + 8) * N + col) =
                make_float2(acc[mi][ni][2], acc[mi][ni][3]);
        }
    }
}

// ---------------------------------------------------------------------------
// RoPE + scatter (unchanged)
// ---------------------------------------------------------------------------
__global__ void rope_scatter_kernel(const int* __restrict__ positions) {
    const int total = B_ * S_ * (NH_ + NKV_) * (D_ / 2);
    int idx = blockIdx.x * blockDim.x + threadIdx.x;
    if (idx >= total) return;

    const int d = idx & 31;
    int t = idx >> 5;
    const int h = t % (NH_ + NKV_); t /= (NH_ + NKV_);
    const int s = t % S_;
    const int b = t / S_;

    const float pos = (float)positions[s];
    const float inv = powf(10000.0f, -(float)(2 * d) / (float)D_);
    const float freq = pos * inv;
    const double dr = (double)freq;
    const double kq = floor(dr * 0.15915494309189534 + 0.5);
    const float  rr = (float)(dr - kq * 6.283185307179586477);
    float sn, cs;
    sincosf(rr, &sn, &cs);

    const float* base = g_qkv + (size_t)(b * S_ + s) * QKVF;
    float x0, x1, scale;
    bf16 *dhi, *dlo;
    if (h < NH_) {
        x0 = base[h * D_ + d];
        x1 = base[h * D_ + d + 32];
        size_t off = (((size_t)(b * NH_ + h)) * S_ + s) * D_;
        dhi = g_q_hi + off; dlo = g_q_lo + off;
        scale = 0.125f;
    } else {
        const int hk = h - NH_;
        x0 = base[NH_ * D_ + hk * D_ + d];
        x1 = base[NH_ * D_ + hk * D_ + d + 32];
        size_t off = (((size_t)(b * NKV_ + hk)) * S_ + s) * D_;
        dhi = g_k_hi + off; dlo = g_k_lo + off;
        scale = 1.0f;
    }
    float v0 = (x0 * cs - x1 * sn) * scale;
    float v1 = (x1 * cs + x0 * sn) * scale;
    bf16 h0 = __float2bfloat16(v0);
    bf16 h1 = __float2bfloat16(v1);
    dhi[d]      = h0;
    dhi[d + 32] = h1;
    dlo[d]      = __float2bfloat16(v0 - __bfloat162float(h0));
    dlo[d + 32] = __float2bfloat16(v1 - __bfloat162float(h1));
}

__global__ void vtranspose_kernel() {
    __shared__ float t[32][65];
    const int s0 = blockIdx.x * 32;
    const int kh = blockIdx.y;
    const int b  = blockIdx.z;
    const int tid = threadIdx.x;

    const float* src = g_qkv + (size_t)b * S_ * QKVF + (NH_ + NKV_) * D_ + kh * D_;
#pragma unroll
    for (int j = 0; j < 8; j++) {
        int e = tid + j * 256;
        int s = e >> 6, d = e & 63;
        t[s][d] = src[(size_t)(s0 + s) * QKVF + d];
    }
    __syncthreads();

    bf16* dhi = g_vt_hi + ((size_t)(b * NKV_ + kh)) * D_ * S_;
    bf16* dlo = g_vt_lo + ((size_t)(b * NKV_ + kh)) * D_ * S_;
#pragma unroll
    for (int j = 0; j < 8; j++) {
        int e = tid + j * 256;
        int d = e >> 5, s = e & 31;
        float x = t[s][d];
        bf16 h = __float2bfloat16(x);
        dhi[(size_t)d * S_ + s0 + s] = h;
        dlo[(size_t)d * S_ + s0 + s] = __float2bfloat16(x - __bfloat162float(h));
    }
}

// ---------------------------------------------------------------------------
// bf16x3 causal flash attention: 128 q-rows per CTA, 256 threads (8 warps,
// 16 q-rows each), 64-key tiles double-buffered, ldmatrix loads.
// smem (uint32 words, AW=36 stride):
//   Qh @0, Ql @1, Ph @2, Pl @3          (128-row tiles, 4608 words each)
//   Kh/Kl @ 18432 + (2*st+hl)*2304      (64-row tiles)
//   Vh/Vl @ 27648 + (2*st+hl)*2304
// Total 36864 words = 147456 B -> 1 CTA/SM.
// ---------------------------------------------------------------------------
#define AW 36
#define QT_W (128 * AW)                // 4608 words (128-row tile)
#define KT_W (64 * AW)                 // 2304 words (64-row tile)
#define KV_BASE (4 * QT_W)             // 18432
#define V_BASE  (KV_BASE + 4 * KT_W)   // 27648
#define ATTN_SMEM ((4 * QT_W + 8 * KT_W) * 4)   // 147456 B

__global__ __launch_bounds__(256, 1)
void attn_kernel(float* /*unused*/) {
    extern __shared__ uint32_t sw[];
    const uint32_t sbase = smem_u32(sw);

    const int qtile = gridDim.x - 1 - blockIdx.x;   // heavy tiles first
    const int h = blockIdx.y;
    const int b = blockIdx.z;
    const int kvh = h / GQA_;
    const int q0 = qtile * 128;

    const bf16* qh_g = g_q_hi + (((size_t)(b * NH_ + h)) * S_ + q0) * D_;
    const bf16* ql_g = g_q_lo + (((size_t)(b * NH_ + h)) * S_ + q0) * D_;
    const bf16* kh_g = g_k_hi + ((size_t)(b * NKV_ + kvh)) * S_ * D_;
    const bf16* kl_g = g_k_lo + ((size_t)(b * NKV_ + kvh)) * S_ * D_;
    const bf16* vh_g = g_vt_hi + ((size_t)(b * NKV_ + kvh)) * D_ * S_;
    const bf16* vl_g = g_vt_lo + ((size_t)(b * NKV_ + kvh)) * D_ * S_;

    const int tid  = threadIdx.x;
    const int wid  = tid >> 5;
    const int lane = tid & 31;
    const int g  = lane >> 2;
    const int tg = lane & 3;
    const int wm = wid * 16;            // warp's q-row offset (0..112)

    const uint32_t aq_off = (uint32_t)(((wm + (lane & 15)) * AW + (lane >> 4) * 4) * 4);
    const uint32_t bk_off = (uint32_t)(((((lane >> 4) << 3) + (lane & 7)) * AW
                                        + ((lane >> 3) & 1) * 4) * 4);

    // Load Q tile (128 rows, hi+lo): 2048 16B chunks / 256 threads
#pragma unroll
    for (int j = 0; j < 8; j++) {
        int idx = tid + j * 256;
        int half = idx >> 10;
        int e = idx & 1023;
        int r = e >> 3, c = e & 7;
        const bf16* src = half ? ql_g : qh_g;
        cp_async16_sa(sbase + (half * QT_W + r * AW + c * 4) * 4,
                      src + (size_t)r * D_ + c * 8);
    }
    cp_commit();

    // KV load: 4 arrays (Kh,Kl,Vh,Vl) x 64 rows x 8 chunks = 2048 / 256 thr
#define ATTN_LOAD_KV(st, kt)                                                     \
    {                                                                             \
        _Pragma("unroll")                                                         \
        for (int j = 0; j < 8; j++) {                                             \
            int idx = tid + j * 256;                                              \
            int arr = idx >> 9;                                                   \
            int e = idx & 511;                                                    \
            int r = e >> 3, c = e & 7;                                            \
            uint32_t toff = (arr < 2 ? KV_BASE : V_BASE)                          \
                          + (2 * (st) + (arr & 1)) * KT_W;                        \
            const bf16* src;                                                      \
            size_t goff;                                                          \
            if (arr == 0)      { src = kh_g; goff = (size_t)((kt) * 64 + r) * D_ + c * 8; } \
            else if (arr == 1) { src = kl_g; goff = (size_t)((kt) * 64 + r) * D_ + c * 8; } \
            else if (arr == 2) { src = vh_g; goff = (size_t)r * S_ + (kt) * 64 + c * 8; }   \
            else               { src = vl_g; goff = (size_t)r * S_ + (kt) * 64 + c * 8; }   \
            cp_async16_sa(sbase + (toff + r * AW + c * 4) * 4, src + goff);       \
        }                                                                         \
        cp_commit();                                                              \
    }

    ATTN_LOAD_KV(0, 0);

    float oacc[8][4];
    float m0 = -1e30f, m1 = -1e30f, l0 = 0.f, l1 = 0.f;
#pragma unroll
    for (int ni = 0; ni < 8; ni++)
#pragma unroll
        for (int r = 0; r < 4; r++) oacc[ni][r] = 0.f;

    const int gq0 = q0 + wm + g;
    const int gq1 = gq0 + 8;

    const uint32_t Qh_b = sbase;
    const uint32_t Ql_b = sbase + QT_W * 4;
    uint32_t* Ph = sw + 2 * QT_W;
    uint32_t* Pl = sw + 3 * QT_W;
    const uint32_t Ph_b = sbase + 2 * QT_W * 4;
    const uint32_t Pl_b = sbase + 3 * QT_W * 4;

    const int KT_MAX = 2 * qtile + 1;   // k-tiles 0..KT_MAX (64 keys each)

    for (int kt = 0; kt <= KT_MAX; kt++) {
        const int cur = kt & 1;
        asm volatile("cp.async.wait_group 0;\n" ::: "memory");
        __syncthreads();
        if (kt + 1 <= KT_MAX) ATTN_LOAD_KV(cur ^ 1, kt + 1);

        const uint32_t Kh_b = sbase + (KV_BASE + 2 * cur * KT_W) * 4;
        const uint32_t Kl_b = Kh_b + KT_W * 4;
        const uint32_t Vh_b = sbase + (V_BASE + 2 * cur * KT_W) * 4;
        const uint32_t Vl_b = Vh_b + KT_W * 4;

        // ---- S = Q @ K^T ----
        float sacc[8][4];
#pragma unroll
        for (int ni = 0; ni < 8; ni++)
#pragma unroll
            for (int r = 0; r < 4; r++) sacc[ni][r] = 0.f;

#pragma unroll
        for (int ch = 0; ch < 4; ch++) {
            const uint32_t kb = (uint32_t)(ch * 8 * 4);
            uint32_t qh[4], ql[4];
            ldsm_x4(Qh_b + aq_off + kb, qh);
            ldsm_x4(Ql_b + aq_off + kb, ql);
#pragma unroll
            for (int p = 0; p < 4; p++) {
                uint32_t kh4[4], kl4[4];
                ldsm_x4(Kh_b + bk_off + (uint32_t)(p * 16 * AW * 4) + kb, kh4);
                ldsm_x4(Kl_b + bk_off + (uint32_t)(p * 16 * AW * 4) + kb, kl4);
#pragma unroll
                for (int s = 0; s < 2; s++) {
                    const int ni = 2 * p + s;
                    mma_bf16(sacc[ni], qh, kh4[2 * s], kh4[2 * s + 1]);
                    mma_bf16(sacc[ni], ql, kh4[2 * s], kh4[2 * s + 1]);
                    mma_bf16(sacc[ni], qh, kl4[2 * s], kl4[2 * s + 1]);
                }
            }
        }

        // ---- causal mask: needed when this k-tile can exceed warp's rows ----
        if (kt * 64 + 63 > q0 + wm) {
#pragma unroll
            for (int ni = 0; ni < 8; ni++) {
                const int col = kt * 64 + ni * 8 + 2 * tg;
                if (col     > gq0) sacc[ni][0] = -1e30f;
                if (col + 1 > gq0) sacc[ni][1] = -1e30f;
                if (col     > gq1) sacc[ni][2] = -1e30f;
                if (col + 1 > gq1) sacc[ni][3] = -1e30f;
            }
        }

        // ---- online softmax ----
        float mx0 = -1e30f, mx1 = -1e30f;
#pragma unroll
        for (int ni = 0; ni < 8; ni++) {
            mx0 = fmaxf(mx0, fmaxf(sacc[ni][0], sacc[ni][1]));
            mx1 = fmaxf(mx1, fmaxf(sacc[ni][2], sacc[ni][3]));
        }
        mx0 = fmaxf(mx0, __shfl_xor_sync(0xffffffffu, mx0, 1));
        mx0 = fmaxf(mx0, __shfl_xor_sync(0xffffffffu, mx0, 2));
        mx1 = fmaxf(mx1, __shfl_xor_sync(0xffffffffu, mx1, 1));
        mx1 = fmaxf(mx1, __shfl_xor_sync(0xffffffffu, mx1, 2));

        const float mn0 = fmaxf(m0, mx0);
        const float mn1 = fmaxf(m1, mx1);
        const float corr0 = __expf(m0 - mn0);
        const float corr1 = __expf(m1 - mn1);
        float rs0 = 0.f, rs1 = 0.f;
#pragma unroll
        for (int ni = 0; ni < 8; ni++) {
            float p0 = __expf(sacc[ni][0] - mn0);
            float p1 = __expf(sacc[ni][1] - mn0);
            float p2 = __expf(sacc[ni][2] - mn1);
            float p3 = __expf(sacc[ni][3] - mn1);
            sacc[ni][0] = p0; sacc[ni][1] = p1;
            sacc[ni][2] = p2; sacc[ni][3] = p3;
            rs0 += p0 + p1;
            rs1 += p2 + p3;
        }
        rs0 += __shfl_xor_sync(0xffffffffu, rs0, 1);
        rs0 += __shfl_xor_sync(0xffffffffu, rs0, 2);
        rs1 += __shfl_xor_sync(0xffffffffu, rs1, 1);
        rs1 += __shfl_xor_sync(0xffffffffu, rs1, 2);
        l0 = l0 * corr0 + rs0;
        l1 = l1 * corr1 + rs1;
        m0 = mn0;
        m1 = mn1;
#pragma unroll
        for (int ni = 0; ni < 8; ni++) {
            oacc[ni][0] *= corr0;
            oacc[ni][1] *= corr0;
            oacc[ni][2] *= corr1;
            oacc[ni][3] *= corr1;
        }

        // ---- P -> smem (split bf16; warp-local rows) ----
#pragma unroll
        for (int ni = 0; ni < 8; ni++) {
            const int cw = ni * 4 + tg;
            uint32_t h0, L0, h1, L1;
            split2(sacc[ni][0], sacc[ni][1], h0, L0);
            split2(sacc[ni][2], sacc[ni][3], h1, L1);
            Ph[(wm + g) * AW + cw] = h0;
            Pl[(wm + g) * AW + cw] = L0;
            Ph[(wm + g + 8) * AW + cw] = h1;
            Pl[(wm + g + 8) * AW + cw] = L1;
        }
        __syncwarp();

        // ---- O += P @ V ----
#pragma unroll
        for (int ch = 0; ch < 4; ch++) {
            const uint32_t kb = (uint32_t)(ch * 8 * 4);
            uint32_t ph[4], pl[4];
            ldsm_x4(Ph_b + aq_off + kb, ph);
            ldsm_x4(Pl_b + aq_off + kb, pl);
#pragma unroll
            for (int p = 0; p < 4; p++) {
                uint32_t vh4[4], vl4[4];
                ldsm_x4(Vh_b + bk_off + (uint32_t)(p * 16 * AW * 4) + kb, vh4);
                ldsm_x4(Vl_b + bk_off + (uint32_t)(p * 16 * AW * 4) + kb, vl4);
#pragma unroll
                for (int s = 0; s < 2; s++) {
                    const int ni = 2 * p + s;
                    mma_bf16(oacc[ni], ph, vh4[2 * s], vh4[2 * s + 1]);
                    mma_bf16(oacc[ni], pl, vh4[2 * s], vh4[2 * s + 1]);
                    mma_bf16(oacc[ni], ph, vl4[2 * s], vl4[2 * s + 1]);
                }
            }
        }
    }

    const float il0 = 1.0f / l0;
    const float il1 = 1.0f / l1;
    uint32_t* ch_w = reinterpret_cast<uint32_t*>(g_ctx_hi);
    uint32_t* cl_w = reinterpret_cast<uint32_t*>(g_ctx_lo);
    const size_t off0 = (((size_t)(b * S_ + gq0)) * (NH_ * D_) + h * D_) >> 1;
    const size_t off1 = (((size_t)(b * S_ + gq1)) * (NH_ * D_) + h * D_) >> 1;
#pragma unroll
    for (int ni = 0; ni < 8; ni++) {
        const int cw = ni * 4 + tg;
        uint32_t h0, L0, h1, L1;
        split2(oacc[ni][0] * il0, oacc[ni][1] * il0, h0, L0);
        split2(oacc[ni][2] * il1, oacc[ni][3] * il1, h1, L1);
        ch_w[off0 + cw] = h0;
        cl_w[off0 + cw] = L0;
        ch_w[off1 + cw] = h1;
        cl_w[off1 + cw] = L1;
    }
}

// ---------------------------------------------------------------------------
// Launch
// ---------------------------------------------------------------------------
extern "C" void kernel_launch(void* const* d_in, const int* in_sizes, int n_in,
                              void* d_out, int out_size) {
    const int*   positions = (const int*)d_in[0];
    const float* hidden    = (const float*)d_in[1];
    const float* Wqkv      = (const float*)d_in[2];
    const float* Wo        = (const float*)d_in[3];
    float* out = (float*)d_out;

    float* qkv_p;
    bf16 *hh, *hl, *wqh, *wql, *woh, *wol, *cth, *ctl;
    cudaGetSymbolAddress((void**)&qkv_p, g_qkv);
    cudaGetSymbolAddress((void**)&hh,  g_hid_hi);
    cudaGetSymbolAddress((void**)&hl,  g_hid_lo);
    cudaGetSymbolAddress((void**)&wqh, g_wqkv_hi);
    cudaGetSymbolAddress((void**)&wql, g_wqkv_lo);
    cudaGetSymbolAddress((void**)&woh, g_wo_hi);
    cudaGetSymbolAddress((void**)&wol, g_wo_lo);
    cudaGetSymbolAddress((void**)&cth, g_ctx_hi);
    cudaGetSymbolAddress((void**)&ctl, g_ctx_lo);

    cudaFuncSetAttribute(gemm_bf16x3, cudaFuncAttributeMaxDynamicSharedMemorySize, GSMEM);
    cudaFuncSetAttribute(gemm_bf16x3, cudaFuncAttributePreferredSharedMemoryCarveout, 100);
    cudaFuncSetAttribute(attn_kernel, cudaFuncAttributeMaxDynamicSharedMemorySize, ATTN_SMEM);
    cudaFuncSetAttribute(attn_kernel, cudaFuncAttributePreferredSharedMemoryCarveout, 100);

    // 0. Pre-split operands
    {
        int n4 = B_ * S_ * H_ / 4;
        split_kernel<<<(n4 + 255) / 256, 256>>>(hidden, (uint2*)hh, (uint2*)hl, n4);
        split_transpose_kernel<<<dim3(QKVF / 32, H_ / 32), dim3(32, 8)>>>(Wqkv, wqh, wql, H_, QKVF);
        split_transpose_kernel<<<dim3(H_ / 32, H_ / 32), dim3(32, 8)>>>(Wo, woh, wol, H_, H_);
    }

    // 1. QKV projection
    gemm_bf16x3<<<dim3(QKVF / 128, (B_ * S_) / 128), 256, GSMEM>>>(
        hh, hl, wqh, wql, qkv_p, B_ * S_, QKVF, H_);

    // 2. RoPE + scatter (split) + V split-transpose
    {
        const int total = B_ * S_ * (NH_ + NKV_) * (D_ / 2);
        rope_scatter_kernel<<<(total + 255) / 256, 256>>>(positions);
        vtranspose_kernel<<<dim3(S_ / 32, NKV_, B_), 256>>>();
    }

    // 3. Causal GQA flash attention (128 q-rows/CTA)
    attn_kernel<<<dim3(S_ / 128, NH_, B_), 256, ATTN_SMEM>>>(nullptr);

    // 4. Output projection
    gemm_bf16x3<<<dim3(H_ / 128, (B_ * S_) / 128), 256, GSMEM>>>(
        cth, ctl, woh, wol, out, B_ * S_, H_, NH_ * D_);
}

// round 11
// speedup vs baseline: 1.0260x; 1.0260x over previous
#include <cuda_runtime.h>
#include <cuda_bf16.h>
#include <math.h>
#include <stdint.h>

#define B_   2
#define S_   2048
#define H_   2048
#define NH_  32
#define NKV_ 8
#define D_   64
#define QKVF ((NH_ + 2 * NKV_) * D_)   // 3072
#define GQA_ (NH_ / NKV_)              // 4

typedef __nv_bfloat16 bf16;

// ---------------------------------------------------------------------------
// Device scratch
// ---------------------------------------------------------------------------
__device__ float g_qkv[(size_t)B_ * S_ * QKVF];
__device__ bf16 g_hid_hi[(size_t)B_ * S_ * H_];
__device__ bf16 g_hid_lo[(size_t)B_ * S_ * H_];
__device__ bf16 g_wqkv_hi[(size_t)QKVF * H_];   // transposed [N][K]
__device__ bf16 g_wqkv_lo[(size_t)QKVF * H_];
__device__ bf16 g_wo_hi[(size_t)H_ * H_];       // transposed [N][K]
__device__ bf16 g_wo_lo[(size_t)H_ * H_];
__device__ bf16 g_q_hi[(size_t)B_ * NH_ * S_ * D_];
__device__ bf16 g_q_lo[(size_t)B_ * NH_ * S_ * D_];
__device__ bf16 g_k_hi[(size_t)B_ * NKV_ * S_ * D_];
__device__ bf16 g_k_lo[(size_t)B_ * NKV_ * S_ * D_];
__device__ bf16 g_vt_hi[(size_t)B_ * NKV_ * D_ * S_];
__device__ bf16 g_vt_lo[(size_t)B_ * NKV_ * D_ * S_];
__device__ bf16 g_ctx_hi[(size_t)B_ * S_ * NH_ * D_];
__device__ bf16 g_ctx_lo[(size_t)B_ * S_ * NH_ * D_];

// ---------------------------------------------------------------------------
// Helpers
// ---------------------------------------------------------------------------
__device__ __forceinline__ uint32_t smem_u32(const void* p) {
    return (uint32_t)__cvta_generic_to_shared(p);
}
__device__ __forceinline__ void cp_async16_sa(uint32_t sa, const void* g) {
    asm volatile("cp.async.cg.shared.global [%0], [%1], 16;\n" :: "r"(sa), "l"(g));
}
__device__ __forceinline__ void cp_commit() {
    asm volatile("cp.async.commit_group;\n");
}
__device__ __forceinline__ uint32_t pack2(float x, float y) {
    uint32_t r;
    asm("cvt.rn.bf16x2.f32 %0, %1, %2;" : "=r"(r) : "f"(y), "f"(x));
    return r;
}
__device__ __forceinline__ void split2(float x, float y, uint32_t& hi, uint32_t& lo) {
    hi = pack2(x, y);
    float hx = __uint_as_float(hi << 16);
    float hy = __uint_as_float(hi & 0xFFFF0000u);
    lo = pack2(x - hx, y - hy);
}
__device__ __forceinline__ void mma_bf16(float* c, const uint32_t* a,
                                         uint32_t b0, uint32_t b1) {
    asm volatile(
        "mma.sync.aligned.m16n8k16.row.col.f32.bf16.bf16.f32 "
        "{%0,%1,%2,%3},{%4,%5,%6,%7},{%8,%9},{%0,%1,%2,%3};"
        : "+f"(c[0]), "+f"(c[1]), "+f"(c[2]), "+f"(c[3])
        : "r"(a[0]), "r"(a[1]), "r"(a[2]), "r"(a[3]), "r"(b0), "r"(b1));
}
__device__ __forceinline__ void ldsm_x4(uint32_t addr, uint32_t* r) {
    asm volatile("ldmatrix.sync.aligned.m8n8.x4.shared.b16 {%0,%1,%2,%3}, [%4];"
                 : "=r"(r[0]), "=r"(r[1]), "=r"(r[2]), "=r"(r[3]) : "r"(addr));
}

// ---------------------------------------------------------------------------
// Fused pre-pass: [0,8192) split hidden; [8192,14336) transpose Wqkv;
// [14336,18432) transpose Wo. One launch keeps the chip saturated.
// ---------------------------------------------------------------------------
#define NB_SPLIT 8192                 // (B*S*H/4)/256
#define NB_WQ    6144                 // (QKVF/32)*(H/32) = 96*64
#define NB_WO    4096                 // (H/32)*(H/32)    = 64*64

__global__ void prepass_kernel(const float* __restrict__ hidden,
                               const float* __restrict__ Wqkv,
                               const float* __restrict__ Wo) {
    __shared__ float t[32][33];
    const int bid = blockIdx.x;
    const int tid = threadIdx.x;

    if (bid < NB_SPLIT) {
        int i = bid * 256 + tid;
        float4 v = reinterpret_cast<const float4*>(hidden)[i];
        uint32_t h0, l0, h1, l1;
        split2(v.x, v.y, h0, l0);
        split2(v.z, v.w, h1, l1);
        reinterpret_cast<uint2*>(g_hid_hi)[i] = make_uint2(h0, h1);
        reinterpret_cast<uint2*>(g_hid_lo)[i] = make_uint2(l0, l1);
        return;
    }

    const float* src;
    bf16 *dhi, *dlo;
    int N, bx, by;
    if (bid < NB_SPLIT + NB_WQ) {
        int b2 = bid - NB_SPLIT;
        bx = b2 % (QKVF / 32); by = b2 / (QKVF / 32);
        src = Wqkv; dhi = g_wqkv_hi; dlo = g_wqkv_lo; N = QKVF;
    } else {
        int b2 = bid - NB_SPLIT - NB_WQ;
        bx = b2 % (H_ / 32); by = b2 / (H_ / 32);
        src = Wo; dhi = g_wo_hi; dlo = g_wo_lo; N = H_;
    }
    const int K = H_;                  // both weights have K rows = 2048
    const int n0 = bx * 32, k0 = by * 32;
    const int tx = tid & 31, ty = tid >> 5;    // (32, 8)
#pragma unroll
    for (int r = 0; r < 4; r++)
        t[ty + 8 * r][tx] = src[(size_t)(k0 + ty + 8 * r) * N + n0 + tx];
    __syncthreads();
#pragma unroll
    for (int r = 0; r < 4; r++) {
        float x = t[tx][ty + 8 * r];
        bf16 h = __float2bfloat16(x);
        size_t off = (size_t)(n0 + ty + 8 * r) * K + k0 + tx;
        dhi[off] = h;
        dlo[off] = __float2bfloat16(x - __bfloat162float(h));
    }
}

// ---------------------------------------------------------------------------
// Fused RoPE-scatter + V split-transpose: [0,20480) rope; [20480,21504) vt.
// ---------------------------------------------------------------------------
#define NB_ROPE 20480                 // B*S*(NH+NKV)*32 / 256

__global__ void rope_vt_kernel(const int* __restrict__ positions) {
    if (blockIdx.x < NB_ROPE) {
        const int idx = blockIdx.x * 256 + threadIdx.x;
        const int d = idx & 31;
        int t = idx >> 5;
        const int h = t % (NH_ + NKV_); t /= (NH_ + NKV_);
        const int s = t % S_;
        const int b = t / S_;

        const float pos = (float)positions[s];
        const float inv = powf(10000.0f, -(float)(2 * d) / (float)D_);
        const float freq = pos * inv;
        const double dr = (double)freq;
        const double kq = floor(dr * 0.15915494309189534 + 0.5);
        const float  rr = (float)(dr - kq * 6.283185307179586477);
        float sn, cs;
        sincosf(rr, &sn, &cs);

        const float* base = g_qkv + (size_t)(b * S_ + s) * QKVF;
        float x0, x1, scale;
        bf16 *dhi, *dlo;
        if (h < NH_) {
            x0 = base[h * D_ + d];
            x1 = base[h * D_ + d + 32];
            size_t off = (((size_t)(b * NH_ + h)) * S_ + s) * D_;
            dhi = g_q_hi + off; dlo = g_q_lo + off;
            scale = 0.125f;
        } else {
            const int hk = h - NH_;
            x0 = base[NH_ * D_ + hk * D_ + d];
            x1 = base[NH_ * D_ + hk * D_ + d + 32];
            size_t off = (((size_t)(b * NKV_ + hk)) * S_ + s) * D_;
            dhi = g_k_hi + off; dlo = g_k_lo + off;
            scale = 1.0f;
        }
        float v0 = (x0 * cs - x1 * sn) * scale;
        float v1 = (x1 * cs + x0 * sn) * scale;
        bf16 h0 = __float2bfloat16(v0);
        bf16 h1 = __float2bfloat16(v1);
        dhi[d]      = h0;
        dhi[d + 32] = h1;
        dlo[d]      = __float2bfloat16(v0 - __bfloat162float(h0));
        dlo[d + 32] = __float2bfloat16(v1 - __bfloat162float(h1));
        return;
    }

    // V split + transpose into [b][kh][d][s]
    __shared__ float t[32][65];
    const int b2 = blockIdx.x - NB_ROPE;
    const int s0 = (b2 & 63) * 32;
    const int kh = (b2 >> 6) & 7;
    const int b  = b2 >> 9;
    const int tid = threadIdx.x;

    const float* src = g_qkv + (size_t)b * S_ * QKVF + (NH_ + NKV_) * D_ + kh * D_;
#pragma unroll
    for (int j = 0; j < 8; j++) {
        int e = tid + j * 256;
        int s = e >> 6, d = e & 63;
        t[s][d] = src[(size_t)(s0 + s) * QKVF + d];
    }
    __syncthreads();

    bf16* dhi = g_vt_hi + ((size_t)(b * NKV_ + kh)) * D_ * S_;
    bf16* dlo = g_vt_lo + ((size_t)(b * NKV_ + kh)) * D_ * S_;
#pragma unroll
    for (int j = 0; j < 8; j++) {
        int e = tid + j * 256;
        int d = e >> 5, s = e & 31;
        float x = t[s][d];
        bf16 h = __float2bfloat16(x);
        dhi[(size_t)d * S_ + s0 + s] = h;
        dlo[(size_t)d * S_ + s0 + s] = __float2bfloat16(x - __bfloat162float(h));
    }
}

// ---------------------------------------------------------------------------
// bf16x3 GEMM (R9 passing version, unchanged)
// ---------------------------------------------------------------------------
#define PW 20
#define TILE_W (128 * PW)
#define GSMEM (2 * 4 * TILE_W * 4)   // 81920 B

__global__ __launch_bounds__(256, 2)
void gemm_bf16x3(const bf16* __restrict__ Ahi, const bf16* __restrict__ Alo,
                 const bf16* __restrict__ Bhi, const bf16* __restrict__ Blo,
                 float* __restrict__ C, int M, int N, int K) {
    extern __shared__ uint32_t sw[];
    const uint32_t sbase = smem_u32(sw);

    const int tid  = threadIdx.x;
    const int wid  = tid >> 5;
    const int lane = tid & 31;
    const int g  = lane >> 2;
    const int tg = lane & 3;
    const int wm = (wid & 3) * 32;
    const int wn = (wid >> 2) * 64;

    const bf16* gptr[4] = {
        Ahi + (size_t)blockIdx.y * 128 * K,
        Alo + (size_t)blockIdx.y * 128 * K,
        Bhi + (size_t)blockIdx.x * 128 * K,
        Blo + (size_t)blockIdx.x * 128 * K
    };

    const uint32_t a_off = (uint32_t)(((wm + (lane & 15)) * PW + (lane >> 4) * 4) * 4);
    const uint32_t b_off = (uint32_t)(((wn + ((lane >> 4) << 3) + (lane & 7)) * PW
                                       + ((lane >> 3) & 1) * 4) * 4);

    float acc[2][8][4];
#pragma unroll
    for (int mi = 0; mi < 2; mi++)
#pragma unroll
        for (int ni = 0; ni < 8; ni++)
#pragma unroll
            for (int r = 0; r < 4; r++) acc[mi][ni][r] = 0.f;

#define GEMM_LOAD(st, k0)                                                     \
    {                                                                          \
        uint32_t s0 = sbase + (st) * (4 * TILE_W) * 4;                         \
        _Pragma("unroll")                                                      \
        for (int j = 0; j < 8; j++) {                                          \
            int idx = tid + j * 256;                                           \
            int arr = j >> 1;                                                  \
            int r = (idx >> 2) & 127, c = idx & 3;                             \
            cp_async16_sa(s0 + (arr * TILE_W + r * PW + c * 4) * 4,            \
                          gptr[arr] + (size_t)r * K + (k0) + c * 8);           \
        }                                                                      \
        cp_commit();                                                           \
    }

    const int NIT = K / 32;
    GEMM_LOAD(0, 0);

    for (int it = 0; it < NIT; ++it) {
        const int st = it & 1;
        asm volatile("cp.async.wait_group 0;\n" ::: "memory");
        __syncthreads();
        if (it + 1 < NIT) GEMM_LOAD(st ^ 1, (it + 1) * 32);

        const uint32_t sA_h = sbase + (st * 4 * TILE_W) * 4;
        const uint32_t sA_l = sA_h + TILE_W * 4;
        const uint32_t sB_h = sA_h + 2 * TILE_W * 4;
        const uint32_t sB_l = sA_h + 3 * TILE_W * 4;

#pragma unroll
        for (int ch = 0; ch < 2; ch++) {
            const uint32_t kb = (uint32_t)(ch * 8 * 4);
            uint32_t ah[2][4], al[2][4];
#pragma unroll
            for (int mi = 0; mi < 2; mi++) {
                ldsm_x4(sA_h + a_off + (uint32_t)(mi * 16 * PW * 4) + kb, ah[mi]);
                ldsm_x4(sA_l + a_off + (uint32_t)(mi * 16 * PW * 4) + kb, al[mi]);
            }
#pragma unroll
            for (int p = 0; p < 4; p++) {
                uint32_t bh[4], bl[4];
                ldsm_x4(sB_h + b_off + (uint32_t)(p * 16 * PW * 4) + kb, bh);
                ldsm_x4(sB_l + b_off + (uint32_t)(p * 16 * PW * 4) + kb, bl);
#pragma unroll
                for (int s = 0; s < 2; s++) {
                    const int ni = 2 * p + s;
#pragma unroll
                    for (int mi = 0; mi < 2; mi++) {
                        mma_bf16(acc[mi][ni], ah[mi], bh[2 * s], bh[2 * s + 1]);
                        mma_bf16(acc[mi][ni], al[mi], bh[2 * s], bh[2 * s + 1]);
                        mma_bf16(acc[mi][ni], ah[mi], bl[2 * s], bl[2 * s + 1]);
                    }
                }
            }
        }
    }

#pragma unroll
    for (int mi = 0; mi < 2; mi++) {
        const int row = blockIdx.y * 128 + wm + mi * 16 + g;
#pragma unroll
        for (int ni = 0; ni < 8; ni++) {
            const int col = blockIdx.x * 128 + wn + ni * 8 + 2 * tg;
            *reinterpret_cast<float2*>(C + (size_t)row * N + col) =
                make_float2(acc[mi][ni][0], acc[mi][ni][1]);
            *reinterpret_cast<float2*>(C + (size_t)(row + 8) * N + col) =
                make_float2(acc[mi][ni][2], acc[mi][ni][3]);
        }
    }
}

// ---------------------------------------------------------------------------
// bf16x3 causal flash attention (R9 passing version: 64 q-rows, 128 thr,
// 2 CTAs/SM, ldmatrix, one barrier per k-tile)
// ---------------------------------------------------------------------------
#define AW 36
#define AT_W (64 * AW)
#define ATTN_SMEM (12 * AT_W * 4)

__global__ __launch_bounds__(128, 2)
void attn_kernel(float* /*unused*/) {
    extern __shared__ uint32_t sw[];
    const uint32_t sbase = smem_u32(sw);

    const int qtile = gridDim.x - 1 - blockIdx.x;
    const int h = blockIdx.y;
    const int b = blockIdx.z;
    const int kvh = h / GQA_;
    const int q0 = qtile * 64;

    const bf16* qh_g = g_q_hi + (((size_t)(b * NH_ + h)) * S_ + q0) * D_;
    const bf16* ql_g = g_q_lo + (((size_t)(b * NH_ + h)) * S_ + q0) * D_;
    const bf16* kh_g = g_k_hi + ((size_t)(b * NKV_ + kvh)) * S_ * D_;
    const bf16* kl_g = g_k_lo + ((size_t)(b * NKV_ + kvh)) * S_ * D_;
    const bf16* vh_g = g_vt_hi + ((size_t)(b * NKV_ + kvh)) * D_ * S_;
    const bf16* vl_g = g_vt_lo + ((size_t)(b * NKV_ + kvh)) * D_ * S_;

    const int tid  = threadIdx.x;
    const int wid  = tid >> 5;
    const int lane = tid & 31;
    const int g  = lane >> 2;
    const int tg = lane & 3;
    const int wm = wid * 16;

    const uint32_t aq_off = (uint32_t)(((wm + (lane & 15)) * AW + (lane >> 4) * 4) * 4);
    const uint32_t bk_off = (uint32_t)(((((lane >> 4) << 3) + (lane & 7)) * AW
                                        + ((lane >> 3) & 1) * 4) * 4);

#pragma unroll
    for (int j = 0; j < 8; j++) {
        int idx = tid + j * 128;
        int r = (idx >> 3) & 63, c = idx & 7;
        const bf16* src = (j >> 2) ? ql_g : qh_g;
        cp_async16_sa(sbase + ((j >> 2) * AT_W + r * AW + c * 4) * 4,
                      src + (size_t)r * D_ + c * 8);
    }
    cp_commit();

#define ATTN_LOAD_KV(st, kt)                                                    \
    {                                                                            \
        _Pragma("unroll")                                                        \
        for (int j = 0; j < 16; j++) {                                           \
            int idx = tid + j * 128;                                              \
            int arr = j >> 2;                                                     \
            int r = (idx >> 3) & 63, c = idx & 7;                                 \
            int tile = (arr < 2 ? 4 : 8) + 2 * (st) + (arr & 1);                  \
            const bf16* src;                                                      \
            size_t goff;                                                          \
            if (arr == 0)      { src = kh_g; goff = (size_t)((kt) * 64 + r) * D_ + c * 8; } \
            else if (arr == 1) { src = kl_g; goff = (size_t)((kt) * 64 + r) * D_ + c * 8; } \
            else if (arr == 2) { src = vh_g; goff = (size_t)r * S_ + (kt) * 64 + c * 8; }   \
            else               { src = vl_g; goff = (size_t)r * S_ + (kt) * 64 + c * 8; }   \
            cp_async16_sa(sbase + (tile * AT_W + r * AW + c * 4) * 4, src + goff); \
        }                                                                         \
        cp_commit();                                                              \
    }

    ATTN_LOAD_KV(0, 0);

    float oacc[8][4];
    float m0 = -1e30f, m1 = -1e30f, l0 = 0.f, l1 = 0.f;
#pragma unroll
    for (int ni = 0; ni < 8; ni++)
#pragma unroll
        for (int r = 0; r < 4; r++) oacc[ni][r] = 0.f;

    const int gq0 = q0 + wm + g;
    const int gq1 = gq0 + 8;

    const uint32_t Qh_b = sbase;
    const uint32_t Ql_b = sbase + AT_W * 4;
    uint32_t* Ph = sw + 2 * AT_W;
    uint32_t* Pl = sw + 3 * AT_W;
    const uint32_t Ph_b = sbase + 2 * AT_W * 4;
    const uint32_t Pl_b = sbase + 3 * AT_W * 4;

    for (int kt = 0; kt <= qtile; kt++) {
        const int cur = kt & 1;
        asm volatile("cp.async.wait_group 0;\n" ::: "memory");
        __syncthreads();
        if (kt + 1 <= qtile) ATTN_LOAD_KV(cur ^ 1, kt + 1);

        const uint32_t Kh_b = sbase + (4 + 2 * cur) * AT_W * 4;
        const uint32_t Kl_b = sbase + (5 + 2 * cur) * AT_W * 4;
        const uint32_t Vh_b = sbase + (8 + 2 * cur) * AT_W * 4;
        const uint32_t Vl_b = sbase + (9 + 2 * cur) * AT_W * 4;

        float sacc[8][4];
#pragma unroll
        for (int ni = 0; ni < 8; ni++)
#pragma unroll
            for (int r = 0; r < 4; r++) sacc[ni][r] = 0.f;

#pragma unroll
        for (int ch = 0; ch < 4; ch++) {
            const uint32_t kb = (uint32_t)(ch * 8 * 4);
            uint32_t qh[4], ql[4];
            ldsm_x4(Qh_b + aq_off + kb, qh);
            ldsm_x4(Ql_b + aq_off + kb, ql);
#pragma unroll
            for (int p = 0; p < 4; p++) {
                uint32_t kh4[4], kl4[4];
                ldsm_x4(Kh_b + bk_off + (uint32_t)(p * 16 * AW * 4) + kb, kh4);
                ldsm_x4(Kl_b + bk_off + (uint32_t)(p * 16 * AW * 4) + kb, kl4);
#pragma unroll
                for (int s = 0; s < 2; s++) {
                    const int ni = 2 * p + s;
                    mma_bf16(sacc[ni], qh, kh4[2 * s], kh4[2 * s + 1]);
                    mma_bf16(sacc[ni], ql, kh4[2 * s], kh4[2 * s + 1]);
                    mma_bf16(sacc[ni], qh, kl4[2 * s], kl4[2 * s + 1]);
                }
            }
        }

        if (kt == qtile) {
#pragma unroll
            for (int ni = 0; ni < 8; ni++) {
                const int col = kt * 64 + ni * 8 + 2 * tg;
                if (col     > gq0) sacc[ni][0] = -1e30f;
                if (col + 1 > gq0) sacc[ni][1] = -1e30f;
                if (col     > gq1) sacc[ni][2] = -1e30f;
                if (col + 1 > gq1) sacc[ni][3] = -1e30f;
            }
        }

        float mx0 = -1e30f, mx1 = -1e30f;
#pragma unroll
        for (int ni = 0; ni < 8; ni++) {
            mx0 = fmaxf(mx0, fmaxf(sacc[ni][0], sacc[ni][1]));
            mx1 = fmaxf(mx1, fmaxf(sacc[ni][2], sacc[ni][3]));
        }
        mx0 = fmaxf(mx0, __shfl_xor_sync(0xffffffffu, mx0, 1));
        mx0 = fmaxf(mx0, __shfl_xor_sync(0xffffffffu, mx0, 2));
        mx1 = fmaxf(mx1, __shfl_xor_sync(0xffffffffu, mx1, 1));
        mx1 = fmaxf(mx1, __shfl_xor_sync(0xffffffffu, mx1, 2));

        const float mn0 = fmaxf(m0, mx0);
        const float mn1 = fmaxf(m1, mx1);
        const float corr0 = __expf(m0 - mn0);
        const float corr1 = __expf(m1 - mn1);
        float rs0 = 0.f, rs1 = 0.f;
#pragma unroll
        for (int ni = 0; ni < 8; ni++) {
            float p0 = __expf(sacc[ni][0] - mn0);
            float p1 = __expf(sacc[ni][1] - mn0);
            float p2 = __expf(sacc[ni][2] - mn1);
            float p3 = __expf(sacc[ni][3] - mn1);
            sacc[ni][0] = p0; sacc[ni][1] = p1;
            sacc[ni][2] = p2; sacc[ni][3] = p3;
            rs0 += p0 + p1;
            rs1 += p2 + p3;
        }
        rs0 += __shfl_xor_sync(0xffffffffu, rs0, 1);
        rs0 += __shfl_xor_sync(0xffffffffu, rs0, 2);
        rs1 += __shfl_xor_sync(0xffffffffu, rs1, 1);
        rs1 += __shfl_xor_sync(0xffffffffu, rs1, 2);
        l0 = l0 * corr0 + rs0;
        l1 = l1 * corr1 + rs1;
        m0 = mn0;
        m1 = mn1;
#pragma unroll
        for (int ni = 0; ni < 8; ni++) {
            oacc[ni][0] *= corr0;
            oacc[ni][1] *= corr0;
            oacc[ni][2] *= corr1;
            oacc[ni][3] *= corr1;
        }

#pragma unroll
        for (int ni = 0; ni < 8; ni++) {
            const int cw = ni * 4 + tg;
            uint32_t h0, L0, h1, L1;
            split2(sacc[ni][0], sacc[ni][1], h0, L0);
            split2(sacc[ni][2], sacc[ni][3], h1, L1);
            Ph[(wm + g) * AW + cw] = h0;
            Pl[(wm + g) * AW + cw] = L0;
            Ph[(wm + g + 8) * AW + cw] = h1;
            Pl[(wm + g + 8) * AW + cw] = L1;
        }
        __syncwarp();

#pragma unroll
        for (int ch = 0; ch < 4; ch++) {
            const uint32_t kb = (uint32_t)(ch * 8 * 4);
            uint32_t ph[4], pl[4];
            ldsm_x4(Ph_b + aq_off + kb, ph);
            ldsm_x4(Pl_b + aq_off + kb, pl);
#pragma unroll
            for (int p = 0; p < 4; p++) {
                uint32_t vh4[4], vl4[4];
                ldsm_x4(Vh_b + bk_off + (uint32_t)(p * 16 * AW * 4) + kb, vh4);
                ldsm_x4(Vl_b + bk_off + (uint32_t)(p * 16 * AW * 4) + kb, vl4);
#pragma unroll
                for (int s = 0; s < 2; s++) {
                    const int ni = 2 * p + s;
                    mma_bf16(oacc[ni], ph, vh4[2 * s], vh4[2 * s + 1]);
                    mma_bf16(oacc[ni], pl, vh4[2 * s], vh4[2 * s + 1]);
                    mma_bf16(oacc[ni], ph, vl4[2 * s], vl4[2 * s + 1]);
                }
            }
        }
    }

    const float il0 = 1.0f / l0;
    const float il1 = 1.0f / l1;
    uint32_t* ch_w = reinterpret_cast<uint32_t*>(g_ctx_hi);
    uint32_t* cl_w = reinterpret_cast<uint32_t*>(g_ctx_lo);
    const size_t off0 = (((size_t)(b * S_ + gq0)) * (NH_ * D_) + h * D_) >> 1;
    const size_t off1 = (((size_t)(b * S_ + gq1)) * (NH_ * D_) + h * D_) >> 1;
#pragma unroll
    for (int ni = 0; ni < 8; ni++) {
        const int cw = ni * 4 + tg;
        uint32_t h0, L0, h1, L1;
        split2(oacc[ni][0] * il0, oacc[ni][1] * il0, h0, L0);
        split2(oacc[ni][2] * il1, oacc[ni][3] * il1, h1, L1);
        ch_w[off0 + cw] = h0;
        cl_w[off0 + cw] = L0;
        ch_w[off1 + cw] = h1;
        cl_w[off1 + cw] = L1;
    }
}

// ---------------------------------------------------------------------------
// Launch
// ---------------------------------------------------------------------------
extern "C" void kernel_launch(void* const* d_in, const int* in_sizes, int n_in,
                              void* d_out, int out_size) {
    const int*   positions = (const int*)d_in[0];
    const float* hidden    = (const float*)d_in[1];
    const float* Wqkv      = (const float*)d_in[2];
    const float* Wo        = (const float*)d_in[3];
    float* out = (float*)d_out;

    float* qkv_p;
    bf16 *hh, *hl, *wqh, *wql, *woh, *wol, *cth, *ctl;
    cudaGetSymbolAddress((void**)&qkv_p, g_qkv);
    cudaGetSymbolAddress((void**)&hh,  g_hid_hi);
    cudaGetSymbolAddress((void**)&hl,  g_hid_lo);
    cudaGetSymbolAddress((void**)&wqh, g_wqkv_hi);
    cudaGetSymbolAddress((void**)&wql, g_wqkv_lo);
    cudaGetSymbolAddress((void**)&woh, g_wo_hi);
    cudaGetSymbolAddress((void**)&wol, g_wo_lo);
    cudaGetSymbolAddress((void**)&cth, g_ctx_hi);
    cudaGetSymbolAddress((void**)&ctl, g_ctx_lo);

    cudaFuncSetAttribute(gemm_bf16x3, cudaFuncAttributeMaxDynamicSharedMemorySize, GSMEM);
    cudaFuncSetAttribute(gemm_bf16x3, cudaFuncAttributePreferredSharedMemoryCarveout, 100);
    cudaFuncSetAttribute(attn_kernel, cudaFuncAttributeMaxDynamicSharedMemorySize, ATTN_SMEM);
    cudaFuncSetAttribute(attn_kernel, cudaFuncAttributePreferredSharedMemoryCarveout, 100);

    // 0. Fused pre-pass (split hidden + transpose both weights)
    prepass_kernel<<<NB_SPLIT + NB_WQ + NB_WO, 256>>>(hidden, Wqkv, Wo);

    // 1. QKV projection
    gemm_bf16x3<<<dim3(QKVF / 128, (B_ * S_) / 128), 256, GSMEM>>>(
        hh, hl, wqh, wql, qkv_p, B_ * S_, QKVF, H_);

    // 2. Fused RoPE + V split-transpose
    rope_vt_kernel<<<NB_ROPE + 64 * NKV_ * B_, 256>>>(positions);

    // 3. Causal GQA flash attention
    attn_kernel<<<dim3(S_ / 64, NH_, B_), 128, ATTN_SMEM>>>(nullptr);

    // 4. Output projection
    gemm_bf16x3<<<dim3(H_ / 128, (B_ * S_) / 128), 256, GSMEM>>>(
        cth, ctl, woh, wol, out, B_ * S_, H_, NH_ * D_);
}

// round 12
// speedup vs baseline: 1.0572x; 1.0304x over previous
#include <cuda_runtime.h>
#include <cuda_bf16.h>
#include <math.h>
#include <stdint.h>

#define B_   2
#define S_   2048
#define H_   2048
#define NH_  32
#define NKV_ 8
#define D_   64
#define QKVF ((NH_ + 2 * NKV_) * D_)   // 3072
#define GQA_ (NH_ / NKV_)              // 4

typedef __nv_bfloat16 bf16;

// ---------------------------------------------------------------------------
// Device scratch
// ---------------------------------------------------------------------------
__device__ float g_qkv[(size_t)B_ * S_ * QKVF];
__device__ bf16 g_hid_hi[(size_t)B_ * S_ * H_];
__device__ bf16 g_hid_lo[(size_t)B_ * S_ * H_];
__device__ bf16 g_wqkv_hi[(size_t)QKVF * H_];   // transposed [N][K]
__device__ bf16 g_wqkv_lo[(size_t)QKVF * H_];
__device__ bf16 g_wo_hi[(size_t)H_ * H_];       // transposed [N][K]
__device__ bf16 g_wo_lo[(size_t)H_ * H_];
__device__ bf16 g_q_hi[(size_t)B_ * NH_ * S_ * D_];
__device__ bf16 g_q_lo[(size_t)B_ * NH_ * S_ * D_];
__device__ bf16 g_k_hi[(size_t)B_ * NKV_ * S_ * D_];
__device__ bf16 g_k_lo[(size_t)B_ * NKV_ * S_ * D_];
__device__ bf16 g_vt_hi[(size_t)B_ * NKV_ * D_ * S_];
__device__ bf16 g_vt_lo[(size_t)B_ * NKV_ * D_ * S_];
__device__ bf16 g_ctx_hi[(size_t)B_ * S_ * NH_ * D_];
__device__ bf16 g_ctx_lo[(size_t)B_ * S_ * NH_ * D_];

// ---------------------------------------------------------------------------
// Helpers
// ---------------------------------------------------------------------------
__device__ __forceinline__ uint32_t smem_u32(const void* p) {
    return (uint32_t)__cvta_generic_to_shared(p);
}
__device__ __forceinline__ void cp_async16_sa(uint32_t sa, const void* g) {
    asm volatile("cp.async.cg.shared.global [%0], [%1], 16;\n" :: "r"(sa), "l"(g));
}
__device__ __forceinline__ void cp_commit() {
    asm volatile("cp.async.commit_group;\n");
}
__device__ __forceinline__ uint32_t pack2(float x, float y) {
    uint32_t r;
    asm("cvt.rn.bf16x2.f32 %0, %1, %2;" : "=r"(r) : "f"(y), "f"(x));
    return r;
}
__device__ __forceinline__ void split2(float x, float y, uint32_t& hi, uint32_t& lo) {
    hi = pack2(x, y);
    float hx = __uint_as_float(hi << 16);
    float hy = __uint_as_float(hi & 0xFFFF0000u);
    lo = pack2(x - hx, y - hy);
}
__device__ __forceinline__ void mma_bf16(float* c, const uint32_t* a,
                                         uint32_t b0, uint32_t b1) {
    asm volatile(
        "mma.sync.aligned.m16n8k16.row.col.f32.bf16.bf16.f32 "
        "{%0,%1,%2,%3},{%4,%5,%6,%7},{%8,%9},{%0,%1,%2,%3};"
        : "+f"(c[0]), "+f"(c[1]), "+f"(c[2]), "+f"(c[3])
        : "r"(a[0]), "r"(a[1]), "r"(a[2]), "r"(a[3]), "r"(b0), "r"(b1));
}
__device__ __forceinline__ void ldsm_x4(uint32_t addr, uint32_t* r) {
    asm volatile("ldmatrix.sync.aligned.m8n8.x4.shared.b16 {%0,%1,%2,%3}, [%4];"
                 : "=r"(r[0]), "=r"(r[1]), "=r"(r[2]), "=r"(r[3]) : "r"(addr));
}

// ---------------------------------------------------------------------------
// Fused pre-pass (unchanged from R11 passing version)
// ---------------------------------------------------------------------------
#define NB_SPLIT 8192
#define NB_WQ    6144
#define NB_WO    4096

__global__ void prepass_kernel(const float* __restrict__ hidden,
                               const float* __restrict__ Wqkv,
                               const float* __restrict__ Wo) {
    __shared__ float t[32][33];
    const int bid = blockIdx.x;
    const int tid = threadIdx.x;

    if (bid < NB_SPLIT) {
        int i = bid * 256 + tid;
        float4 v = reinterpret_cast<const float4*>(hidden)[i];
        uint32_t h0, l0, h1, l1;
        split2(v.x, v.y, h0, l0);
        split2(v.z, v.w, h1, l1);
        reinterpret_cast<uint2*>(g_hid_hi)[i] = make_uint2(h0, h1);
        reinterpret_cast<uint2*>(g_hid_lo)[i] = make_uint2(l0, l1);
        return;
    }

    const float* src;
    bf16 *dhi, *dlo;
    int N, bx, by;
    if (bid < NB_SPLIT + NB_WQ) {
        int b2 = bid - NB_SPLIT;
        bx = b2 % (QKVF / 32); by = b2 / (QKVF / 32);
        src = Wqkv; dhi = g_wqkv_hi; dlo = g_wqkv_lo; N = QKVF;
    } else {
        int b2 = bid - NB_SPLIT - NB_WQ;
        bx = b2 % (H_ / 32); by = b2 / (H_ / 32);
        src = Wo; dhi = g_wo_hi; dlo = g_wo_lo; N = H_;
    }
    const int K = H_;
    const int n0 = bx * 32, k0 = by * 32;
    const int tx = tid & 31, ty = tid >> 5;
#pragma unroll
    for (int r = 0; r < 4; r++)
        t[ty + 8 * r][tx] = src[(size_t)(k0 + ty + 8 * r) * N + n0 + tx];
    __syncthreads();
#pragma unroll
    for (int r = 0; r < 4; r++) {
        float x = t[tx][ty + 8 * r];
        bf16 h = __float2bfloat16(x);
        size_t off = (size_t)(n0 + ty + 8 * r) * K + k0 + tx;
        dhi[off] = h;
        dlo[off] = __float2bfloat16(x - __bfloat162float(h));
    }
}

// ---------------------------------------------------------------------------
// Fused RoPE-scatter + V split-transpose (unchanged)
// ---------------------------------------------------------------------------
#define NB_ROPE 20480

__global__ void rope_vt_kernel(const int* __restrict__ positions) {
    if (blockIdx.x < NB_ROPE) {
        const int idx = blockIdx.x * 256 + threadIdx.x;
        const int d = idx & 31;
        int t = idx >> 5;
        const int h = t % (NH_ + NKV_); t /= (NH_ + NKV_);
        const int s = t % S_;
        const int b = t / S_;

        const float pos = (float)positions[s];
        const float inv = powf(10000.0f, -(float)(2 * d) / (float)D_);
        const float freq = pos * inv;
        const double dr = (double)freq;
        const double kq = floor(dr * 0.15915494309189534 + 0.5);
        const float  rr = (float)(dr - kq * 6.283185307179586477);
        float sn, cs;
        sincosf(rr, &sn, &cs);

        const float* base = g_qkv + (size_t)(b * S_ + s) * QKVF;
        float x0, x1, scale;
        bf16 *dhi, *dlo;
        if (h < NH_) {
            x0 = base[h * D_ + d];
            x1 = base[h * D_ + d + 32];
            size_t off = (((size_t)(b * NH_ + h)) * S_ + s) * D_;
            dhi = g_q_hi + off; dlo = g_q_lo + off;
            scale = 0.125f;
        } else {
            const int hk = h - NH_;
            x0 = base[NH_ * D_ + hk * D_ + d];
            x1 = base[NH_ * D_ + hk * D_ + d + 32];
            size_t off = (((size_t)(b * NKV_ + hk)) * S_ + s) * D_;
            dhi = g_k_hi + off; dlo = g_k_lo + off;
            scale = 1.0f;
        }
        float v0 = (x0 * cs - x1 * sn) * scale;
        float v1 = (x1 * cs + x0 * sn) * scale;
        bf16 h0 = __float2bfloat16(v0);
        bf16 h1 = __float2bfloat16(v1);
        dhi[d]      = h0;
        dhi[d + 32] = h1;
        dlo[d]      = __float2bfloat16(v0 - __bfloat162float(h0));
        dlo[d + 32] = __float2bfloat16(v1 - __bfloat162float(h1));
        return;
    }

    __shared__ float t[32][65];
    const int b2 = blockIdx.x - NB_ROPE;
    const int s0 = (b2 & 63) * 32;
    const int kh = (b2 >> 6) & 7;
    const int b  = b2 >> 9;
    const int tid = threadIdx.x;

    const float* src = g_qkv + (size_t)b * S_ * QKVF + (NH_ + NKV_) * D_ + kh * D_;
#pragma unroll
    for (int j = 0; j < 8; j++) {
        int e = tid + j * 256;
        int s = e >> 6, d = e & 63;
        t[s][d] = src[(size_t)(s0 + s) * QKVF + d];
    }
    __syncthreads();

    bf16* dhi = g_vt_hi + ((size_t)(b * NKV_ + kh)) * D_ * S_;
    bf16* dlo = g_vt_lo + ((size_t)(b * NKV_ + kh)) * D_ * S_;
#pragma unroll
    for (int j = 0; j < 8; j++) {
        int e = tid + j * 256;
        int d = e >> 5, s = e & 31;
        float x = t[s][d];
        bf16 h = __float2bfloat16(x);
        dhi[(size_t)d * S_ + s0 + s] = h;
        dlo[(size_t)d * S_ + s0 + s] = __float2bfloat16(x - __bfloat162float(h));
    }
}

// ---------------------------------------------------------------------------
// bf16x3 GEMM (R9/R11 passing version, unchanged)
// ---------------------------------------------------------------------------
#define PW 20
#define TILE_W (128 * PW)
#define GSMEM (2 * 4 * TILE_W * 4)   // 81920 B

__global__ __launch_bounds__(256, 2)
void gemm_bf16x3(const bf16* __restrict__ Ahi, const bf16* __restrict__ Alo,
                 const bf16* __restrict__ Bhi, const bf16* __restrict__ Blo,
                 float* __restrict__ C, int M, int N, int K) {
    extern __shared__ uint32_t sw[];
    const uint32_t sbase = smem_u32(sw);

    const int tid  = threadIdx.x;
    const int wid  = tid >> 5;
    const int lane = tid & 31;
    const int g  = lane >> 2;
    const int tg = lane & 3;
    const int wm = (wid & 3) * 32;
    const int wn = (wid >> 2) * 64;

    const bf16* gptr[4] = {
        Ahi + (size_t)blockIdx.y * 128 * K,
        Alo + (size_t)blockIdx.y * 128 * K,
        Bhi + (size_t)blockIdx.x * 128 * K,
        Blo + (size_t)blockIdx.x * 128 * K
    };

    const uint32_t a_off = (uint32_t)(((wm + (lane & 15)) * PW + (lane >> 4) * 4) * 4);
    const uint32_t b_off = (uint32_t)(((wn + ((lane >> 4) << 3) + (lane & 7)) * PW
                                       + ((lane >> 3) & 1) * 4) * 4);

    float acc[2][8][4];
#pragma unroll
    for (int mi = 0; mi < 2; mi++)
#pragma unroll
        for (int ni = 0; ni < 8; ni++)
#pragma unroll
            for (int r = 0; r < 4; r++) acc[mi][ni][r] = 0.f;

#define GEMM_LOAD(st, k0)                                                     \
    {                                                                          \
        uint32_t s0 = sbase + (st) * (4 * TILE_W) * 4;                         \
        _Pragma("unroll")                                                      \
        for (int j = 0; j < 8; j++) {                                          \
            int idx = tid + j * 256;                                           \
            int arr = j >> 1;                                                  \
            int r = (idx >> 2) & 127, c = idx & 3;                             \
            cp_async16_sa(s0 + (arr * TILE_W + r * PW + c * 4) * 4,            \
                          gptr[arr] + (size_t)r * K + (k0) + c * 8);           \
        }                                                                      \
        cp_commit();                                                           \
    }

    const int NIT = K / 32;
    GEMM_LOAD(0, 0);

    for (int it = 0; it < NIT; ++it) {
        const int st = it & 1;
        asm volatile("cp.async.wait_group 0;\n" ::: "memory");
        __syncthreads();
        if (it + 1 < NIT) GEMM_LOAD(st ^ 1, (it + 1) * 32);

        const uint32_t sA_h = sbase + (st * 4 * TILE_W) * 4;
        const uint32_t sA_l = sA_h + TILE_W * 4;
        const uint32_t sB_h = sA_h + 2 * TILE_W * 4;
        const uint32_t sB_l = sA_h + 3 * TILE_W * 4;

#pragma unroll
        for (int ch = 0; ch < 2; ch++) {
            const uint32_t kb = (uint32_t)(ch * 8 * 4);
            uint32_t ah[2][4], al[2][4];
#pragma unroll
            for (int mi = 0; mi < 2; mi++) {
                ldsm_x4(sA_h + a_off + (uint32_t)(mi * 16 * PW * 4) + kb, ah[mi]);
                ldsm_x4(sA_l + a_off + (uint32_t)(mi * 16 * PW * 4) + kb, al[mi]);
            }
#pragma unroll
            for (int p = 0; p < 4; p++) {
                uint32_t bh[4], bl[4];
                ldsm_x4(sB_h + b_off + (uint32_t)(p * 16 * PW * 4) + kb, bh);
                ldsm_x4(sB_l + b_off + (uint32_t)(p * 16 * PW * 4) + kb, bl);
#pragma unroll
                for (int s = 0; s < 2; s++) {
                    const int ni = 2 * p + s;
#pragma unroll
                    for (int mi = 0; mi < 2; mi++) {
                        mma_bf16(acc[mi][ni], ah[mi], bh[2 * s], bh[2 * s + 1]);
                        mma_bf16(acc[mi][ni], al[mi], bh[2 * s], bh[2 * s + 1]);
                        mma_bf16(acc[mi][ni], ah[mi], bl[2 * s], bl[2 * s + 1]);
                    }
                }
            }
        }
    }

#pragma unroll
    for (int mi = 0; mi < 2; mi++) {
        const int row = blockIdx.y * 128 + wm + mi * 16 + g;
#pragma unroll
        for (int ni = 0; ni < 8; ni++) {
            const int col = blockIdx.x * 128 + wn + ni * 8 + 2 * tg;
            *reinterpret_cast<float2*>(C + (size_t)row * N + col) =
                make_float2(acc[mi][ni][0], acc[mi][ni][1]);
            *reinterpret_cast<float2*>(C + (size_t)(row + 8) * N + col) =
                make_float2(acc[mi][ni][2], acc[mi][ni][3]);
        }
    }
}

// ---------------------------------------------------------------------------
// bf16x3 causal flash attention. 64 q-rows, 128 thr, 2 CTAs/SM, ldmatrix.
// NEW: P stays in registers — QK's C-fragment layout == PV's A-fragment
// layout, so softmax output feeds PV MMAs directly (no smem round-trip).
// smem tiles (AW=36 stride): Qh=0 Ql=1 | Kh/Kl=2+2st,3+2st | Vh/Vl=6+2st,7+2st
// ---------------------------------------------------------------------------
#define AW 36
#define AT_W (64 * AW)
#define ATTN_SMEM (10 * AT_W * 4)    // 92160 B

__global__ __launch_bounds__(128, 2)
void attn_kernel(float* /*unused*/) {
    extern __shared__ uint32_t sw[];
    const uint32_t sbase = smem_u32(sw);

    const int qtile = gridDim.x - 1 - blockIdx.x;
    const int h = blockIdx.y;
    const int b = blockIdx.z;
    const int kvh = h / GQA_;
    const int q0 = qtile * 64;

    const bf16* qh_g = g_q_hi + (((size_t)(b * NH_ + h)) * S_ + q0) * D_;
    const bf16* ql_g = g_q_lo + (((size_t)(b * NH_ + h)) * S_ + q0) * D_;
    const bf16* kh_g = g_k_hi + ((size_t)(b * NKV_ + kvh)) * S_ * D_;
    const bf16* kl_g = g_k_lo + ((size_t)(b * NKV_ + kvh)) * S_ * D_;
    const bf16* vh_g = g_vt_hi + ((size_t)(b * NKV_ + kvh)) * D_ * S_;
    const bf16* vl_g = g_vt_lo + ((size_t)(b * NKV_ + kvh)) * D_ * S_;

    const int tid  = threadIdx.x;
    const int wid  = tid >> 5;
    const int lane = tid & 31;
    const int g  = lane >> 2;
    const int tg = lane & 3;
    const int wm = wid * 16;

    const uint32_t aq_off = (uint32_t)(((wm + (lane & 15)) * AW + (lane >> 4) * 4) * 4);
    const uint32_t bk_off = (uint32_t)(((((lane >> 4) << 3) + (lane & 7)) * AW
                                        + ((lane >> 3) & 1) * 4) * 4);

#pragma unroll
    for (int j = 0; j < 8; j++) {
        int idx = tid + j * 128;
        int r = (idx >> 3) & 63, c = idx & 7;
        const bf16* src = (j >> 2) ? ql_g : qh_g;
        cp_async16_sa(sbase + ((j >> 2) * AT_W + r * AW + c * 4) * 4,
                      src + (size_t)r * D_ + c * 8);
    }
    cp_commit();

#define ATTN_LOAD_KV(st, kt)                                                    \
    {                                                                            \
        _Pragma("unroll")                                                        \
        for (int j = 0; j < 16; j++) {                                           \
            int idx = tid + j * 128;                                              \
            int arr = j >> 2;                                                     \
            int r = (idx >> 3) & 63, c = idx & 7;                                 \
            int tile = (arr < 2 ? 2 : 6) + 2 * (st) + (arr & 1);                  \
            const bf16* src;                                                      \
            size_t goff;                                                          \
            if (arr == 0)      { src = kh_g; goff = (size_t)((kt) * 64 + r) * D_ + c * 8; } \
            else if (arr == 1) { src = kl_g; goff = (size_t)((kt) * 64 + r) * D_ + c * 8; } \
            else if (arr == 2) { src = vh_g; goff = (size_t)r * S_ + (kt) * 64 + c * 8; }   \
            else               { src = vl_g; goff = (size_t)r * S_ + (kt) * 64 + c * 8; }   \
            cp_async16_sa(sbase + (tile * AT_W + r * AW + c * 4) * 4, src + goff); \
        }                                                                         \
        cp_commit();                                                              \
    }

    ATTN_LOAD_KV(0, 0);

    float oacc[8][4];
    float m0 = -1e30f, m1 = -1e30f, l0 = 0.f, l1 = 0.f;
#pragma unroll
    for (int ni = 0; ni < 8; ni++)
#pragma unroll
        for (int r = 0; r < 4; r++) oacc[ni][r] = 0.f;

    const int gq0 = q0 + wm + g;
    const int gq1 = gq0 + 8;

    const uint32_t Qh_b = sbase;
    const uint32_t Ql_b = sbase + AT_W * 4;

    for (int kt = 0; kt <= qtile; kt++) {
        const int cur = kt & 1;
        asm volatile("cp.async.wait_group 0;\n" ::: "memory");
        __syncthreads();
        if (kt + 1 <= qtile) ATTN_LOAD_KV(cur ^ 1, kt + 1);

        const uint32_t Kh_b = sbase + (2 + 2 * cur) * AT_W * 4;
        const uint32_t Kl_b = sbase + (3 + 2 * cur) * AT_W * 4;
        const uint32_t Vh_b = sbase + (6 + 2 * cur) * AT_W * 4;
        const uint32_t Vl_b = sbase + (7 + 2 * cur) * AT_W * 4;

        // ---- S = Q @ K^T ----
        float sacc[8][4];
#pragma unroll
        for (int ni = 0; ni < 8; ni++)
#pragma unroll
            for (int r = 0; r < 4; r++) sacc[ni][r] = 0.f;

#pragma unroll
        for (int ch = 0; ch < 4; ch++) {
            const uint32_t kb = (uint32_t)(ch * 8 * 4);
            uint32_t qh[4], ql[4];
            ldsm_x4(Qh_b + aq_off + kb, qh);
            ldsm_x4(Ql_b + aq_off + kb, ql);
#pragma unroll
            for (int p = 0; p < 4; p++) {
                uint32_t kh4[4], kl4[4];
                ldsm_x4(Kh_b + bk_off + (uint32_t)(p * 16 * AW * 4) + kb, kh4);
                ldsm_x4(Kl_b + bk_off + (uint32_t)(p * 16 * AW * 4) + kb, kl4);
#pragma unroll
                for (int s = 0; s < 2; s++) {
                    const int ni = 2 * p + s;
                    mma_bf16(sacc[ni], qh, kh4[2 * s], kh4[2 * s + 1]);
                    mma_bf16(sacc[ni], ql, kh4[2 * s], kh4[2 * s + 1]);
                    mma_bf16(sacc[ni], qh, kl4[2 * s], kl4[2 * s + 1]);
                }
            }
        }

        // ---- causal mask ----
        if (kt == qtile) {
#pragma unroll
            for (int ni = 0; ni < 8; ni++) {
                const int col = kt * 64 + ni * 8 + 2 * tg;
                if (col     > gq0) sacc[ni][0] = -1e30f;
                if (col + 1 > gq0) sacc[ni][1] = -1e30f;
                if (col     > gq1) sacc[ni][2] = -1e30f;
                if (col + 1 > gq1) sacc[ni][3] = -1e30f;
            }
        }

        // ---- online softmax ----
        float mx0 = -1e30f, mx1 = -1e30f;
#pragma unroll
        for (int ni = 0; ni < 8; ni++) {
            mx0 = fmaxf(mx0, fmaxf(sacc[ni][0], sacc[ni][1]));
            mx1 = fmaxf(mx1, fmaxf(sacc[ni][2], sacc[ni][3]));
        }
        mx0 = fmaxf(mx0, __shfl_xor_sync(0xffffffffu, mx0, 1));
        mx0 = fmaxf(mx0, __shfl_xor_sync(0xffffffffu, mx0, 2));
        mx1 = fmaxf(mx1, __shfl_xor_sync(0xffffffffu, mx1, 1));
        mx1 = fmaxf(mx1, __shfl_xor_sync(0xffffffffu, mx1, 2));

        const float mn0 = fmaxf(m0, mx0);
        const float mn1 = fmaxf(m1, mx1);
        const float corr0 = __expf(m0 - mn0);
        const float corr1 = __expf(m1 - mn1);
        float rs0 = 0.f, rs1 = 0.f;
#pragma unroll
        for (int ni = 0; ni < 8; ni++) {
            float p0 = __expf(sacc[ni][0] - mn0);
            float p1 = __expf(sacc[ni][1] - mn0);
            float p2 = __expf(sacc[ni][2] - mn1);
            float p3 = __expf(sacc[ni][3] - mn1);
            sacc[ni][0] = p0; sacc[ni][1] = p1;
            sacc[ni][2] = p2; sacc[ni][3] = p3;
            rs0 += p0 + p1;
            rs1 += p2 + p3;
        }
        rs0 += __shfl_xor_sync(0xffffffffu, rs0, 1);
        rs0 += __shfl_xor_sync(0xffffffffu, rs0, 2);
        rs1 += __shfl_xor_sync(0xffffffffu, rs1, 1);
        rs1 += __shfl_xor_sync(0xffffffffu, rs1, 2);
        l0 = l0 * corr0 + rs0;
        l1 = l1 * corr1 + rs1;
        m0 = mn0;
        m1 = mn1;
#pragma unroll
        for (int ni = 0; ni < 8; ni++) {
            oacc[ni][0] *= corr0;
            oacc[ni][1] *= corr0;
            oacc[ni][2] *= corr1;
            oacc[ni][3] *= corr1;
        }

        // ---- O += P @ V : P fed straight from registers ----
        // C-fragment of QK == A-fragment of PV for k-block ch:
        //   a0 = (g, 2tg..)   = sacc[2ch][0,1]
        //   a1 = (g+8, 2tg..) = sacc[2ch][2,3]
        //   a2 = (g, 2tg+8..) = sacc[2ch+1][0,1]
        //   a3 = (g+8,2tg+8..)= sacc[2ch+1][2,3]
#pragma unroll
        for (int ch = 0; ch < 4; ch++) {
            const uint32_t kb = (uint32_t)(ch * 8 * 4);
            uint32_t ph[4], pl[4];
            split2(sacc[2 * ch][0],     sacc[2 * ch][1],     ph[0], pl[0]);
            split2(sacc[2 * ch][2],     sacc[2 * ch][3],     ph[1], pl[1]);
            split2(sacc[2 * ch + 1][0], sacc[2 * ch + 1][1], ph[2], pl[2]);
            split2(sacc[2 * ch + 1][2], sacc[2 * ch + 1][3], ph[3], pl[3]);
#pragma unroll
            for (int p = 0; p < 4; p++) {
                uint32_t vh4[4], vl4[4];
                ldsm_x4(Vh_b + bk_off + (uint32_t)(p * 16 * AW * 4) + kb, vh4);
                ldsm_x4(Vl_b + bk_off + (uint32_t)(p * 16 * AW * 4) + kb, vl4);
#pragma unroll
                for (int s = 0; s < 2; s++) {
                    const int ni = 2 * p + s;
                    mma_bf16(oacc[ni], ph, vh4[2 * s], vh4[2 * s + 1]);
                    mma_bf16(oacc[ni], pl, vh4[2 * s], vh4[2 * s + 1]);
                    mma_bf16(oacc[ni], ph, vl4[2 * s], vl4[2 * s + 1]);
                }
            }
        }
    }

    const float il0 = 1.0f / l0;
    const float il1 = 1.0f / l1;
    uint32_t* ch_w = reinterpret_cast<uint32_t*>(g_ctx_hi);
    uint32_t* cl_w = reinterpret_cast<uint32_t*>(g_ctx_lo);
    const size_t off0 = (((size_t)(b * S_ + gq0)) * (NH_ * D_) + h * D_) >> 1;
    const size_t off1 = (((size_t)(b * S_ + gq1)) * (NH_ * D_) + h * D_) >> 1;
#pragma unroll
    for (int ni = 0; ni < 8; ni++) {
        const int cw = ni * 4 + tg;
        uint32_t h0, L0, h1, L1;
        split2(oacc[ni][0] * il0, oacc[ni][1] * il0, h0, L0);
        split2(oacc[ni][2] * il1, oacc[ni][3] * il1, h1, L1);
        ch_w[off0 + cw] = h0;
        cl_w[off0 + cw] = L0;
        ch_w[off1 + cw] = h1;
        cl_w[off1 + cw] = L1;
    }
}

// ---------------------------------------------------------------------------
// Launch
// ---------------------------------------------------------------------------
extern "C" void kernel_launch(void* const* d_in, const int* in_sizes, int n_in,
                              void* d_out, int out_size) {
    const int*   positions = (const int*)d_in[0];
    const float* hidden    = (const float*)d_in[1];
    const float* Wqkv      = (const float*)d_in[2];
    const float* Wo        = (const float*)d_in[3];
    float* out = (float*)d_out;

    float* qkv_p;
    bf16 *hh, *hl, *wqh, *wql, *woh, *wol, *cth, *ctl;
    cudaGetSymbolAddress((void**)&qkv_p, g_qkv);
    cudaGetSymbolAddress((void**)&hh,  g_hid_hi);
    cudaGetSymbolAddress((void**)&hl,  g_hid_lo);
    cudaGetSymbolAddress((void**)&wqh, g_wqkv_hi);
    cudaGetSymbolAddress((void**)&wql, g_wqkv_lo);
    cudaGetSymbolAddress((void**)&woh, g_wo_hi);
    cudaGetSymbolAddress((void**)&wol, g_wo_lo);
    cudaGetSymbolAddress((void**)&cth, g_ctx_hi);
    cudaGetSymbolAddress((void**)&ctl, g_ctx_lo);

    cudaFuncSetAttribute(gemm_bf16x3, cudaFuncAttributeMaxDynamicSharedMemorySize, GSMEM);
    cudaFuncSetAttribute(gemm_bf16x3, cudaFuncAttributePreferredSharedMemoryCarveout, 100);
    cudaFuncSetAttribute(attn_kernel, cudaFuncAttributeMaxDynamicSharedMemorySize, ATTN_SMEM);
    cudaFuncSetAttribute(attn_kernel, cudaFuncAttributePreferredSharedMemoryCarveout, 100);

    // 0. Fused pre-pass (split hidden + transpose both weights)
    prepass_kernel<<<NB_SPLIT + NB_WQ + NB_WO, 256>>>(hidden, Wqkv, Wo);

    // 1. QKV projection
    gemm_bf16x3<<<dim3(QKVF / 128, (B_ * S_) / 128), 256, GSMEM>>>(
        hh, hl, wqh, wql, qkv_p, B_ * S_, QKVF, H_);

    // 2. Fused RoPE + V split-transpose
    rope_vt_kernel<<<NB_ROPE + 64 * NKV_ * B_, 256>>>(positions);

    // 3. Causal GQA flash attention (P register-resident)
    attn_kernel<<<dim3(S_ / 64, NH_, B_), 128, ATTN_SMEM>>>(nullptr);

    // 4. Output projection
    gemm_bf16x3<<<dim3(H_ / 128, (B_ * S_) / 128), 256, GSMEM>>>(
        cth, ctl, woh, wol, out, B_ * S_, H_, NH_ * D_);
}

// round 13
// speedup vs baseline: 1.0900x; 1.0310x over previous
#include <cuda_runtime.h>
#include <cuda_bf16.h>
#include <math.h>
#include <stdint.h>

#define B_   2
#define S_   2048
#define H_   2048
#define NH_  32
#define NKV_ 8
#define D_   64
#define QKVF ((NH_ + 2 * NKV_) * D_)   // 3072
#define GQA_ (NH_ / NKV_)              // 4

typedef __nv_bfloat16 bf16;

// ---------------------------------------------------------------------------
// Device scratch
// ---------------------------------------------------------------------------
__device__ float g_qkv[(size_t)B_ * S_ * QKVF];     // only V region written now
__device__ bf16 g_hid_hi[(size_t)B_ * S_ * H_];
__device__ bf16 g_hid_lo[(size_t)B_ * S_ * H_];
__device__ bf16 g_wqkv_hi[(size_t)QKVF * H_];       // transposed [N][K]
__device__ bf16 g_wqkv_lo[(size_t)QKVF * H_];
__device__ bf16 g_wo_hi[(size_t)H_ * H_];           // transposed [N][K]
__device__ bf16 g_wo_lo[(size_t)H_ * H_];
__device__ bf16 g_q_hi[(size_t)B_ * NH_ * S_ * D_];
__device__ bf16 g_q_lo[(size_t)B_ * NH_ * S_ * D_];
__device__ bf16 g_k_hi[(size_t)B_ * NKV_ * S_ * D_];
__device__ bf16 g_k_lo[(size_t)B_ * NKV_ * S_ * D_];
__device__ bf16 g_vt_hi[(size_t)B_ * NKV_ * D_ * S_];
__device__ bf16 g_vt_lo[(size_t)B_ * NKV_ * D_ * S_];
__device__ bf16 g_ctx_hi[(size_t)B_ * S_ * NH_ * D_];
__device__ bf16 g_ctx_lo[(size_t)B_ * S_ * NH_ * D_];

// ---------------------------------------------------------------------------
// Helpers
// ---------------------------------------------------------------------------
__device__ __forceinline__ uint32_t smem_u32(const void* p) {
    return (uint32_t)__cvta_generic_to_shared(p);
}
__device__ __forceinline__ void cp_async16_sa(uint32_t sa, const void* g) {
    asm volatile("cp.async.cg.shared.global [%0], [%1], 16;\n" :: "r"(sa), "l"(g));
}
__device__ __forceinline__ void cp_commit() {
    asm volatile("cp.async.commit_group;\n");
}
__device__ __forceinline__ uint32_t pack2(float x, float y) {
    uint32_t r;
    asm("cvt.rn.bf16x2.f32 %0, %1, %2;" : "=r"(r) : "f"(y), "f"(x));
    return r;
}
__device__ __forceinline__ void split2(float x, float y, uint32_t& hi, uint32_t& lo) {
    hi = pack2(x, y);
    float hx = __uint_as_float(hi << 16);
    float hy = __uint_as_float(hi & 0xFFFF0000u);
    lo = pack2(x - hx, y - hy);
}
__device__ __forceinline__ void mma_bf16(float* c, const uint32_t* a,
                                         uint32_t b0, uint32_t b1) {
    asm volatile(
        "mma.sync.aligned.m16n8k16.row.col.f32.bf16.bf16.f32 "
        "{%0,%1,%2,%3},{%4,%5,%6,%7},{%8,%9},{%0,%1,%2,%3};"
        : "+f"(c[0]), "+f"(c[1]), "+f"(c[2]), "+f"(c[3])
        : "r"(a[0]), "r"(a[1]), "r"(a[2]), "r"(a[3]), "r"(b0), "r"(b1));
}
__device__ __forceinline__ void ldsm_x4(uint32_t addr, uint32_t* r) {
    asm volatile("ldmatrix.sync.aligned.m8n8.x4.shared.b16 {%0,%1,%2,%3}, [%4];"
                 : "=r"(r[0]), "=r"(r[1]), "=r"(r[2]), "=r"(r[3]) : "r"(addr));
}
// exact same sincos path as the original rope kernel
__device__ __forceinline__ void rope_sincos(float pos, int d, float& sn, float& cs) {
    const float inv = powf(10000.0f, -(float)(2 * d) / (float)D_);
    const float freq = pos * inv;
    const double dr = (double)freq;
    const double kq = floor(dr * 0.15915494309189534 + 0.5);
    const float  rr = (float)(dr - kq * 6.283185307179586477);
    sincosf(rr, &sn, &cs);
}

// ---------------------------------------------------------------------------
// Fused pre-pass (unchanged)
// ---------------------------------------------------------------------------
#define NB_SPLIT 8192
#define NB_WQ    6144
#define NB_WO    4096

__global__ void prepass_kernel(const float* __restrict__ hidden,
                               const float* __restrict__ Wqkv,
                               const float* __restrict__ Wo) {
    __shared__ float t[32][33];
    const int bid = blockIdx.x;
    const int tid = threadIdx.x;

    if (bid < NB_SPLIT) {
        int i = bid * 256 + tid;
        float4 v = reinterpret_cast<const float4*>(hidden)[i];
        uint32_t h0, l0, h1, l1;
        split2(v.x, v.y, h0, l0);
        split2(v.z, v.w, h1, l1);
        reinterpret_cast<uint2*>(g_hid_hi)[i] = make_uint2(h0, h1);
        reinterpret_cast<uint2*>(g_hid_lo)[i] = make_uint2(l0, l1);
        return;
    }

    const float* src;
    bf16 *dhi, *dlo;
    int N, bx, by;
    if (bid < NB_SPLIT + NB_WQ) {
        int b2 = bid - NB_SPLIT;
        bx = b2 % (QKVF / 32); by = b2 / (QKVF / 32);
        src = Wqkv; dhi = g_wqkv_hi; dlo = g_wqkv_lo; N = QKVF;
    } else {
        int b2 = bid - NB_SPLIT - NB_WQ;
        bx = b2 % (H_ / 32); by = b2 / (H_ / 32);
        src = Wo; dhi = g_wo_hi; dlo = g_wo_lo; N = H_;
    }
    const int K = H_;
    const int n0 = bx * 32, k0 = by * 32;
    const int tx = tid & 31, ty = tid >> 5;
#pragma unroll
    for (int r = 0; r < 4; r++)
        t[ty + 8 * r][tx] = src[(size_t)(k0 + ty + 8 * r) * N + n0 + tx];
    __syncthreads();
#pragma unroll
    for (int r = 0; r < 4; r++) {
        float x = t[tx][ty + 8 * r];
        bf16 h = __float2bfloat16(x);
        size_t off = (size_t)(n0 + ty + 8 * r) * K + k0 + tx;
        dhi[off] = h;
        dlo[off] = __float2bfloat16(x - __bfloat162float(h));
    }
}

// ---------------------------------------------------------------------------
// V split + transpose into [b][kh][d][s] (only remaining scatter pre-pass)
// ---------------------------------------------------------------------------
__global__ void vt_kernel() {
    __shared__ float t[32][65];
    const int s0 = blockIdx.x * 32;
    const int kh = blockIdx.y;
    const int b  = blockIdx.z;
    const int tid = threadIdx.x;

    const float* src = g_qkv + (size_t)b * S_ * QKVF + (NH_ + NKV_) * D_ + kh * D_;
#pragma unroll
    for (int j = 0; j < 8; j++) {
        int e = tid + j * 256;
        int s = e >> 6, d = e & 63;
        t[s][d] = src[(size_t)(s0 + s) * QKVF + d];
    }
    __syncthreads();

    bf16* dhi = g_vt_hi + ((size_t)(b * NKV_ + kh)) * D_ * S_;
    bf16* dlo = g_vt_lo + ((size_t)(b * NKV_ + kh)) * D_ * S_;
#pragma unroll
    for (int j = 0; j < 8; j++) {
        int e = tid + j * 256;
        int d = e >> 5, s = e & 31;
        float x = t[s][d];
        bf16 h = __float2bfloat16(x);
        dhi[(size_t)d * S_ + s0 + s] = h;
        dlo[(size_t)d * S_ + s0 + s] = __float2bfloat16(x - __bfloat162float(h));
    }
}

// ---------------------------------------------------------------------------
// Shared GEMM mainloop pieces (128x128x32, 256 thr, 2-stage, ldmatrix)
// ---------------------------------------------------------------------------
#define PW 20
#define TILE_W (128 * PW)
#define GSMEM (2 * 4 * TILE_W * 4)   // 81920 B

#define GEMM_LOAD(st, k0)                                                     \
    {                                                                          \
        uint32_t s0 = sbase + (st) * (4 * TILE_W) * 4;                         \
        _Pragma("unroll")                                                      \
        for (int j = 0; j < 8; j++) {                                          \
            int idx = tid + j * 256;                                           \
            int arr = j >> 1;                                                  \
            int r = (idx >> 2) & 127, c = idx & 3;                             \
            cp_async16_sa(s0 + (arr * TILE_W + r * PW + c * 4) * 4,            \
                          gptr[arr] + (size_t)r * K + (k0) + c * 8);           \
        }                                                                      \
        cp_commit();                                                           \
    }

#define GEMM_MAINLOOP(K)                                                       \
    const int NIT = (K) / 32;                                                  \
    GEMM_LOAD(0, 0);                                                           \
    for (int it = 0; it < NIT; ++it) {                                         \
        const int st = it & 1;                                                 \
        asm volatile("cp.async.wait_group 0;\n" ::: "memory");                 \
        __syncthreads();                                                       \
        if (it + 1 < NIT) GEMM_LOAD(st ^ 1, (it + 1) * 32);                    \
        const uint32_t sA_h = sbase + (st * 4 * TILE_W) * 4;                   \
        const uint32_t sA_l = sA_h + TILE_W * 4;                               \
        const uint32_t sB_h = sA_h + 2 * TILE_W * 4;                           \
        const uint32_t sB_l = sA_h + 3 * TILE_W * 4;                           \
        _Pragma("unroll")                                                      \
        for (int ch = 0; ch < 2; ch++) {                                       \
            const uint32_t kb = (uint32_t)(ch * 8 * 4);                        \
            uint32_t ah[2][4], al[2][4];                                       \
            _Pragma("unroll")                                                  \
            for (int mi = 0; mi < 2; mi++) {                                   \
                ldsm_x4(sA_h + a_off + (uint32_t)(mi * 16 * PW * 4) + kb, ah[mi]); \
                ldsm_x4(sA_l + a_off + (uint32_t)(mi * 16 * PW * 4) + kb, al[mi]); \
            }                                                                  \
            _Pragma("unroll")                                                  \
            for (int p = 0; p < 4; p++) {                                      \
                uint32_t bh[4], bl[4];                                         \
                ldsm_x4(sB_h + b_off + (uint32_t)(p * 16 * PW * 4) + kb, bh);  \
                ldsm_x4(sB_l + b_off + (uint32_t)(p * 16 * PW * 4) + kb, bl);  \
                _Pragma("unroll")                                              \
                for (int s = 0; s < 2; s++) {                                  \
                    const int ni = 2 * p + s;                                  \
                    _Pragma("unroll")                                          \
                    for (int mi = 0; mi < 2; mi++) {                           \
                        mma_bf16(acc[mi][ni], ah[mi], bh[2 * s], bh[2 * s + 1]); \
                        mma_bf16(acc[mi][ni], al[mi], bh[2 * s], bh[2 * s + 1]); \
                        mma_bf16(acc[mi][ni], ah[mi], bl[2 * s], bl[2 * s + 1]); \
                    }                                                          \
                }                                                              \
            }                                                                  \
        }                                                                      \
    }

#define GEMM_PROLOG(Ahi, Alo, Bhi, Blo, K)                                     \
    extern __shared__ uint32_t sw[];                                           \
    const uint32_t sbase = smem_u32(sw);                                       \
    const int tid  = threadIdx.x;                                              \
    const int wid  = tid >> 5;                                                 \
    const int lane = tid & 31;                                                 \
    const int g  = lane >> 2;                                                  \
    const int tg = lane & 3;                                                   \
    const int wm = (wid & 3) * 32;                                             \
    const int wn = (wid >> 2) * 64;                                            \
    const bf16* gptr[4] = {                                                    \
        (Ahi) + (size_t)blockIdx.y * 128 * (K),                                \
        (Alo) + (size_t)blockIdx.y * 128 * (K),                                \
        (Bhi) + (size_t)blockIdx.x * 128 * (K),                                \
        (Blo) + (size_t)blockIdx.x * 128 * (K)                                 \
    };                                                                         \
    const uint32_t a_off = (uint32_t)(((wm + (lane & 15)) * PW + (lane >> 4) * 4) * 4); \
    const uint32_t b_off = (uint32_t)(((wn + ((lane >> 4) << 3) + (lane & 7)) * PW      \
                                       + ((lane >> 3) & 1) * 4) * 4);          \
    float acc[2][8][4];                                                        \
    _Pragma("unroll")                                                          \
    for (int mi = 0; mi < 2; mi++)                                             \
        _Pragma("unroll")                                                      \
        for (int ni = 0; ni < 8; ni++)                                         \
            _Pragma("unroll")                                                  \
            for (int r = 0; r < 4; r++) acc[mi][ni][r] = 0.f;

// ---------------------------------------------------------------------------
// Generic GEMM (used for Wo projection): C = A @ Bt^T, fp32 out
// ---------------------------------------------------------------------------
__global__ __launch_bounds__(256, 2)
void gemm_bf16x3(const bf16* __restrict__ Ahi, const bf16* __restrict__ Alo,
                 const bf16* __restrict__ Bhi, const bf16* __restrict__ Blo,
                 float* __restrict__ C, int M, int N, int K) {
    GEMM_PROLOG(Ahi, Alo, Bhi, Blo, K)
    GEMM_MAINLOOP(K)
#pragma unroll
    for (int mi = 0; mi < 2; mi++) {
        const int row = blockIdx.y * 128 + wm + mi * 16 + g;
#pragma unroll
        for (int ni = 0; ni < 8; ni++) {
            const int col = blockIdx.x * 128 + wn + ni * 8 + 2 * tg;
            *reinterpret_cast<float2*>(C + (size_t)row * N + col) =
                make_float2(acc[mi][ni][0], acc[mi][ni][1]);
            *reinterpret_cast<float2*>(C + (size_t)(row + 8) * N + col) =
                make_float2(acc[mi][ni][2], acc[mi][ni][3]);
        }
    }
}

// ---------------------------------------------------------------------------
// QKV GEMM with fused RoPE epilogue.
// Q cols [0,2048): rope, scale 1/8, write split to g_q.
// K cols [2048,2560): rope, write split to g_k.
// V cols [2560,3072): write fp32 to g_qkv (vt_kernel transposes later).
// Fragment pairing: for ni<4, acc[mi][ni] holds d (<32) and acc[mi][ni+4]
// holds d+32 of the SAME rows — rope is register-local.
// ---------------------------------------------------------------------------
__global__ __launch_bounds__(256, 2)
void gemm_qkv(const bf16* __restrict__ Ahi, const bf16* __restrict__ Alo,
              const bf16* __restrict__ Bhi, const bf16* __restrict__ Blo,
              const int* __restrict__ positions) {
    const int K = H_;
    GEMM_PROLOG(Ahi, Alo, Bhi, Blo, K)
    GEMM_MAINLOOP(K)

    const int tileN0 = blockIdx.x * 128;
    if (tileN0 >= (NH_ + NKV_) * D_) {
        // V tile: plain fp32 store into g_qkv
#pragma unroll
        for (int mi = 0; mi < 2; mi++) {
            const int row = blockIdx.y * 128 + wm + mi * 16 + g;
#pragma unroll
            for (int ni = 0; ni < 8; ni++) {
                const int col = tileN0 + wn + ni * 8 + 2 * tg;
                *reinterpret_cast<float2*>(g_qkv + (size_t)row * QKVF + col) =
                    make_float2(acc[mi][ni][0], acc[mi][ni][1]);
                *reinterpret_cast<float2*>(g_qkv + (size_t)(row + 8) * QKVF + col) =
                    make_float2(acc[mi][ni][2], acc[mi][ni][3]);
            }
        }
        return;
    }

    const bool isQ = tileN0 < NH_ * D_;
    const float scale = isQ ? 0.125f : 1.0f;
    bf16* phi = isQ ? g_q_hi : g_k_hi;
    bf16* plo = isQ ? g_q_lo : g_k_lo;

#pragma unroll
    for (int mi = 0; mi < 2; mi++) {
#pragma unroll
        for (int rh = 0; rh < 2; rh++) {
            const int row = blockIdx.y * 128 + wm + mi * 16 + g + rh * 8;
            const int bb = row >> 11;
            const int ss = row & 2047;
            const float pos = (float)positions[ss];
#pragma unroll
            for (int ni = 0; ni < 4; ni++) {
                const int col = tileN0 + wn + ni * 8 + 2 * tg;   // d<32 slot
                float o0[2], o1[2];
#pragma unroll
                for (int j = 0; j < 2; j++) {
                    const int d = (col & 63) + j;                 // < 32
                    float sn, cs;
                    rope_sincos(pos, d, sn, cs);
                    const float x0 = acc[mi][ni][rh * 2 + j];
                    const float x1 = acc[mi][ni + 4][rh * 2 + j];
                    o0[j] = (x0 * cs - x1 * sn) * scale;
                    o1[j] = (x1 * cs + x0 * sn) * scale;
                }
                uint32_t h0, l0, h1, l1;
                split2(o0[0], o0[1], h0, l0);
                split2(o1[0], o1[1], h1, l1);
                const int hh = isQ ? (col >> 6) : ((col - NH_ * D_) >> 6);
                const int nheads = isQ ? NH_ : NKV_;
                const size_t base = (((size_t)(bb * nheads + hh)) * S_ + ss) * D_
                                  + (col & 63);
                *reinterpret_cast<uint32_t*>(phi + base)      = h0;
                *reinterpret_cast<uint32_t*>(plo + base)      = l0;
                *reinterpret_cast<uint32_t*>(phi + base + 32) = h1;
                *reinterpret_cast<uint32_t*>(plo + base + 32) = l1;
            }
        }
    }
}

// ---------------------------------------------------------------------------
// bf16x3 causal flash attention. 64 q-rows, 128 thr, 2 CTAs/SM.
// Q fragments hoisted to registers (loaded once from global); P register-
// resident (R12). smem = KV double-buffer only (8 tiles, 72 KB).
// Tiles: Kh/Kl = 0+2st,1+2st ; Vh/Vl = 4+2st,5+2st.
// ---------------------------------------------------------------------------
#define AW 36
#define AT_W (64 * AW)
#define ATTN_SMEM (8 * AT_W * 4)     // 73728 B

__global__ __launch_bounds__(128, 2)
void attn_kernel(float* /*unused*/) {
    extern __shared__ uint32_t sw[];
    const uint32_t sbase = smem_u32(sw);

    const int qtile = gridDim.x - 1 - blockIdx.x;
    const int h = blockIdx.y;
    const int b = blockIdx.z;
    const int kvh = h / GQA_;
    const int q0 = qtile * 64;

    const bf16* qh_g = g_q_hi + (((size_t)(b * NH_ + h)) * S_ + q0) * D_;
    const bf16* ql_g = g_q_lo + (((size_t)(b * NH_ + h)) * S_ + q0) * D_;
    const bf16* kh_g = g_k_hi + ((size_t)(b * NKV_ + kvh)) * S_ * D_;
    const bf16* kl_g = g_k_lo + ((size_t)(b * NKV_ + kvh)) * S_ * D_;
    const bf16* vh_g = g_vt_hi + ((size_t)(b * NKV_ + kvh)) * D_ * S_;
    const bf16* vl_g = g_vt_lo + ((size_t)(b * NKV_ + kvh)) * D_ * S_;

    const int tid  = threadIdx.x;
    const int wid  = tid >> 5;
    const int lane = tid & 31;
    const int g  = lane >> 2;
    const int tg = lane & 3;
    const int wm = wid * 16;

    const uint32_t bk_off = (uint32_t)(((((lane >> 4) << 3) + (lane & 7)) * AW
                                        + ((lane >> 3) & 1) * 4) * 4);

#define ATTN_LOAD_KV(st, kt)                                                    \
    {                                                                            \
        _Pragma("unroll")                                                        \
        for (int j = 0; j < 16; j++) {                                           \
            int idx = tid + j * 128;                                              \
            int arr = j >> 2;                                                     \
            int r = (idx >> 3) & 63, c = idx & 7;                                 \
            int tile = (arr < 2 ? 0 : 4) + 2 * (st) + (arr & 1);                  \
            const bf16* src;                                                      \
            size_t goff;                                                          \
            if (arr == 0)      { src = kh_g; goff = (size_t)((kt) * 64 + r) * D_ + c * 8; } \
            else if (arr == 1) { src = kl_g; goff = (size_t)((kt) * 64 + r) * D_ + c * 8; } \
            else if (arr == 2) { src = vh_g; goff = (size_t)r * S_ + (kt) * 64 + c * 8; }   \
            else               { src = vl_g; goff = (size_t)r * S_ + (kt) * 64 + c * 8; }   \
            cp_async16_sa(sbase + (tile * AT_W + r * AW + c * 4) * 4, src + goff); \
        }                                                                         \
        cp_commit();                                                              \
    }

    ATTN_LOAD_KV(0, 0);

    // Hoisted Q fragments (loop-invariant), loaded directly from global.
    // Mapping matches ldmatrix x4: [0]=(g,2tg) [1]=(g+8,2tg) [2]=(g,2tg+8) [3]=(g+8,2tg+8)
    uint32_t qh[4][4], ql[4][4];
#pragma unroll
    for (int ch = 0; ch < 4; ch++) {
        const size_t e = (size_t)(wm + g) * D_ + ch * 16 + 2 * tg;
        qh[ch][0] = *reinterpret_cast<const uint32_t*>(qh_g + e);
        qh[ch][1] = *reinterpret_cast<const uint32_t*>(qh_g + e + 8 * D_);
        qh[ch][2] = *reinterpret_cast<const uint32_t*>(qh_g + e + 8);
        qh[ch][3] = *reinterpret_cast<const uint32_t*>(qh_g + e + 8 * D_ + 8);
        ql[ch][0] = *reinterpret_cast<const uint32_t*>(ql_g + e);
        ql[ch][1] = *reinterpret_cast<const uint32_t*>(ql_g + e + 8 * D_);
        ql[ch][2] = *reinterpret_cast<const uint32_t*>(ql_g + e + 8);
        ql[ch][3] = *reinterpret_cast<const uint32_t*>(ql_g + e + 8 * D_ + 8);
    }

    float oacc[8][4];
    float m0 = -1e30f, m1 = -1e30f, l0 = 0.f, l1 = 0.f;
#pragma unroll
    for (int ni = 0; ni < 8; ni++)
#pragma unroll
        for (int r = 0; r < 4; r++) oacc[ni][r] = 0.f;

    const int gq0 = q0 + wm + g;
    const int gq1 = gq0 + 8;

    for (int kt = 0; kt <= qtile; kt++) {
        const int cur = kt & 1;
        asm volatile("cp.async.wait_group 0;\n" ::: "memory");
        __syncthreads();
        if (kt + 1 <= qtile) ATTN_LOAD_KV(cur ^ 1, kt + 1);

        const uint32_t Kh_b = sbase + (0 + 2 * cur) * AT_W * 4;
        const uint32_t Kl_b = sbase + (1 + 2 * cur) * AT_W * 4;
        const uint32_t Vh_b = sbase + (4 + 2 * cur) * AT_W * 4;
        const uint32_t Vl_b = sbase + (5 + 2 * cur) * AT_W * 4;

        // ---- S = Q @ K^T ----
        float sacc[8][4];
#pragma unroll
        for (int ni = 0; ni < 8; ni++)
#pragma unroll
            for (int r = 0; r < 4; r++) sacc[ni][r] = 0.f;

#pragma unroll
        for (int ch = 0; ch < 4; ch++) {
            const uint32_t kb = (uint32_t)(ch * 8 * 4);
#pragma unroll
            for (int p = 0; p < 4; p++) {
                uint32_t kh4[4], kl4[4];
                ldsm_x4(Kh_b + bk_off + (uint32_t)(p * 16 * AW * 4) + kb, kh4);
                ldsm_x4(Kl_b + bk_off + (uint32_t)(p * 16 * AW * 4) + kb, kl4);
#pragma unroll
                for (int s = 0; s < 2; s++) {
                    const int ni = 2 * p + s;
                    mma_bf16(sacc[ni], qh[ch], kh4[2 * s], kh4[2 * s + 1]);
                    mma_bf16(sacc[ni], ql[ch], kh4[2 * s], kh4[2 * s + 1]);
                    mma_bf16(sacc[ni], qh[ch], kl4[2 * s], kl4[2 * s + 1]);
                }
            }
        }

        // ---- causal mask ----
        if (kt == qtile) {
#pragma unroll
            for (int ni = 0; ni < 8; ni++) {
                const int col = kt * 64 + ni * 8 + 2 * tg;
                if (col     > gq0) sacc[ni][0] = -1e30f;
                if (col + 1 > gq0) sacc[ni][1] = -1e30f;
                if (col     > gq1) sacc[ni][2] = -1e30f;
                if (col + 1 > gq1) sacc[ni][3] = -1e30f;
            }
        }

        // ---- online softmax ----
        float mx0 = -1e30f, mx1 = -1e30f;
#pragma unroll
        for (int ni = 0; ni < 8; ni++) {
            mx0 = fmaxf(mx0, fmaxf(sacc[ni][0], sacc[ni][1]));
            mx1 = fmaxf(mx1, fmaxf(sacc[ni][2], sacc[ni][3]));
        }
        mx0 = fmaxf(mx0, __shfl_xor_sync(0xffffffffu, mx0, 1));
        mx0 = fmaxf(mx0, __shfl_xor_sync(0xffffffffu, mx0, 2));
        mx1 = fmaxf(mx1, __shfl_xor_sync(0xffffffffu, mx1, 1));
        mx1 = fmaxf(mx1, __shfl_xor_sync(0xffffffffu, mx1, 2));

        const float mn0 = fmaxf(m0, mx0);
        const float mn1 = fmaxf(m1, mx1);
        const float corr0 = __expf(m0 - mn0);
        const float corr1 = __expf(m1 - mn1);
        float rs0 = 0.f, rs1 = 0.f;
#pragma unroll
        for (int ni = 0; ni < 8; ni++) {
            float p0 = __expf(sacc[ni][0] - mn0);
            float p1 = __expf(sacc[ni][1] - mn0);
            float p2 = __expf(sacc[ni][2] - mn1);
            float p3 = __expf(sacc[ni][3] - mn1);
            sacc[ni][0] = p0; sacc[ni][1] = p1;
            sacc[ni][2] = p2; sacc[ni][3] = p3;
            rs0 += p0 + p1;
            rs1 += p2 + p3;
        }
        rs0 += __shfl_xor_sync(0xffffffffu, rs0, 1);
        rs0 += __shfl_xor_sync(0xffffffffu, rs0, 2);
        rs1 += __shfl_xor_sync(0xffffffffu, rs1, 1);
        rs1 += __shfl_xor_sync(0xffffffffu, rs1, 2);
        l0 = l0 * corr0 + rs0;
        l1 = l1 * corr1 + rs1;
        m0 = mn0;
        m1 = mn1;
#pragma unroll
        for (int ni = 0; ni < 8; ni++) {
            oacc[ni][0] *= corr0;
            oacc[ni][1] *= corr0;
            oacc[ni][2] *= corr1;
            oacc[ni][3] *= corr1;
        }

        // ---- O += P @ V (P from registers) ----
#pragma unroll
        for (int ch = 0; ch < 4; ch++) {
            const uint32_t kb = (uint32_t)(ch * 8 * 4);
            uint32_t ph[4], pl[4];
            split2(sacc[2 * ch][0],     sacc[2 * ch][1],     ph[0], pl[0]);
            split2(sacc[2 * ch][2],     sacc[2 * ch][3],     ph[1], pl[1]);
            split2(sacc[2 * ch + 1][0], sacc[2 * ch + 1][1], ph[2], pl[2]);
            split2(sacc[2 * ch + 1][2], sacc[2 * ch + 1][3], ph[3], pl[3]);
#pragma unroll
            for (int p = 0; p < 4; p++) {
                uint32_t vh4[4], vl4[4];
                ldsm_x4(Vh_b + bk_off + (uint32_t)(p * 16 * AW * 4) + kb, vh4);
                ldsm_x4(Vl_b + bk_off + (uint32_t)(p * 16 * AW * 4) + kb, vl4);
#pragma unroll
                for (int s = 0; s < 2; s++) {
                    const int ni = 2 * p + s;
                    mma_bf16(oacc[ni], ph, vh4[2 * s], vh4[2 * s + 1]);
                    mma_bf16(oacc[ni], pl, vh4[2 * s], vh4[2 * s + 1]);
                    mma_bf16(oacc[ni], ph, vl4[2 * s], vl4[2 * s + 1]);
                }
            }
        }
    }

    const float il0 = 1.0f / l0;
    const float il1 = 1.0f / l1;
    uint32_t* ch_w = reinterpret_cast<uint32_t*>(g_ctx_hi);
    uint32_t* cl_w = reinterpret_cast<uint32_t*>(g_ctx_lo);
    const size_t off0 = (((size_t)(b * S_ + gq0)) * (NH_ * D_) + h * D_) >> 1;
    const size_t off1 = (((size_t)(b * S_ + gq1)) * (NH_ * D_) + h * D_) >> 1;
#pragma unroll
    for (int ni = 0; ni < 8; ni++) {
        const int cw = ni * 4 + tg;
        uint32_t h0, L0, h1, L1;
        split2(oacc[ni][0] * il0, oacc[ni][1] * il0, h0, L0);
        split2(oacc[ni][2] * il1, oacc[ni][3] * il1, h1, L1);
        ch_w[off0 + cw] = h0;
        cl_w[off0 + cw] = L0;
        ch_w[off1 + cw] = h1;
        cl_w[off1 + cw] = L1;
    }
}

// ---------------------------------------------------------------------------
// Launch
// ---------------------------------------------------------------------------
extern "C" void kernel_launch(void* const* d_in, const int* in_sizes, int n_in,
                              void* d_out, int out_size) {
    const int*   positions = (const int*)d_in[0];
    const float* hidden    = (const float*)d_in[1];
    const float* Wqkv      = (const float*)d_in[2];
    const float* Wo        = (const float*)d_in[3];
    float* out = (float*)d_out;

    bf16 *hh, *hl, *wqh, *wql, *woh, *wol, *cth, *ctl;
    cudaGetSymbolAddress((void**)&hh,  g_hid_hi);
    cudaGetSymbolAddress((void**)&hl,  g_hid_lo);
    cudaGetSymbolAddress((void**)&wqh, g_wqkv_hi);
    cudaGetSymbolAddress((void**)&wql, g_wqkv_lo);
    cudaGetSymbolAddress((void**)&woh, g_wo_hi);
    cudaGetSymbolAddress((void**)&wol, g_wo_lo);
    cudaGetSymbolAddress((void**)&cth, g_ctx_hi);
    cudaGetSymbolAddress((void**)&ctl, g_ctx_lo);

    cudaFuncSetAttribute(gemm_bf16x3, cudaFuncAttributeMaxDynamicSharedMemorySize, GSMEM);
    cudaFuncSetAttribute(gemm_bf16x3, cudaFuncAttributePreferredSharedMemoryCarveout, 100);
    cudaFuncSetAttribute(gemm_qkv, cudaFuncAttributeMaxDynamicSharedMemorySize, GSMEM);
    cudaFuncSetAttribute(gemm_qkv, cudaFuncAttributePreferredSharedMemoryCarveout, 100);
    cudaFuncSetAttribute(attn_kernel, cudaFuncAttributeMaxDynamicSharedMemorySize, ATTN_SMEM);
    cudaFuncSetAttribute(attn_kernel, cudaFuncAttributePreferredSharedMemoryCarveout, 100);

    // 0. Fused pre-pass (split hidden + transpose both weights)
    prepass_kernel<<<NB_SPLIT + NB_WQ + NB_WO, 256>>>(hidden, Wqkv, Wo);

    // 1. QKV projection with fused RoPE epilogue
    gemm_qkv<<<dim3(QKVF / 128, (B_ * S_) / 128), 256, GSMEM>>>(
        hh, hl, wqh, wql, positions);

    // 2. V split-transpose
    vt_kernel<<<dim3(S_ / 32, NKV_, B_), 256>>>();

    // 3. Causal GQA flash attention
    attn_kernel<<<dim3(S_ / 64, NH_, B_), 128, ATTN_SMEM>>>(nullptr);

    // 4. Output projection
    gemm_bf16x3<<<dim3(H_ / 128, (B_ * S_) / 128), 256, GSMEM>>>(
        cth, ctl, woh, wol, out, B_ * S_, H_, NH_ * D_);
}

// round 14
// speedup vs baseline: 1.0931x; 1.0029x over previous
#include <cuda_runtime.h>
#include <cuda_bf16.h>
#include <math.h>
#include <stdint.h>

#define B_   2
#define S_   2048
#define H_   2048
#define NH_  32
#define NKV_ 8
#define D_   64
#define QKVF ((NH_ + 2 * NKV_) * D_)   // 3072
#define GQA_ (NH_ / NKV_)              // 4

typedef __nv_bfloat16 bf16;

// ---------------------------------------------------------------------------
// Device scratch
// ---------------------------------------------------------------------------
__device__ bf16 g_hid_hi[(size_t)B_ * S_ * H_];
__device__ bf16 g_hid_lo[(size_t)B_ * S_ * H_];
__device__ bf16 g_wqkv_hi[(size_t)QKVF * H_];       // transposed [N][K]
__device__ bf16 g_wqkv_lo[(size_t)QKVF * H_];
__device__ bf16 g_wo_hi[(size_t)H_ * H_];           // transposed [N][K]
__device__ bf16 g_wo_lo[(size_t)H_ * H_];
__device__ bf16 g_q_hi[(size_t)B_ * NH_ * S_ * D_];
__device__ bf16 g_q_lo[(size_t)B_ * NH_ * S_ * D_];
__device__ bf16 g_k_hi[(size_t)B_ * NKV_ * S_ * D_];
__device__ bf16 g_k_lo[(size_t)B_ * NKV_ * S_ * D_];
__device__ bf16 g_vt_hi[(size_t)B_ * NKV_ * D_ * S_];
__device__ bf16 g_vt_lo[(size_t)B_ * NKV_ * D_ * S_];
__device__ bf16 g_ctx_hi[(size_t)B_ * S_ * NH_ * D_];
__device__ bf16 g_ctx_lo[(size_t)B_ * S_ * NH_ * D_];

// ---------------------------------------------------------------------------
// Helpers
// ---------------------------------------------------------------------------
__device__ __forceinline__ uint32_t smem_u32(const void* p) {
    return (uint32_t)__cvta_generic_to_shared(p);
}
__device__ __forceinline__ void cp_async16_sa(uint32_t sa, const void* g) {
    asm volatile("cp.async.cg.shared.global [%0], [%1], 16;\n" :: "r"(sa), "l"(g));
}
__device__ __forceinline__ void cp_commit() {
    asm volatile("cp.async.commit_group;\n");
}
__device__ __forceinline__ uint32_t pack2(float x, float y) {
    uint32_t r;
    asm("cvt.rn.bf16x2.f32 %0, %1, %2;" : "=r"(r) : "f"(y), "f"(x));
    return r;
}
__device__ __forceinline__ void split2(float x, float y, uint32_t& hi, uint32_t& lo) {
    hi = pack2(x, y);
    float hx = __uint_as_float(hi << 16);
    float hy = __uint_as_float(hi & 0xFFFF0000u);
    lo = pack2(x - hx, y - hy);
}
__device__ __forceinline__ void mma_bf16(float* c, const uint32_t* a,
                                         uint32_t b0, uint32_t b1) {
    asm volatile(
        "mma.sync.aligned.m16n8k16.row.col.f32.bf16.bf16.f32 "
        "{%0,%1,%2,%3},{%4,%5,%6,%7},{%8,%9},{%0,%1,%2,%3};"
        : "+f"(c[0]), "+f"(c[1]), "+f"(c[2]), "+f"(c[3])
        : "r"(a[0]), "r"(a[1]), "r"(a[2]), "r"(a[3]), "r"(b0), "r"(b1));
}
__device__ __forceinline__ void ldsm_x4(uint32_t addr, uint32_t* r) {
    asm volatile("ldmatrix.sync.aligned.m8n8.x4.shared.b16 {%0,%1,%2,%3}, [%4];"
                 : "=r"(r[0]), "=r"(r[1]), "=r"(r[2]), "=r"(r[3]) : "r"(addr));
}
__device__ __forceinline__ void rope_sincos(float pos, int d, float& sn, float& cs) {
    const float inv = powf(10000.0f, -(float)(2 * d) / (float)D_);
    const float freq = pos * inv;
    const double dr = (double)freq;
    const double kq = floor(dr * 0.15915494309189534 + 0.5);
    const float  rr = (float)(dr - kq * 6.283185307179586477);
    sincosf(rr, &sn, &cs);
}

// ---------------------------------------------------------------------------
// Fused pre-pass (unchanged)
// ---------------------------------------------------------------------------
#define NB_SPLIT 8192
#define NB_WQ    6144
#define NB_WO    4096

__global__ void prepass_kernel(const float* __restrict__ hidden,
                               const float* __restrict__ Wqkv,
                               const float* __restrict__ Wo) {
    __shared__ float t[32][33];
    const int bid = blockIdx.x;
    const int tid = threadIdx.x;

    if (bid < NB_SPLIT) {
        int i = bid * 256 + tid;
        float4 v = reinterpret_cast<const float4*>(hidden)[i];
        uint32_t h0, l0, h1, l1;
        split2(v.x, v.y, h0, l0);
        split2(v.z, v.w, h1, l1);
        reinterpret_cast<uint2*>(g_hid_hi)[i] = make_uint2(h0, h1);
        reinterpret_cast<uint2*>(g_hid_lo)[i] = make_uint2(l0, l1);
        return;
    }

    const float* src;
    bf16 *dhi, *dlo;
    int N, bx, by;
    if (bid < NB_SPLIT + NB_WQ) {
        int b2 = bid - NB_SPLIT;
        bx = b2 % (QKVF / 32); by = b2 / (QKVF / 32);
        src = Wqkv; dhi = g_wqkv_hi; dlo = g_wqkv_lo; N = QKVF;
    } else {
        int b2 = bid - NB_SPLIT - NB_WQ;
        bx = b2 % (H_ / 32); by = b2 / (H_ / 32);
        src = Wo; dhi = g_wo_hi; dlo = g_wo_lo; N = H_;
    }
    const int K = H_;
    const int n0 = bx * 32, k0 = by * 32;
    const int tx = tid & 31, ty = tid >> 5;
#pragma unroll
    for (int r = 0; r < 4; r++)
        t[ty + 8 * r][tx] = src[(size_t)(k0 + ty + 8 * r) * N + n0 + tx];
    __syncthreads();
#pragma unroll
    for (int r = 0; r < 4; r++) {
        float x = t[tx][ty + 8 * r];
        bf16 h = __float2bfloat16(x);
        size_t off = (size_t)(n0 + ty + 8 * r) * K + k0 + tx;
        dhi[off] = h;
        dlo[off] = __float2bfloat16(x - __bfloat162float(h));
    }
}

// ---------------------------------------------------------------------------
// Shared GEMM mainloop pieces (128x128x32, 256 thr, 2-stage, ldmatrix)
// ---------------------------------------------------------------------------
#define PW 20
#define TILE_W (128 * PW)
#define GSMEM (2 * 4 * TILE_W * 4)   // 81920 B

#define GEMM_LOAD(st, k0)                                                     \
    {                                                                          \
        uint32_t s0 = sbase + (st) * (4 * TILE_W) * 4;                         \
        _Pragma("unroll")                                                      \
        for (int j = 0; j < 8; j++) {                                          \
            int idx = tid + j * 256;                                           \
            int arr = j >> 1;                                                  \
            int r = (idx >> 2) & 127, c = idx & 3;                             \
            cp_async16_sa(s0 + (arr * TILE_W + r * PW + c * 4) * 4,            \
                          gptr[arr] + (size_t)r * K + (k0) + c * 8);           \
        }                                                                      \
        cp_commit();                                                           \
    }

#define GEMM_MAINLOOP(K)                                                       \
    const int NIT = (K) / 32;                                                  \
    GEMM_LOAD(0, 0);                                                           \
    for (int it = 0; it < NIT; ++it) {                                         \
        const int st = it & 1;                                                 \
        asm volatile("cp.async.wait_group 0;\n" ::: "memory");                 \
        __syncthreads();                                                       \
        if (it + 1 < NIT) GEMM_LOAD(st ^ 1, (it + 1) * 32);                    \
        const uint32_t sA_h = sbase + (st * 4 * TILE_W) * 4;                   \
        const uint32_t sA_l = sA_h + TILE_W * 4;                               \
        const uint32_t sB_h = sA_h + 2 * TILE_W * 4;                           \
        const uint32_t sB_l = sA_h + 3 * TILE_W * 4;                           \
        _Pragma("unroll")                                                      \
        for (int ch = 0; ch < 2; ch++) {                                       \
            const uint32_t kb = (uint32_t)(ch * 8 * 4);                        \
            uint32_t ah[2][4], al[2][4];                                       \
            _Pragma("unroll")                                                  \
            for (int mi = 0; mi < 2; mi++) {                                   \
                ldsm_x4(sA_h + a_off + (uint32_t)(mi * 16 * PW * 4) + kb, ah[mi]); \
                ldsm_x4(sA_l + a_off + (uint32_t)(mi * 16 * PW * 4) + kb, al[mi]); \
            }                                                                  \
            _Pragma("unroll")                                                  \
            for (int p = 0; p < 4; p++) {                                      \
                uint32_t bh[4], bl[4];                                         \
                ldsm_x4(sB_h + b_off + (uint32_t)(p * 16 * PW * 4) + kb, bh);  \
                ldsm_x4(sB_l + b_off + (uint32_t)(p * 16 * PW * 4) + kb, bl);  \
                _Pragma("unroll")                                              \
                for (int s = 0; s < 2; s++) {                                  \
                    const int ni = 2 * p + s;                                  \
                    _Pragma("unroll")                                          \
                    for (int mi = 0; mi < 2; mi++) {                           \
                        mma_bf16(acc[mi][ni], ah[mi], bh[2 * s], bh[2 * s + 1]); \
                        mma_bf16(acc[mi][ni], al[mi], bh[2 * s], bh[2 * s + 1]); \
                        mma_bf16(acc[mi][ni], ah[mi], bl[2 * s], bl[2 * s + 1]); \
                    }                                                          \
                }                                                              \
            }                                                                  \
        }                                                                      \
    }

#define GEMM_PROLOG(Ahi, Alo, Bhi, Blo, K)                                     \
    extern __shared__ uint32_t sw[];                                           \
    const uint32_t sbase = smem_u32(sw);                                       \
    const int tid  = threadIdx.x;                                              \
    const int wid  = tid >> 5;                                                 \
    const int lane = tid & 31;                                                 \
    const int g  = lane >> 2;                                                  \
    const int tg = lane & 3;                                                   \
    const int wm = (wid & 3) * 32;                                             \
    const int wn = (wid >> 2) * 64;                                            \
    const bf16* gptr[4] = {                                                    \
        (Ahi) + (size_t)blockIdx.y * 128 * (K),                                \
        (Alo) + (size_t)blockIdx.y * 128 * (K),                                \
        (Bhi) + (size_t)blockIdx.x * 128 * (K),                                \
        (Blo) + (size_t)blockIdx.x * 128 * (K)                                 \
    };                                                                         \
    const uint32_t a_off = (uint32_t)(((wm + (lane & 15)) * PW + (lane >> 4) * 4) * 4); \
    const uint32_t b_off = (uint32_t)(((wn + ((lane >> 4) << 3) + (lane & 7)) * PW      \
                                       + ((lane >> 3) & 1) * 4) * 4);          \
    float acc[2][8][4];                                                        \
    _Pragma("unroll")                                                          \
    for (int mi = 0; mi < 2; mi++)                                             \
        _Pragma("unroll")                                                      \
        for (int ni = 0; ni < 8; ni++)                                         \
            _Pragma("unroll")                                                  \
            for (int r = 0; r < 4; r++) acc[mi][ni][r] = 0.f;

// ---------------------------------------------------------------------------
// Generic GEMM (used for Wo projection): C = A @ Bt^T, fp32 out
// ---------------------------------------------------------------------------
__global__ __launch_bounds__(256, 2)
void gemm_bf16x3(const bf16* __restrict__ Ahi, const bf16* __restrict__ Alo,
                 const bf16* __restrict__ Bhi, const bf16* __restrict__ Blo,
                 float* __restrict__ C, int M, int N, int K) {
    GEMM_PROLOG(Ahi, Alo, Bhi, Blo, K)
    GEMM_MAINLOOP(K)
#pragma unroll
    for (int mi = 0; mi < 2; mi++) {
        const int row = blockIdx.y * 128 + wm + mi * 16 + g;
#pragma unroll
        for (int ni = 0; ni < 8; ni++) {
            const int col = blockIdx.x * 128 + wn + ni * 8 + 2 * tg;
            *reinterpret_cast<float2*>(C + (size_t)row * N + col) =
                make_float2(acc[mi][ni][0], acc[mi][ni][1]);
            *reinterpret_cast<float2*>(C + (size_t)(row + 8) * N + col) =
                make_float2(acc[mi][ni][2], acc[mi][ni][3]);
        }
    }
}

// ---------------------------------------------------------------------------
// QKV GEMM with fused RoPE epilogue + fused V split-transpose.
// Q cols [0,2048): rope, scale 1/8, split -> g_q.
// K cols [2048,2560): rope, split -> g_k.
// V cols [2560,3072): split + transpose -> g_vt[b][kh][d][s] directly.
// ---------------------------------------------------------------------------
__global__ __launch_bounds__(256, 2)
void gemm_qkv(const bf16* __restrict__ Ahi, const bf16* __restrict__ Alo,
              const bf16* __restrict__ Bhi, const bf16* __restrict__ Blo,
              const int* __restrict__ positions) {
    const int K = H_;
    GEMM_PROLOG(Ahi, Alo, Bhi, Blo, K)
    GEMM_MAINLOOP(K)

    const int tileN0 = blockIdx.x * 128;
    if (tileN0 >= (NH_ + NKV_) * D_) {
        // V tile: split + transpose directly into g_vt (same cvt order as old vt_kernel)
        const int colBase = tileN0 - (NH_ + NKV_) * D_;   // 0..384
#pragma unroll
        for (int mi = 0; mi < 2; mi++) {
#pragma unroll
            for (int rh = 0; rh < 2; rh++) {
                const int row = blockIdx.y * 128 + wm + mi * 16 + g + rh * 8;
                const int bb = row >> 11;
                const int ss = row & 2047;
#pragma unroll
                for (int ni = 0; ni < 8; ni++) {
                    const int col = colBase + wn + ni * 8 + 2 * tg;   // 0..511
                    const int kh = col >> 6;
                    const int d  = col & 63;
                    const size_t dbase = ((size_t)(bb * NKV_ + kh)) * D_ * S_;
#pragma unroll
                    for (int j = 0; j < 2; j++) {
                        const float x = acc[mi][ni][rh * 2 + j];
                        bf16 hv = __float2bfloat16(x);
                        g_vt_hi[dbase + (size_t)(d + j) * S_ + ss] = hv;
                        g_vt_lo[dbase + (size_t)(d + j) * S_ + ss] =
                            __float2bfloat16(x - __bfloat162float(hv));
                    }
                }
            }
        }
        return;
    }

    const bool isQ = tileN0 < NH_ * D_;
    const float scale = isQ ? 0.125f : 1.0f;
    bf16* phi = isQ ? g_q_hi : g_k_hi;
    bf16* plo = isQ ? g_q_lo : g_k_lo;

#pragma unroll
    for (int mi = 0; mi < 2; mi++) {
#pragma unroll
        for (int rh = 0; rh < 2; rh++) {
            const int row = blockIdx.y * 128 + wm + mi * 16 + g + rh * 8;
            const int bb = row >> 11;
            const int ss = row & 2047;
            const float pos = (float)positions[ss];
#pragma unroll
            for (int ni = 0; ni < 4; ni++) {
                const int col = tileN0 + wn + ni * 8 + 2 * tg;   // d<32 slot
                float o0[2], o1[2];
#pragma unroll
                for (int j = 0; j < 2; j++) {
                    const int d = (col & 63) + j;
                    float sn, cs;
                    rope_sincos(pos, d, sn, cs);
                    const float x0 = acc[mi][ni][rh * 2 + j];
                    const float x1 = acc[mi][ni + 4][rh * 2 + j];
                    o0[j] = (x0 * cs - x1 * sn) * scale;
                    o1[j] = (x1 * cs + x0 * sn) * scale;
                }
                uint32_t h0, l0, h1, l1;
                split2(o0[0], o0[1], h0, l0);
                split2(o1[0], o1[1], h1, l1);
                const int hh = isQ ? (col >> 6) : ((col - NH_ * D_) >> 6);
                const int nheads = isQ ? NH_ : NKV_;
                const size_t base = (((size_t)(bb * nheads + hh)) * S_ + ss) * D_
                                  + (col & 63);
                *reinterpret_cast<uint32_t*>(phi + base)      = h0;
                *reinterpret_cast<uint32_t*>(plo + base)      = l0;
                *reinterpret_cast<uint32_t*>(phi + base + 32) = h1;
                *reinterpret_cast<uint32_t*>(plo + base + 32) = l1;
            }
        }
    }
}

// ---------------------------------------------------------------------------
// bf16x3 causal flash attention. 64 q-rows, 128 thr, now 3 CTAs/SM target
// (smem 72KB, regs capped via launch bounds). Q and P register-resident.
// ---------------------------------------------------------------------------
#define AW 36
#define AT_W (64 * AW)
#define ATTN_SMEM (8 * AT_W * 4)     // 73728 B

__global__ __launch_bounds__(128, 3)
void attn_kernel(float* /*unused*/) {
    extern __shared__ uint32_t sw[];
    const uint32_t sbase = smem_u32(sw);

    const int qtile = gridDim.x - 1 - blockIdx.x;
    const int h = blockIdx.y;
    const int b = blockIdx.z;
    const int kvh = h / GQA_;
    const int q0 = qtile * 64;

    const bf16* qh_g = g_q_hi + (((size_t)(b * NH_ + h)) * S_ + q0) * D_;
    const bf16* ql_g = g_q_lo + (((size_t)(b * NH_ + h)) * S_ + q0) * D_;
    const bf16* kh_g = g_k_hi + ((size_t)(b * NKV_ + kvh)) * S_ * D_;
    const bf16* kl_g = g_k_lo + ((size_t)(b * NKV_ + kvh)) * S_ * D_;
    const bf16* vh_g = g_vt_hi + ((size_t)(b * NKV_ + kvh)) * D_ * S_;
    const bf16* vl_g = g_vt_lo + ((size_t)(b * NKV_ + kvh)) * D_ * S_;

    const int tid  = threadIdx.x;
    const int wid  = tid >> 5;
    const int lane = tid & 31;
    const int g  = lane >> 2;
    const int tg = lane & 3;
    const int wm = wid * 16;

    const uint32_t bk_off = (uint32_t)(((((lane >> 4) << 3) + (lane & 7)) * AW
                                        + ((lane >> 3) & 1) * 4) * 4);

#define ATTN_LOAD_KV(st, kt)                                                    \
    {                                                                            \
        _Pragma("unroll")                                                        \
        for (int j = 0; j < 16; j++) {                                           \
            int idx = tid + j * 128;                                              \
            int arr = j >> 2;                                                     \
            int r = (idx >> 3) & 63, c = idx & 7;                                 \
            int tile = (arr < 2 ? 0 : 4) + 2 * (st) + (arr & 1);                  \
            const bf16* src;                                                      \
            size_t goff;                                                          \
            if (arr == 0)      { src = kh_g; goff = (size_t)((kt) * 64 + r) * D_ + c * 8; } \
            else if (arr == 1) { src = kl_g; goff = (size_t)((kt) * 64 + r) * D_ + c * 8; } \
            else if (arr == 2) { src = vh_g; goff = (size_t)r * S_ + (kt) * 64 + c * 8; }   \
            else               { src = vl_g; goff = (size_t)r * S_ + (kt) * 64 + c * 8; }   \
            cp_async16_sa(sbase + (tile * AT_W + r * AW + c * 4) * 4, src + goff); \
        }                                                                         \
        cp_commit();                                                              \
    }

    ATTN_LOAD_KV(0, 0);

    // Hoisted Q fragments (loop-invariant), loaded once from global.
    uint32_t qh[4][4], ql[4][4];
#pragma unroll
    for (int ch = 0; ch < 4; ch++) {
        const size_t e = (size_t)(wm + g) * D_ + ch * 16 + 2 * tg;
        qh[ch][0] = *reinterpret_cast<const uint32_t*>(qh_g + e);
        qh[ch][1] = *reinterpret_cast<const uint32_t*>(qh_g + e + 8 * D_);
        qh[ch][2] = *reinterpret_cast<const uint32_t*>(qh_g + e + 8);
        qh[ch][3] = *reinterpret_cast<const uint32_t*>(qh_g + e + 8 * D_ + 8);
        ql[ch][0] = *reinterpret_cast<const uint32_t*>(ql_g + e);
        ql[ch][1] = *reinterpret_cast<const uint32_t*>(ql_g + e + 8 * D_);
        ql[ch][2] = *reinterpret_cast<const uint32_t*>(ql_g + e + 8);
        ql[ch][3] = *reinterpret_cast<const uint32_t*>(ql_g + e + 8 * D_ + 8);
    }

    float oacc[8][4];
    float m0 = -1e30f, m1 = -1e30f, l0 = 0.f, l1 = 0.f;
#pragma unroll
    for (int ni = 0; ni < 8; ni++)
#pragma unroll
        for (int r = 0; r < 4; r++) oacc[ni][r] = 0.f;

    const int gq0 = q0 + wm + g;
    const int gq1 = gq0 + 8;

    for (int kt = 0; kt <= qtile; kt++) {
        const int cur = kt & 1;
        asm volatile("cp.async.wait_group 0;\n" ::: "memory");
        __syncthreads();
        if (kt + 1 <= qtile) ATTN_LOAD_KV(cur ^ 1, kt + 1);

        const uint32_t Kh_b = sbase + (0 + 2 * cur) * AT_W * 4;
        const uint32_t Kl_b = sbase + (1 + 2 * cur) * AT_W * 4;
        const uint32_t Vh_b = sbase + (4 + 2 * cur) * AT_W * 4;
        const uint32_t Vl_b = sbase + (5 + 2 * cur) * AT_W * 4;

        // ---- S = Q @ K^T ----
        float sacc[8][4];
#pragma unroll
        for (int ni = 0; ni < 8; ni++)
#pragma unroll
            for (int r = 0; r < 4; r++) sacc[ni][r] = 0.f;

#pragma unroll
        for (int ch = 0; ch < 4; ch++) {
            const uint32_t kb = (uint32_t)(ch * 8 * 4);
#pragma unroll
            for (int p = 0; p < 4; p++) {
                uint32_t kh4[4], kl4[4];
                ldsm_x4(Kh_b + bk_off + (uint32_t)(p * 16 * AW * 4) + kb, kh4);
                ldsm_x4(Kl_b + bk_off + (uint32_t)(p * 16 * AW * 4) + kb, kl4);
#pragma unroll
                for (int s = 0; s < 2; s++) {
                    const int ni = 2 * p + s;
                    mma_bf16(sacc[ni], qh[ch], kh4[2 * s], kh4[2 * s + 1]);
                    mma_bf16(sacc[ni], ql[ch], kh4[2 * s], kh4[2 * s + 1]);
                    mma_bf16(sacc[ni], qh[ch], kl4[2 * s], kl4[2 * s + 1]);
                }
            }
        }

        // ---- causal mask ----
        if (kt == qtile) {
#pragma unroll
            for (int ni = 0; ni < 8; ni++) {
                const int col = kt * 64 + ni * 8 + 2 * tg;
                if (col     > gq0) sacc[ni][0] = -1e30f;
                if (col + 1 > gq0) sacc[ni][1] = -1e30f;
                if (col     > gq1) sacc[ni][2] = -1e30f;
                if (col + 1 > gq1) sacc[ni][3] = -1e30f;
            }
        }

        // ---- online softmax ----
        float mx0 = -1e30f, mx1 = -1e30f;
#pragma unroll
        for (int ni = 0; ni < 8; ni++) {
            mx0 = fmaxf(mx0, fmaxf(sacc[ni][0], sacc[ni][1]));
            mx1 = fmaxf(mx1, fmaxf(sacc[ni][2], sacc[ni][3]));
        }
        mx0 = fmaxf(mx0, __shfl_xor_sync(0xffffffffu, mx0, 1));
        mx0 = fmaxf(mx0, __shfl_xor_sync(0xffffffffu, mx0, 2));
        mx1 = fmaxf(mx1, __shfl_xor_sync(0xffffffffu, mx1, 1));
        mx1 = fmaxf(mx1, __shfl_xor_sync(0xffffffffu, mx1, 2));

        const float mn0 = fmaxf(m0, mx0);
        const float mn1 = fmaxf(m1, mx1);
        const float corr0 = __expf(m0 - mn0);
        const float corr1 = __expf(m1 - mn1);
        float rs0 = 0.f, rs1 = 0.f;
#pragma unroll
        for (int ni = 0; ni < 8; ni++) {
            float p0 = __expf(sacc[ni][0] - mn0);
            float p1 = __expf(sacc[ni][1] - mn0);
            float p2 = __expf(sacc[ni][2] - mn1);
            float p3 = __expf(sacc[ni][3] - mn1);
            sacc[ni][0] = p0; sacc[ni][1] = p1;
            sacc[ni][2] = p2; sacc[ni][3] = p3;
            rs0 += p0 + p1;
            rs1 += p2 + p3;
        }
        rs0 += __shfl_xor_sync(0xffffffffu, rs0, 1);
        rs0 += __shfl_xor_sync(0xffffffffu, rs0, 2);
        rs1 += __shfl_xor_sync(0xffffffffu, rs1, 1);
        rs1 += __shfl_xor_sync(0xffffffffu, rs1, 2);
        l0 = l0 * corr0 + rs0;
        l1 = l1 * corr1 + rs1;
        m0 = mn0;
        m1 = mn1;
#pragma unroll
        for (int ni = 0; ni < 8; ni++) {
            oacc[ni][0] *= corr0;
            oacc[ni][1] *= corr0;
            oacc[ni][2] *= corr1;
            oacc[ni][3] *= corr1;
        }

        // ---- O += P @ V (P from registers) ----
#pragma unroll
        for (int ch = 0; ch < 4; ch++) {
            const uint32_t kb = (uint32_t)(ch * 8 * 4);
            uint32_t ph[4], pl[4];
            split2(sacc[2 * ch][0],     sacc[2 * ch][1],     ph[0], pl[0]);
            split2(sacc[2 * ch][2],     sacc[2 * ch][3],     ph[1], pl[1]);
            split2(sacc[2 * ch + 1][0], sacc[2 * ch + 1][1], ph[2], pl[2]);
            split2(sacc[2 * ch + 1][2], sacc[2 * ch + 1][3], ph[3], pl[3]);
#pragma unroll
            for (int p = 0; p < 4; p++) {
                uint32_t vh4[4], vl4[4];
                ldsm_x4(Vh_b + bk_off + (uint32_t)(p * 16 * AW * 4) + kb, vh4);
                ldsm_x4(Vl_b + bk_off + (uint32_t)(p * 16 * AW * 4) + kb, vl4);
#pragma unroll
                for (int s = 0; s < 2; s++) {
                    const int ni = 2 * p + s;
                    mma_bf16(oacc[ni], ph, vh4[2 * s], vh4[2 * s + 1]);
                    mma_bf16(oacc[ni], pl, vh4[2 * s], vh4[2 * s + 1]);
                    mma_bf16(oacc[ni], ph, vl4[2 * s], vl4[2 * s + 1]);
                }
            }
        }
    }

    const float il0 = 1.0f / l0;
    const float il1 = 1.0f / l1;
    uint32_t* ch_w = reinterpret_cast<uint32_t*>(g_ctx_hi);
    uint32_t* cl_w = reinterpret_cast<uint32_t*>(g_ctx_lo);
    const size_t off0 = (((size_t)(b * S_ + gq0)) * (NH_ * D_) + h * D_) >> 1;
    const size_t off1 = (((size_t)(b * S_ + gq1)) * (NH_ * D_) + h * D_) >> 1;
#pragma unroll
    for (int ni = 0; ni < 8; ni++) {
        const int cw = ni * 4 + tg;
        uint32_t h0, L0, h1, L1;
        split2(oacc[ni][0] * il0, oacc[ni][1] * il0, h0, L0);
        split2(oacc[ni][2] * il1, oacc[ni][3] * il1, h1, L1);
        ch_w[off0 + cw] = h0;
        cl_w[off0 + cw] = L0;
        ch_w[off1 + cw] = h1;
        cl_w[off1 + cw] = L1;
    }
}

// ---------------------------------------------------------------------------
// Launch
// ---------------------------------------------------------------------------
extern "C" void kernel_launch(void* const* d_in, const int* in_sizes, int n_in,
                              void* d_out, int out_size) {
    const int*   positions = (const int*)d_in[0];
    const float* hidden    = (const float*)d_in[1];
    const float* Wqkv      = (const float*)d_in[2];
    const float* Wo        = (const float*)d_in[3];
    float* out = (float*)d_out;

    bf16 *hh, *hl, *wqh, *wql, *woh, *wol, *cth, *ctl;
    cudaGetSymbolAddress((void**)&hh,  g_hid_hi);
    cudaGetSymbolAddress((void**)&hl,  g_hid_lo);
    cudaGetSymbolAddress((void**)&wqh, g_wqkv_hi);
    cudaGetSymbolAddress((void**)&wql, g_wqkv_lo);
    cudaGetSymbolAddress((void**)&woh, g_wo_hi);
    cudaGetSymbolAddress((void**)&wol, g_wo_lo);
    cudaGetSymbolAddress((void**)&cth, g_ctx_hi);
    cudaGetSymbolAddress((void**)&ctl, g_ctx_lo);

    cudaFuncSetAttribute(gemm_bf16x3, cudaFuncAttributeMaxDynamicSharedMemorySize, GSMEM);
    cudaFuncSetAttribute(gemm_bf16x3, cudaFuncAttributePreferredSharedMemoryCarveout, 100);
    cudaFuncSetAttribute(gemm_qkv, cudaFuncAttributeMaxDynamicSharedMemorySize, GSMEM);
    cudaFuncSetAttribute(gemm_qkv, cudaFuncAttributePreferredSharedMemoryCarveout, 100);
    cudaFuncSetAttribute(attn_kernel, cudaFuncAttributeMaxDynamicSharedMemorySize, ATTN_SMEM);
    cudaFuncSetAttribute(attn_kernel, cudaFuncAttributePreferredSharedMemoryCarveout, 100);

    // 0. Fused pre-pass (split hidden + transpose both weights)
    prepass_kernel<<<NB_SPLIT + NB_WQ + NB_WO, 256>>>(hidden, Wqkv, Wo);

    // 1. QKV projection with fused RoPE + V-transpose epilogue
    gemm_qkv<<<dim3(QKVF / 128, (B_ * S_) / 128), 256, GSMEM>>>(
        hh, hl, wqh, wql, positions);

    // 2. Causal GQA flash attention
    attn_kernel<<<dim3(S_ / 64, NH_, B_), 128, ATTN_SMEM>>>(nullptr);

    // 3. Output projection
    gemm_bf16x3<<<dim3(H_ / 128, (B_ * S_) / 128), 256, GSMEM>>>(
        cth, ctl, woh, wol, out, B_ * S_, H_, NH_ * D_);
}

// round 16
// speedup vs baseline: 1.2061x; 1.1034x over previous
#include <cuda_runtime.h>
#include <cuda_bf16.h>
#include <math.h>
#include <stdint.h>

#define B_   2
#define S_   2048
#define H_   2048
#define NH_  32
#define NKV_ 8
#define D_   64
#define QKVF ((NH_ + 2 * NKV_) * D_)   // 3072
#define GQA_ (NH_ / NKV_)              // 4

typedef __nv_bfloat16 bf16;

// ---------------------------------------------------------------------------
// Device scratch
// ---------------------------------------------------------------------------
__device__ bf16 g_hid_hi[(size_t)B_ * S_ * H_];
__device__ bf16 g_hid_lo[(size_t)B_ * S_ * H_];
__device__ bf16 g_wqkv_hi[(size_t)QKVF * H_];       // transposed [N][K]
__device__ bf16 g_wqkv_lo[(size_t)QKVF * H_];
__device__ bf16 g_wo_hi[(size_t)H_ * H_];           // transposed [N][K]
__device__ bf16 g_wo_lo[(size_t)H_ * H_];
__device__ bf16 g_q_hi[(size_t)B_ * NH_ * S_ * D_];
__device__ bf16 g_q_lo[(size_t)B_ * NH_ * S_ * D_];
__device__ bf16 g_k_hi[(size_t)B_ * NKV_ * S_ * D_];
__device__ bf16 g_k_lo[(size_t)B_ * NKV_ * S_ * D_];
__device__ bf16 g_vt_hi[(size_t)B_ * NKV_ * D_ * S_];
__device__ bf16 g_vt_lo[(size_t)B_ * NKV_ * D_ * S_];
__device__ bf16 g_ctx_hi[(size_t)B_ * S_ * NH_ * D_];
__device__ bf16 g_ctx_lo[(size_t)B_ * S_ * NH_ * D_];

// ---------------------------------------------------------------------------
// Helpers
// ---------------------------------------------------------------------------
__device__ __forceinline__ uint32_t smem_u32(const void* p) {
    return (uint32_t)__cvta_generic_to_shared(p);
}
__device__ __forceinline__ void cp_async16_sa(uint32_t sa, const void* g) {
    asm volatile("cp.async.cg.shared.global [%0], [%1], 16;\n" :: "r"(sa), "l"(g));
}
__device__ __forceinline__ void cp_commit() {
    asm volatile("cp.async.commit_group;\n");
}
__device__ __forceinline__ uint32_t pack2(float x, float y) {
    uint32_t r;
    asm("cvt.rn.bf16x2.f32 %0, %1, %2;" : "=r"(r) : "f"(y), "f"(x));
    return r;
}
__device__ __forceinline__ void split2(float x, float y, uint32_t& hi, uint32_t& lo) {
    hi = pack2(x, y);
    float hx = __uint_as_float(hi << 16);
    float hy = __uint_as_float(hi & 0xFFFF0000u);
    lo = pack2(x - hx, y - hy);
}
__device__ __forceinline__ void mma_bf16(float* c, const uint32_t* a,
                                         uint32_t b0, uint32_t b1) {
    asm volatile(
        "mma.sync.aligned.m16n8k16.row.col.f32.bf16.bf16.f32 "
        "{%0,%1,%2,%3},{%4,%5,%6,%7},{%8,%9},{%0,%1,%2,%3};"
        : "+f"(c[0]), "+f"(c[1]), "+f"(c[2]), "+f"(c[3])
        : "r"(a[0]), "r"(a[1]), "r"(a[2]), "r"(a[3]), "r"(b0), "r"(b1));
}
__device__ __forceinline__ void ldsm_x4(uint32_t addr, uint32_t* r) {
    asm volatile("ldmatrix.sync.aligned.m8n8.x4.shared.b16 {%0,%1,%2,%3}, [%4];"
                 : "=r"(r[0]), "=r"(r[1]), "=r"(r[2]), "=r"(r[3]) : "r"(addr));
}
__device__ __forceinline__ void rope_sincos(float pos, int d, float& sn, float& cs) {
    const float inv = powf(10000.0f, -(float)(2 * d) / (float)D_);
    const float freq = pos * inv;
    const double dr = (double)freq;
    const double kq = floor(dr * 0.15915494309189534 + 0.5);
    const float  rr = (float)(dr - kq * 6.283185307179586477);
    sincosf(rr, &sn, &cs);
}

// ---------------------------------------------------------------------------
// Fused pre-pass (unchanged)
// ---------------------------------------------------------------------------
#define NB_SPLIT 8192
#define NB_WQ    6144
#define NB_WO    4096

__global__ void prepass_kernel(const float* __restrict__ hidden,
                               const float* __restrict__ Wqkv,
                               const float* __restrict__ Wo) {
    __shared__ float t[32][33];
    const int bid = blockIdx.x;
    const int tid = threadIdx.x;

    if (bid < NB_SPLIT) {
        int i = bid * 256 + tid;
        float4 v = reinterpret_cast<const float4*>(hidden)[i];
        uint32_t h0, l0, h1, l1;
        split2(v.x, v.y, h0, l0);
        split2(v.z, v.w, h1, l1);
        reinterpret_cast<uint2*>(g_hid_hi)[i] = make_uint2(h0, h1);
        reinterpret_cast<uint2*>(g_hid_lo)[i] = make_uint2(l0, l1);
        return;
    }

    const float* src;
    bf16 *dhi, *dlo;
    int N, bx, by;
    if (bid < NB_SPLIT + NB_WQ) {
        int b2 = bid - NB_SPLIT;
        bx = b2 % (QKVF / 32); by = b2 / (QKVF / 32);
        src = Wqkv; dhi = g_wqkv_hi; dlo = g_wqkv_lo; N = QKVF;
    } else {
        int b2 = bid - NB_SPLIT - NB_WQ;
        bx = b2 % (H_ / 32); by = b2 / (H_ / 32);
        src = Wo; dhi = g_wo_hi; dlo = g_wo_lo; N = H_;
    }
    const int K = H_;
    const int n0 = bx * 32, k0 = by * 32;
    const int tx = tid & 31, ty = tid >> 5;
#pragma unroll
    for (int r = 0; r < 4; r++)
        t[ty + 8 * r][tx] = src[(size_t)(k0 + ty + 8 * r) * N + n0 + tx];
    __syncthreads();
#pragma unroll
    for (int r = 0; r < 4; r++) {
        float x = t[tx][ty + 8 * r];
        bf16 h = __float2bfloat16(x);
        size_t off = (size_t)(n0 + ty + 8 * r) * K + k0 + tx;
        dhi[off] = h;
        dlo[off] = __float2bfloat16(x - __bfloat162float(h));
    }
}

// ---------------------------------------------------------------------------
// Shared GEMM mainloop: 128x128x32, 256 thr, 3-stage cp.async, ldmatrix,
// PW=16 (64B rows) + XOR swizzle (unit c -> c ^ ((row>>1)&3)).
// All smem addresses 16B-aligned; LDSM & stores conflict-free.
// Stage = 32KB, 3 stages = 96KB -> 2 CTAs/SM.
// ---------------------------------------------------------------------------
#define PW 16
#define TILE_W (128 * PW)            // 2048 words
#define GSMEM (3 * 4 * TILE_W * 4)   // 98304 B

#define GEMM_LOAD(st, k0)                                                     \
    {                                                                          \
        uint32_t s0 = sbase + (st) * (4 * TILE_W) * 4;                         \
        _Pragma("unroll")                                                      \
        for (int j = 0; j < 8; j++) {                                          \
            int idx = tid + j * 256;                                           \
            int arr = j >> 1;                                                  \
            int r = (idx >> 2) & 127, c = idx & 3;                             \
            int csw = c ^ ((r >> 1) & 3);                                      \
            cp_async16_sa(s0 + (arr * TILE_W + r * PW + csw * 4) * 4,          \
                          gptr[arr] + (size_t)r * K + (k0) + c * 8);           \
        }                                                                      \
        cp_commit();                                                           \
    }

#define GEMM_MAINLOOP(K)                                                       \
    const int NIT = (K) / 32;                                                  \
    GEMM_LOAD(0, 0);                                                           \
    GEMM_LOAD(1, 32);                                                          \
    for (int it = 0; it < NIT; ++it) {                                         \
        const int st = it % 3;                                                 \
        if (it + 1 < NIT) {                                                    \
            asm volatile("cp.async.wait_group 1;\n" ::: "memory");             \
        } else {                                                               \
            asm volatile("cp.async.wait_group 0;\n" ::: "memory");             \
        }                                                                      \
        __syncthreads();                                                       \
        if (it + 2 < NIT) GEMM_LOAD((it + 2) % 3, (it + 2) * 32);              \
        const uint32_t sA_h = sbase + (st * 4 * TILE_W) * 4;                   \
        const uint32_t sA_l = sA_h + TILE_W * 4;                               \
        const uint32_t sB_h = sA_h + 2 * TILE_W * 4;                           \
        const uint32_t sB_l = sA_h + 3 * TILE_W * 4;                           \
        _Pragma("unroll")                                                      \
        for (int ch = 0; ch < 2; ch++) {                                       \
            const uint32_t aswo = (uint32_t)(((aunit + 2 * ch) ^ rsw_a) << 4); \
            const uint32_t bswo = (uint32_t)(((bunit + 2 * ch) ^ rsw_b) << 4); \
            uint32_t ah[2][4], al[2][4];                                       \
            _Pragma("unroll")                                                  \
            for (int mi = 0; mi < 2; mi++) {                                   \
                const uint32_t ar = (uint32_t)((arow0 + mi * 16) * 64) + aswo; \
                ldsm_x4(sA_h + ar, ah[mi]);                                    \
                ldsm_x4(sA_l + ar, al[mi]);                                    \
            }                                                                  \
            _Pragma("unroll")                                                  \
            for (int p = 0; p < 4; p++) {                                      \
                const uint32_t br = (uint32_t)((brow0 + p * 16) * 64) + bswo;  \
                uint32_t bh[4], bl[4];                                         \
                ldsm_x4(sB_h + br, bh);                                        \
                ldsm_x4(sB_l + br, bl);                                        \
                _Pragma("unroll")                                              \
                for (int s = 0; s < 2; s++) {                                  \
                    const int ni = 2 * p + s;                                  \
                    _Pragma("unroll")                                          \
                    for (int mi = 0; mi < 2; mi++) {                           \
                        mma_bf16(acc[mi][ni], ah[mi], bh[2 * s], bh[2 * s + 1]); \
                        mma_bf16(acc[mi][ni], al[mi], bh[2 * s], bh[2 * s + 1]); \
                        mma_bf16(acc[mi][ni], ah[mi], bl[2 * s], bl[2 * s + 1]); \
                    }                                                          \
                }                                                              \
            }                                                                  \
        }                                                                      \
    }

#define GEMM_PROLOG(Ahi, Alo, Bhi, Blo, K)                                     \
    extern __shared__ uint32_t sw[];                                           \
    const uint32_t sbase = smem_u32(sw);                                       \
    const int tid  = threadIdx.x;                                              \
    const int wid  = tid >> 5;                                                 \
    const int lane = tid & 31;                                                 \
    const int g  = lane >> 2;                                                  \
    const int tg = lane & 3;                                                   \
    const int wm = (wid & 3) * 32;                                             \
    const int wn = (wid >> 2) * 64;                                            \
    const bf16* gptr[4] = {                                                    \
        (Ahi) + (size_t)blockIdx.y * 128 * (K),                                \
        (Alo) + (size_t)blockIdx.y * 128 * (K),                                \
        (Bhi) + (size_t)blockIdx.x * 128 * (K),                                \
        (Blo) + (size_t)blockIdx.x * 128 * (K)                                 \
    };                                                                         \
    const int arow0 = wm + (lane & 15);                                        \
    const int brow0 = wn + ((lane >> 4) << 3) + (lane & 7);                    \
    const int aunit = lane >> 4;                                               \
    const int bunit = (lane >> 3) & 1;                                         \
    const int rsw_a = (arow0 >> 1) & 3;                                        \
    const int rsw_b = (brow0 >> 1) & 3;                                        \
    float acc[2][8][4];                                                        \
    _Pragma("unroll")                                                          \
    for (int mi = 0; mi < 2; mi++)                                             \
        _Pragma("unroll")                                                      \
        for (int ni = 0; ni < 8; ni++)                                         \
            _Pragma("unroll")                                                  \
            for (int r = 0; r < 4; r++) acc[mi][ni][r] = 0.f;

// ---------------------------------------------------------------------------
// Generic GEMM (Wo projection)
// ---------------------------------------------------------------------------
__global__ __launch_bounds__(256, 2)
void gemm_bf16x3(const bf16* __restrict__ Ahi, const bf16* __restrict__ Alo,
                 const bf16* __restrict__ Bhi, const bf16* __restrict__ Blo,
                 float* __restrict__ C, int M, int N, int K) {
    GEMM_PROLOG(Ahi, Alo, Bhi, Blo, K)
    GEMM_MAINLOOP(K)
#pragma unroll
    for (int mi = 0; mi < 2; mi++) {
        const int row = blockIdx.y * 128 + wm + mi * 16 + g;
#pragma unroll
        for (int ni = 0; ni < 8; ni++) {
            const int col = blockIdx.x * 128 + wn + ni * 8 + 2 * tg;
            *reinterpret_cast<float2*>(C + (size_t)row * N + col) =
                make_float2(acc[mi][ni][0], acc[mi][ni][1]);
            *reinterpret_cast<float2*>(C + (size_t)(row + 8) * N + col) =
                make_float2(acc[mi][ni][2], acc[mi][ni][3]);
        }
    }
}

// ---------------------------------------------------------------------------
// QKV GEMM with fused RoPE + V split-transpose epilogue (unchanged logic)
// ---------------------------------------------------------------------------
__global__ __launch_bounds__(256, 2)
void gemm_qkv(const bf16* __restrict__ Ahi, const bf16* __restrict__ Alo,
              const bf16* __restrict__ Bhi, const bf16* __restrict__ Blo,
              const int* __restrict__ positions) {
    const int K = H_;
    GEMM_PROLOG(Ahi, Alo, Bhi, Blo, K)
    GEMM_MAINLOOP(K)

    const int tileN0 = blockIdx.x * 128;
    if (tileN0 >= (NH_ + NKV_) * D_) {
        const int colBase = tileN0 - (NH_ + NKV_) * D_;
#pragma unroll
        for (int mi = 0; mi < 2; mi++) {
#pragma unroll
            for (int rh = 0; rh < 2; rh++) {
                const int row = blockIdx.y * 128 + wm + mi * 16 + g + rh * 8;
                const int bb = row >> 11;
                const int ss = row & 2047;
#pragma unroll
                for (int ni = 0; ni < 8; ni++) {
                    const int col = colBase + wn + ni * 8 + 2 * tg;
                    const int kh = col >> 6;
                    const int d  = col & 63;
                    const size_t dbase = ((size_t)(bb * NKV_ + kh)) * D_ * S_;
#pragma unroll
                    for (int j = 0; j < 2; j++) {
                        const float x = acc[mi][ni][rh * 2 + j];
                        bf16 hv = __float2bfloat16(x);
                        g_vt_hi[dbase + (size_t)(d + j) * S_ + ss] = hv;
                        g_vt_lo[dbase + (size_t)(d + j) * S_ + ss] =
                            __float2bfloat16(x - __bfloat162float(hv));
                    }
                }
            }
        }
        return;
    }

    const bool isQ = tileN0 < NH_ * D_;
    const float scale = isQ ? 0.125f : 1.0f;
    bf16* phi = isQ ? g_q_hi : g_k_hi;
    bf16* plo = isQ ? g_q_lo : g_k_lo;

#pragma unroll
    for (int mi = 0; mi < 2; mi++) {
#pragma unroll
        for (int rh = 0; rh < 2; rh++) {
            const int row = blockIdx.y * 128 + wm + mi * 16 + g + rh * 8;
            const int bb = row >> 11;
            const int ss = row & 2047;
            const float pos = (float)positions[ss];
#pragma unroll
            for (int ni = 0; ni < 4; ni++) {
                const int col = tileN0 + wn + ni * 8 + 2 * tg;
                float o0[2], o1[2];
#pragma unroll
                for (int j = 0; j < 2; j++) {
                    const int d = (col & 63) + j;
                    float sn, cs;
                    rope_sincos(pos, d, sn, cs);
                    const float x0 = acc[mi][ni][rh * 2 + j];
                    const float x1 = acc[mi][ni + 4][rh * 2 + j];
                    o0[j] = (x0 * cs - x1 * sn) * scale;
                    o1[j] = (x1 * cs + x0 * sn) * scale;
                }
                uint32_t h0, l0, h1, l1;
                split2(o0[0], o0[1], h0, l0);
                split2(o1[0], o1[1], h1, l1);
                const int hh = isQ ? (col >> 6) : ((col - NH_ * D_) >> 6);
                const int nheads = isQ ? NH_ : NKV_;
                const size_t base = (((size_t)(bb * nheads + hh)) * S_ + ss) * D_
                                  + (col & 63);
                *reinterpret_cast<uint32_t*>(phi + base)      = h0;
                *reinterpret_cast<uint32_t*>(plo + base)      = l0;
                *reinterpret_cast<uint32_t*>(phi + base + 32) = h1;
                *reinterpret_cast<uint32_t*>(plo + base + 32) = l1;
            }
        }
    }
}

// ---------------------------------------------------------------------------
// bf16x3 causal flash attention (unchanged from R14 passing version)
// ---------------------------------------------------------------------------
#define AW 36
#define AT_W (64 * AW)
#define ATTN_SMEM (8 * AT_W * 4)     // 73728 B

__global__ __launch_bounds__(128, 3)
void attn_kernel(float* /*unused*/) {
    extern __shared__ uint32_t sw[];
    const uint32_t sbase = smem_u32(sw);

    const int qtile = gridDim.x - 1 - blockIdx.x;
    const int h = blockIdx.y;
    const int b = blockIdx.z;
    const int kvh = h / GQA_;
    const int q0 = qtile * 64;

    const bf16* qh_g = g_q_hi + (((size_t)(b * NH_ + h)) * S_ + q0) * D_;
    const bf16* ql_g = g_q_lo + (((size_t)(b * NH_ + h)) * S_ + q0) * D_;
    const bf16* kh_g = g_k_hi + ((size_t)(b * NKV_ + kvh)) * S_ * D_;
    const bf16* kl_g = g_k_lo + ((size_t)(b * NKV_ + kvh)) * S_ * D_;
    const bf16* vh_g = g_vt_hi + ((size_t)(b * NKV_ + kvh)) * D_ * S_;
    const bf16* vl_g = g_vt_lo + ((size_t)(b * NKV_ + kvh)) * D_ * S_;

    const int tid  = threadIdx.x;
    const int wid  = tid >> 5;
    const int lane = tid & 31;
    const int g  = lane >> 2;
    const int tg = lane & 3;
    const int wm = wid * 16;

    const uint32_t bk_off = (uint32_t)(((((lane >> 4) << 3) + (lane & 7)) * AW
                                        + ((lane >> 3) & 1) * 4) * 4);

#define ATTN_LOAD_KV(st, kt)                                                    \
    {                                                                            \
        _Pragma("unroll")                                                        \
        for (int j = 0; j < 16; j++) {                                           \
            int idx = tid + j * 128;                                              \
            int arr = j >> 2;                                                     \
            int r = (idx >> 3) & 63, c = idx & 7;                                 \
            int tile = (arr < 2 ? 0 : 4) + 2 * (st) + (arr & 1);                  \
            const bf16* src;                                                      \
            size_t goff;                                                          \
            if (arr == 0)      { src = kh_g; goff = (size_t)((kt) * 64 + r) * D_ + c * 8; } \
            else if (arr == 1) { src = kl_g; goff = (size_t)((kt) * 64 + r) * D_ + c * 8; } \
            else if (arr == 2) { src = vh_g; goff = (size_t)r * S_ + (kt) * 64 + c * 8; }   \
            else               { src = vl_g; goff = (size_t)r * S_ + (kt) * 64 + c * 8; }   \
            cp_async16_sa(sbase + (tile * AT_W + r * AW + c * 4) * 4, src + goff); \
        }                                                                         \
        cp_commit();                                                              \
    }

    ATTN_LOAD_KV(0, 0);

    uint32_t qh[4][4], ql[4][4];
#pragma unroll
    for (int ch = 0; ch < 4; ch++) {
        const size_t e = (size_t)(wm + g) * D_ + ch * 16 + 2 * tg;
        qh[ch][0] = *reinterpret_cast<const uint32_t*>(qh_g + e);
        qh[ch][1] = *reinterpret_cast<const uint32_t*>(qh_g + e + 8 * D_);
        qh[ch][2] = *reinterpret_cast<const uint32_t*>(qh_g + e + 8);
        qh[ch][3] = *reinterpret_cast<const uint32_t*>(qh_g + e + 8 * D_ + 8);
        ql[ch][0] = *reinterpret_cast<const uint32_t*>(ql_g + e);
        ql[ch][1] = *reinterpret_cast<const uint32_t*>(ql_g + e + 8 * D_);
        ql[ch][2] = *reinterpret_cast<const uint32_t*>(ql_g + e + 8);
        ql[ch][3] = *reinterpret_cast<const uint32_t*>(ql_g + e + 8 * D_ + 8);
    }

    float oacc[8][4];
    float m0 = -1e30f, m1 = -1e30f, l0 = 0.f, l1 = 0.f;
#pragma unroll
    for (int ni = 0; ni < 8; ni++)
#pragma unroll
        for (int r = 0; r < 4; r++) oacc[ni][r] = 0.f;

    const int gq0 = q0 + wm + g;
    const int gq1 = gq0 + 8;

    for (int kt = 0; kt <= qtile; kt++) {
        const int cur = kt & 1;
        asm volatile("cp.async.wait_group 0;\n" ::: "memory");
        __syncthreads();
        if (kt + 1 <= qtile) ATTN_LOAD_KV(cur ^ 1, kt + 1);

        const uint32_t Kh_b = sbase + (0 + 2 * cur) * AT_W * 4;
        const uint32_t Kl_b = sbase + (1 + 2 * cur) * AT_W * 4;
        const uint32_t Vh_b = sbase + (4 + 2 * cur) * AT_W * 4;
        const uint32_t Vl_b = sbase + (5 + 2 * cur) * AT_W * 4;

        float sacc[8][4];
#pragma unroll
        for (int ni = 0; ni < 8; ni++)
#pragma unroll
            for (int r = 0; r < 4; r++) sacc[ni][r] = 0.f;

#pragma unroll
        for (int ch = 0; ch < 4; ch++) {
            const uint32_t kb = (uint32_t)(ch * 8 * 4);
#pragma unroll
            for (int p = 0; p < 4; p++) {
                uint32_t kh4[4], kl4[4];
                ldsm_x4(Kh_b + bk_off + (uint32_t)(p * 16 * AW * 4) + kb, kh4);
                ldsm_x4(Kl_b + bk_off + (uint32_t)(p * 16 * AW * 4) + kb, kl4);
#pragma unroll
                for (int s = 0; s < 2; s++) {
                    const int ni = 2 * p + s;
                    mma_bf16(sacc[ni], qh[ch], kh4[2 * s], kh4[2 * s + 1]);
                    mma_bf16(sacc[ni], ql[ch], kh4[2 * s], kh4[2 * s + 1]);
                    mma_bf16(sacc[ni], qh[ch], kl4[2 * s], kl4[2 * s + 1]);
                }
            }
        }

        if (kt == qtile) {
#pragma unroll
            for (int ni = 0; ni < 8; ni++) {
                const int col = kt * 64 + ni * 8 + 2 * tg;
                if (col     > gq0) sacc[ni][0] = -1e30f;
                if (col + 1 > gq0) sacc[ni][1] = -1e30f;
                if (col     > gq1) sacc[ni][2] = -1e30f;
                if (col + 1 > gq1) sacc[ni][3] = -1e30f;
            }
        }

        float mx0 = -1e30f, mx1 = -1e30f;
#pragma unroll
        for (int ni = 0; ni < 8; ni++) {
            mx0 = fmaxf(mx0, fmaxf(sacc[ni][0], sacc[ni][1]));
            mx1 = fmaxf(mx1, fmaxf(sacc[ni][2], sacc[ni][3]));
        }
        mx0 = fmaxf(mx0, __shfl_xor_sync(0xffffffffu, mx0, 1));
        mx0 = fmaxf(mx0, __shfl_xor_sync(0xffffffffu, mx0, 2));
        mx1 = fmaxf(mx1, __shfl_xor_sync(0xffffffffu, mx1, 1));
        mx1 = fmaxf(mx1, __shfl_xor_sync(0xffffffffu, mx1, 2));

        const float mn0 = fmaxf(m0, mx0);
        const float mn1 = fmaxf(m1, mx1);
        const float corr0 = __expf(m0 - mn0);
        const float corr1 = __expf(m1 - mn1);
        float rs0 = 0.f, rs1 = 0.f;
#pragma unroll
        for (int ni = 0; ni < 8; ni++) {
            float p0 = __expf(sacc[ni][0] - mn0);
            float p1 = __expf(sacc[ni][1] - mn0);
            float p2 = __expf(sacc[ni][2] - mn1);
            float p3 = __expf(sacc[ni][3] - mn1);
            sacc[ni][0] = p0; sacc[ni][1] = p1;
            sacc[ni][2] = p2; sacc[ni][3] = p3;
            rs0 += p0 + p1;
            rs1 += p2 + p3;
        }
        rs0 += __shfl_xor_sync(0xffffffffu, rs0, 1);
        rs0 += __shfl_xor_sync(0xffffffffu, rs0, 2);
        rs1 += __shfl_xor_sync(0xffffffffu, rs1, 1);
        rs1 += __shfl_xor_sync(0xffffffffu, rs1, 2);
        l0 = l0 * corr0 + rs0;
        l1 = l1 * corr1 + rs1;
        m0 = mn0;
        m1 = mn1;
#pragma unroll
        for (int ni = 0; ni < 8; ni++) {
            oacc[ni][0] *= corr0;
            oacc[ni][1] *= corr0;
            oacc[ni][2] *= corr1;
            oacc[ni][3] *= corr1;
        }

#pragma unroll
        for (int ch = 0; ch < 4; ch++) {
            const uint32_t kb = (uint32_t)(ch * 8 * 4);
            uint32_t ph[4], pl[4];
            split2(sacc[2 * ch][0],     sacc[2 * ch][1],     ph[0], pl[0]);
            split2(sacc[2 * ch][2],     sacc[2 * ch][3],     ph[1], pl[1]);
            split2(sacc[2 * ch + 1][0], sacc[2 * ch + 1][1], ph[2], pl[2]);
            split2(sacc[2 * ch + 1][2], sacc[2 * ch + 1][3], ph[3], pl[3]);
#pragma unroll
            for (int p = 0; p < 4; p++) {
                uint32_t vh4[4], vl4[4];
                ldsm_x4(Vh_b + bk_off + (uint32_t)(p * 16 * AW * 4) + kb, vh4);
                ldsm_x4(Vl_b + bk_off + (uint32_t)(p * 16 * AW * 4) + kb, vl4);
#pragma unroll
                for (int s = 0; s < 2; s++) {
                    const int ni = 2 * p + s;
                    mma_bf16(oacc[ni], ph, vh4[2 * s], vh4[2 * s + 1]);
                    mma_bf16(oacc[ni], pl, vh4[2 * s], vh4[2 * s + 1]);
                    mma_bf16(oacc[ni], ph, vl4[2 * s], vl4[2 * s + 1]);
                }
            }
        }
    }

    const float il0 = 1.0f / l0;
    const float il1 = 1.0f / l1;
    uint32_t* ch_w = reinterpret_cast<uint32_t*>(g_ctx_hi);
    uint32_t* cl_w = reinterpret_cast<uint32_t*>(g_ctx_lo);
    const size_t off0 = (((size_t)(b * S_ + gq0)) * (NH_ * D_) + h * D_) >> 1;
    const size_t off1 = (((size_t)(b * S_ + gq1)) * (NH_ * D_) + h * D_) >> 1;
#pragma unroll
    for (int ni = 0; ni < 8; ni++) {
        const int cw = ni * 4 + tg;
        uint32_t h0, L0, h1, L1;
        split2(oacc[ni][0] * il0, oacc[ni][1] * il0, h0, L0);
        split2(oacc[ni][2] * il1, oacc[ni][3] * il1, h1, L1);
        ch_w[off0 + cw] = h0;
        cl_w[off0 + cw] = L0;
        ch_w[off1 + cw] = h1;
        cl_w[off1 + cw] = L1;
    }
}

// ---------------------------------------------------------------------------
// Launch
// ---------------------------------------------------------------------------
extern "C" void kernel_launch(void* const* d_in, const int* in_sizes, int n_in,
                              void* d_out, int out_size) {
    const int*   positions = (const int*)d_in[0];
    const float* hidden    = (const float*)d_in[1];
    const float* Wqkv      = (const float*)d_in[2];
    const float* Wo        = (const float*)d_in[3];
    float* out = (float*)d_out;

    bf16 *hh, *hl, *wqh, *wql, *woh, *wol, *cth, *ctl;
    cudaGetSymbolAddress((void**)&hh,  g_hid_hi);
    cudaGetSymbolAddress((void**)&hl,  g_hid_lo);
    cudaGetSymbolAddress((void**)&wqh, g_wqkv_hi);
    cudaGetSymbolAddress((void**)&wql, g_wqkv_lo);
    cudaGetSymbolAddress((void**)&woh, g_wo_hi);
    cudaGetSymbolAddress((void**)&wol, g_wo_lo);
    cudaGetSymbolAddress((void**)&cth, g_ctx_hi);
    cudaGetSymbolAddress((void**)&ctl, g_ctx_lo);

    cudaFuncSetAttribute(gemm_bf16x3, cudaFuncAttributeMaxDynamicSharedMemorySize, GSMEM);
    cudaFuncSetAttribute(gemm_bf16x3, cudaFuncAttributePreferredSharedMemoryCarveout, 100);
    cudaFuncSetAttribute(gemm_qkv, cudaFuncAttributeMaxDynamicSharedMemorySize, GSMEM);
    cudaFuncSetAttribute(gemm_qkv, cudaFuncAttributePreferredSharedMemoryCarveout, 100);
    cudaFuncSetAttribute(attn_kernel, cudaFuncAttributeMaxDynamicSharedMemorySize, ATTN_SMEM);
    cudaFuncSetAttribute(attn_kernel, cudaFuncAttributePreferredSharedMemoryCarveout, 100);

    // 0. Fused pre-pass (split hidden + transpose both weights)
    prepass_kernel<<<NB_SPLIT + NB_WQ + NB_WO, 256>>>(hidden, Wqkv, Wo);

    // 1. QKV projection with fused RoPE + V-transpose epilogue
    gemm_qkv<<<dim3(QKVF / 128, (B_ * S_) / 128), 256, GSMEM>>>(
        hh, hl, wqh, wql, positions);

    // 2. Causal GQA flash attention
    attn_kernel<<<dim3(S_ / 64, NH_, B_), 128, ATTN_SMEM>>>(nullptr);

    // 3. Output projection
    gemm_bf16x3<<<dim3(H_ / 128, (B_ * S_) / 128), 256, GSMEM>>>(
        cth, ctl, woh, wol, out, B_ * S_, H_, NH_ * D_);
}

// round 17
// speedup vs baseline: 1.2136x; 1.0062x over previous
#include <cuda_runtime.h>
#include <cuda_bf16.h>
#include <math.h>
#include <stdint.h>

#define B_   2
#define S_   2048
#define H_   2048
#define NH_  32
#define NKV_ 8
#define D_   64
#define QKVF ((NH_ + 2 * NKV_) * D_)   // 3072
#define GQA_ (NH_ / NKV_)              // 4

typedef __nv_bfloat16 bf16;

// ---------------------------------------------------------------------------
// Device scratch
// ---------------------------------------------------------------------------
__device__ bf16 g_hid_hi[(size_t)B_ * S_ * H_];
__device__ bf16 g_hid_lo[(size_t)B_ * S_ * H_];
__device__ bf16 g_wqkv_hi[(size_t)QKVF * H_];       // transposed [N][K]
__device__ bf16 g_wqkv_lo[(size_t)QKVF * H_];
__device__ bf16 g_wo_hi[(size_t)H_ * H_];           // transposed [N][K]
__device__ bf16 g_wo_lo[(size_t)H_ * H_];
__device__ bf16 g_q_hi[(size_t)B_ * NH_ * S_ * D_];
__device__ bf16 g_q_lo[(size_t)B_ * NH_ * S_ * D_];
__device__ bf16 g_k_hi[(size_t)B_ * NKV_ * S_ * D_];
__device__ bf16 g_k_lo[(size_t)B_ * NKV_ * S_ * D_];
__device__ bf16 g_vt_hi[(size_t)B_ * NKV_ * D_ * S_];
__device__ bf16 g_vt_lo[(size_t)B_ * NKV_ * D_ * S_];
__device__ bf16 g_ctx_hi[(size_t)B_ * S_ * NH_ * D_];
__device__ bf16 g_ctx_lo[(size_t)B_ * S_ * NH_ * D_];

// ---------------------------------------------------------------------------
// Helpers
// ---------------------------------------------------------------------------
__device__ __forceinline__ uint32_t smem_u32(const void* p) {
    return (uint32_t)__cvta_generic_to_shared(p);
}
__device__ __forceinline__ void cp_async16_sa(uint32_t sa, const void* g) {
    asm volatile("cp.async.cg.shared.global [%0], [%1], 16;\n" :: "r"(sa), "l"(g));
}
__device__ __forceinline__ void cp_commit() {
    asm volatile("cp.async.commit_group;\n");
}
__device__ __forceinline__ uint32_t pack2(float x, float y) {
    uint32_t r;
    asm("cvt.rn.bf16x2.f32 %0, %1, %2;" : "=r"(r) : "f"(y), "f"(x));
    return r;
}
__device__ __forceinline__ void split2(float x, float y, uint32_t& hi, uint32_t& lo) {
    hi = pack2(x, y);
    float hx = __uint_as_float(hi << 16);
    float hy = __uint_as_float(hi & 0xFFFF0000u);
    lo = pack2(x - hx, y - hy);
}
__device__ __forceinline__ void mma_bf16(float* c, const uint32_t* a,
                                         uint32_t b0, uint32_t b1) {
    asm volatile(
        "mma.sync.aligned.m16n8k16.row.col.f32.bf16.bf16.f32 "
        "{%0,%1,%2,%3},{%4,%5,%6,%7},{%8,%9},{%0,%1,%2,%3};"
        : "+f"(c[0]), "+f"(c[1]), "+f"(c[2]), "+f"(c[3])
        : "r"(a[0]), "r"(a[1]), "r"(a[2]), "r"(a[3]), "r"(b0), "r"(b1));
}
__device__ __forceinline__ void ldsm_x4(uint32_t addr, uint32_t* r) {
    asm volatile("ldmatrix.sync.aligned.m8n8.x4.shared.b16 {%0,%1,%2,%3}, [%4];"
                 : "=r"(r[0]), "=r"(r[1]), "=r"(r[2]), "=r"(r[3]) : "r"(addr));
}
// Double-precision range reduction (prepass-era path; kept for reference use)
__device__ __forceinline__ void rope_sincos(float pos, int d, float& sn, float& cs) {
    const float inv = powf(10000.0f, -(float)(2 * d) / (float)D_);
    const float freq = pos * inv;
    const double dr = (double)freq;
    const double kq = floor(dr * 0.15915494309189534 + 0.5);
    const float  rr = (float)(dr - kq * 6.283185307179586477);
    sincosf(rr, &sn, &cs);
}
// fp32 Cody-Waite range reduction (angle err ~5e-7, k <= 326)
__device__ __forceinline__ void rope_sincos_f(float pos, float inv, float& sn, float& cs) {
    const float freq = pos * inv;
    const float k = rintf(freq * 0.15915494f);
    float r = fmaf(-k, 6.2831855f, freq);          // float(2pi) = 0x40C90FDB
    r = fmaf(-k, -1.7484555e-07f, r);              // c2 = 2pi - float(2pi)
    sincosf(r, &sn, &cs);
}

// ---------------------------------------------------------------------------
// Fused pre-pass (unchanged)
// ---------------------------------------------------------------------------
#define NB_SPLIT 8192
#define NB_WQ    6144
#define NB_WO    4096

__global__ void prepass_kernel(const float* __restrict__ hidden,
                               const float* __restrict__ Wqkv,
                               const float* __restrict__ Wo) {
    __shared__ float t[32][33];
    const int bid = blockIdx.x;
    const int tid = threadIdx.x;

    if (bid < NB_SPLIT) {
        int i = bid * 256 + tid;
        float4 v = reinterpret_cast<const float4*>(hidden)[i];
        uint32_t h0, l0, h1, l1;
        split2(v.x, v.y, h0, l0);
        split2(v.z, v.w, h1, l1);
        reinterpret_cast<uint2*>(g_hid_hi)[i] = make_uint2(h0, h1);
        reinterpret_cast<uint2*>(g_hid_lo)[i] = make_uint2(l0, l1);
        return;
    }

    const float* src;
    bf16 *dhi, *dlo;
    int N, bx, by;
    if (bid < NB_SPLIT + NB_WQ) {
        int b2 = bid - NB_SPLIT;
        bx = b2 % (QKVF / 32); by = b2 / (QKVF / 32);
        src = Wqkv; dhi = g_wqkv_hi; dlo = g_wqkv_lo; N = QKVF;
    } else {
        int b2 = bid - NB_SPLIT - NB_WQ;
        bx = b2 % (H_ / 32); by = b2 / (H_ / 32);
        src = Wo; dhi = g_wo_hi; dlo = g_wo_lo; N = H_;
    }
    const int K = H_;
    const int n0 = bx * 32, k0 = by * 32;
    const int tx = tid & 31, ty = tid >> 5;
#pragma unroll
    for (int r = 0; r < 4; r++)
        t[ty + 8 * r][tx] = src[(size_t)(k0 + ty + 8 * r) * N + n0 + tx];
    __syncthreads();
#pragma unroll
    for (int r = 0; r < 4; r++) {
        float x = t[tx][ty + 8 * r];
        bf16 h = __float2bfloat16(x);
        size_t off = (size_t)(n0 + ty + 8 * r) * K + k0 + tx;
        dhi[off] = h;
        dlo[off] = __float2bfloat16(x - __bfloat162float(h));
    }
}

// ---------------------------------------------------------------------------
// Shared GEMM mainloop: 128x128x32, 256 thr, 3-stage cp.async, ldmatrix,
// PW=16 (64B rows) + XOR swizzle (unit c -> c ^ ((row>>1)&3)).
// ---------------------------------------------------------------------------
#define PW 16
#define TILE_W (128 * PW)            // 2048 words
#define GSMEM (3 * 4 * TILE_W * 4)   // 98304 B

#define GEMM_LOAD(st, k0)                                                     \
    {                                                                          \
        uint32_t s0 = sbase + (st) * (4 * TILE_W) * 4;                         \
        _Pragma("unroll")                                                      \
        for (int j = 0; j < 8; j++) {                                          \
            int idx = tid + j * 256;                                           \
            int arr = j >> 1;                                                  \
            int r = (idx >> 2) & 127, c = idx & 3;                             \
            int csw = c ^ ((r >> 1) & 3);                                      \
            cp_async16_sa(s0 + (arr * TILE_W + r * PW + csw * 4) * 4,          \
                          gptr[arr] + (size_t)r * K + (k0) + c * 8);           \
        }                                                                      \
        cp_commit();                                                           \
    }

#define GEMM_MAINLOOP(K)                                                       \
    const int NIT = (K) / 32;                                                  \
    GEMM_LOAD(0, 0);                                                           \
    GEMM_LOAD(1, 32);                                                          \
    for (int it = 0; it < NIT; ++it) {                                         \
        const int st = it % 3;                                                 \
        if (it + 1 < NIT) {                                                    \
            asm volatile("cp.async.wait_group 1;\n" ::: "memory");             \
        } else {                                                               \
            asm volatile("cp.async.wait_group 0;\n" ::: "memory");             \
        }                                                                      \
        __syncthreads();                                                       \
        if (it + 2 < NIT) GEMM_LOAD((it + 2) % 3, (it + 2) * 32);              \
        const uint32_t sA_h = sbase + (st * 4 * TILE_W) * 4;                   \
        const uint32_t sA_l = sA_h + TILE_W * 4;                               \
        const uint32_t sB_h = sA_h + 2 * TILE_W * 4;                           \
        const uint32_t sB_l = sA_h + 3 * TILE_W * 4;                           \
        _Pragma("unroll")                                                      \
        for (int ch = 0; ch < 2; ch++) {                                       \
            const uint32_t aswo = (uint32_t)(((aunit + 2 * ch) ^ rsw_a) << 4); \
            const uint32_t bswo = (uint32_t)(((bunit + 2 * ch) ^ rsw_b) << 4); \
            uint32_t ah[2][4], al[2][4];                                       \
            _Pragma("unroll")                                                  \
            for (int mi = 0; mi < 2; mi++) {                                   \
                const uint32_t ar = (uint32_t)((arow0 + mi * 16) * 64) + aswo; \
                ldsm_x4(sA_h + ar, ah[mi]);                                    \
                ldsm_x4(sA_l + ar, al[mi]);                                    \
            }                                                                  \
            _Pragma("unroll")                                                  \
            for (int p = 0; p < 4; p++) {                                      \
                const uint32_t br = (uint32_t)((brow0 + p * 16) * 64) + bswo;  \
                uint32_t bh[4], bl[4];                                         \
                ldsm_x4(sB_h + br, bh);                                        \
                ldsm_x4(sB_l + br, bl);                                        \
                _Pragma("unroll")                                              \
                for (int s = 0; s < 2; s++) {                                  \
                    const int ni = 2 * p + s;                                  \
                    _Pragma("unroll")                                          \
                    for (int mi = 0; mi < 2; mi++) {                           \
                        mma_bf16(acc[mi][ni], ah[mi], bh[2 * s], bh[2 * s + 1]); \
                        mma_bf16(acc[mi][ni], al[mi], bh[2 * s], bh[2 * s + 1]); \
                        mma_bf16(acc[mi][ni], ah[mi], bl[2 * s], bl[2 * s + 1]); \
                    }                                                          \
                }                                                              \
            }                                                                  \
        }                                                                      \
    }

#define GEMM_PROLOG(Ahi, Alo, Bhi, Blo, K)                                     \
    extern __shared__ uint32_t sw[];                                           \
    const uint32_t sbase = smem_u32(sw);                                       \
    const int tid  = threadIdx.x;                                              \
    const int wid  = tid >> 5;                                                 \
    const int lane = tid & 31;                                                 \
    const int g  = lane >> 2;                                                  \
    const int tg = lane & 3;                                                   \
    const int wm = (wid & 3) * 32;                                             \
    const int wn = (wid >> 2) * 64;                                            \
    const bf16* gptr[4] = {                                                    \
        (Ahi) + (size_t)blockIdx.y * 128 * (K),                                \
        (Alo) + (size_t)blockIdx.y * 128 * (K),                                \
        (Bhi) + (size_t)blockIdx.x * 128 * (K),                                \
        (Blo) + (size_t)blockIdx.x * 128 * (K)                                 \
    };                                                                         \
    const int arow0 = wm + (lane & 15);                                        \
    const int brow0 = wn + ((lane >> 4) << 3) + (lane & 7);                    \
    const int aunit = lane >> 4;                                               \
    const int bunit = (lane >> 3) & 1;                                         \
    const int rsw_a = (arow0 >> 1) & 3;                                        \
    const int rsw_b = (brow0 >> 1) & 3;                                        \
    float acc[2][8][4];                                                        \
    _Pragma("unroll")                                                          \
    for (int mi = 0; mi < 2; mi++)                                             \
        _Pragma("unroll")                                                      \
        for (int ni = 0; ni < 8; ni++)                                         \
            _Pragma("unroll")                                                  \
            for (int r = 0; r < 4; r++) acc[mi][ni][r] = 0.f;

// ---------------------------------------------------------------------------
// Generic GEMM (Wo projection)
// ---------------------------------------------------------------------------
__global__ __launch_bounds__(256, 2)
void gemm_bf16x3(const bf16* __restrict__ Ahi, const bf16* __restrict__ Alo,
                 const bf16* __restrict__ Bhi, const bf16* __restrict__ Blo,
                 float* __restrict__ C, int M, int N, int K) {
    GEMM_PROLOG(Ahi, Alo, Bhi, Blo, K)
    GEMM_MAINLOOP(K)
#pragma unroll
    for (int mi = 0; mi < 2; mi++) {
        const int row = blockIdx.y * 128 + wm + mi * 16 + g;
#pragma unroll
        for (int ni = 0; ni < 8; ni++) {
            const int col = blockIdx.x * 128 + wn + ni * 8 + 2 * tg;
            *reinterpret_cast<float2*>(C + (size_t)row * N + col) =
                make_float2(acc[mi][ni][0], acc[mi][ni][1]);
            *reinterpret_cast<float2*>(C + (size_t)(row + 8) * N + col) =
                make_float2(acc[mi][ni][2], acc[mi][ni][3]);
        }
    }
}

// ---------------------------------------------------------------------------
// QKV GEMM with fused RoPE + V split-transpose epilogue.
// RoPE epilogue: powf hoisted to 8 distinct d values; fp32 Cody-Waite.
// ---------------------------------------------------------------------------
__global__ __launch_bounds__(256, 2)
void gemm_qkv(const bf16* __restrict__ Ahi, const bf16* __restrict__ Alo,
              const bf16* __restrict__ Bhi, const bf16* __restrict__ Blo,
              const int* __restrict__ positions) {
    const int K = H_;
    GEMM_PROLOG(Ahi, Alo, Bhi, Blo, K)
    GEMM_MAINLOOP(K)

    const int tileN0 = blockIdx.x * 128;
    if (tileN0 >= (NH_ + NKV_) * D_) {
        const int colBase = tileN0 - (NH_ + NKV_) * D_;
#pragma unroll
        for (int mi = 0; mi < 2; mi++) {
#pragma unroll
            for (int rh = 0; rh < 2; rh++) {
                const int row = blockIdx.y * 128 + wm + mi * 16 + g + rh * 8;
                const int bb = row >> 11;
                const int ss = row & 2047;
#pragma unroll
                for (int ni = 0; ni < 8; ni++) {
                    const int col = colBase + wn + ni * 8 + 2 * tg;
                    const int kh = col >> 6;
                    const int d  = col & 63;
                    const size_t dbase = ((size_t)(bb * NKV_ + kh)) * D_ * S_;
#pragma unroll
                    for (int j = 0; j < 2; j++) {
                        const float x = acc[mi][ni][rh * 2 + j];
                        bf16 hv = __float2bfloat16(x);
                        g_vt_hi[dbase + (size_t)(d + j) * S_ + ss] = hv;
                        g_vt_lo[dbase + (size_t)(d + j) * S_ + ss] =
                            __float2bfloat16(x - __bfloat162float(hv));
                    }
                }
            }
        }
        return;
    }

    const bool isQ = tileN0 < NH_ * D_;
    const float scale = isQ ? 0.125f : 1.0f;
    bf16* phi = isQ ? g_q_hi : g_k_hi;
    bf16* plo = isQ ? g_q_lo : g_k_lo;

    // Hoisted: 8 distinct inverse-frequency values per thread (d depends on ni,j only)
    float invv[4][2];
#pragma unroll
    for (int ni = 0; ni < 4; ni++) {
        const int col = tileN0 + wn + ni * 8 + 2 * tg;
#pragma unroll
        for (int j = 0; j < 2; j++) {
            const int d = (col & 63) + j;
            invv[ni][j] = powf(10000.0f, -(float)(2 * d) / (float)D_);
        }
    }

#pragma unroll
    for (int mi = 0; mi < 2; mi++) {
#pragma unroll
        for (int rh = 0; rh < 2; rh++) {
            const int row = blockIdx.y * 128 + wm + mi * 16 + g + rh * 8;
            const int bb = row >> 11;
            const int ss = row & 2047;
            const float pos = (float)positions[ss];
#pragma unroll
            for (int ni = 0; ni < 4; ni++) {
                const int col = tileN0 + wn + ni * 8 + 2 * tg;
                float o0[2], o1[2];
#pragma unroll
                for (int j = 0; j < 2; j++) {
                    float sn, cs;
                    rope_sincos_f(pos, invv[ni][j], sn, cs);
                    const float x0 = acc[mi][ni][rh * 2 + j];
                    const float x1 = acc[mi][ni + 4][rh * 2 + j];
                    o0[j] = (x0 * cs - x1 * sn) * scale;
                    o1[j] = (x1 * cs + x0 * sn) * scale;
                }
                uint32_t h0, l0, h1, l1;
                split2(o0[0], o0[1], h0, l0);
                split2(o1[0], o1[1], h1, l1);
                const int hh = isQ ? (col >> 6) : ((col - NH_ * D_) >> 6);
                const int nheads = isQ ? NH_ : NKV_;
                const size_t base = (((size_t)(bb * nheads + hh)) * S_ + ss) * D_
                                  + (col & 63);
                *reinterpret_cast<uint32_t*>(phi + base)      = h0;
                *reinterpret_cast<uint32_t*>(plo + base)      = l0;
                *reinterpret_cast<uint32_t*>(phi + base + 32) = h1;
                *reinterpret_cast<uint32_t*>(plo + base + 32) = l1;
            }
        }
    }
}

// ---------------------------------------------------------------------------
// bf16x3 causal flash attention (64 q-rows, 128 thr, 2 CTAs/SM — measured-best)
// ---------------------------------------------------------------------------
#define AW 36
#define AT_W (64 * AW)
#define ATTN_SMEM (8 * AT_W * 4)     // 73728 B

__global__ __launch_bounds__(128, 2)
void attn_kernel(float* /*unused*/) {
    extern __shared__ uint32_t sw[];
    const uint32_t sbase = smem_u32(sw);

    const int qtile = gridDim.x - 1 - blockIdx.x;
    const int h = blockIdx.y;
    const int b = blockIdx.z;
    const int kvh = h / GQA_;
    const int q0 = qtile * 64;

    const bf16* qh_g = g_q_hi + (((size_t)(b * NH_ + h)) * S_ + q0) * D_;
    const bf16* ql_g = g_q_lo + (((size_t)(b * NH_ + h)) * S_ + q0) * D_;
    const bf16* kh_g = g_k_hi + ((size_t)(b * NKV_ + kvh)) * S_ * D_;
    const bf16* kl_g = g_k_lo + ((size_t)(b * NKV_ + kvh)) * S_ * D_;
    const bf16* vh_g = g_vt_hi + ((size_t)(b * NKV_ + kvh)) * D_ * S_;
    const bf16* vl_g = g_vt_lo + ((size_t)(b * NKV_ + kvh)) * D_ * S_;

    const int tid  = threadIdx.x;
    const int wid  = tid >> 5;
    const int lane = tid & 31;
    const int g  = lane >> 2;
    const int tg = lane & 3;
    const int wm = wid * 16;

    const uint32_t bk_off = (uint32_t)(((((lane >> 4) << 3) + (lane & 7)) * AW
                                        + ((lane >> 3) & 1) * 4) * 4);

#define ATTN_LOAD_KV(st, kt)                                                    \
    {                                                                            \
        _Pragma("unroll")                                                        \
        for (int j = 0; j < 16; j++) {                                           \
            int idx = tid + j * 128;                                              \
            int arr = j >> 2;                                                     \
            int r = (idx >> 3) & 63, c = idx & 7;                                 \
            int tile = (arr < 2 ? 0 : 4) + 2 * (st) + (arr & 1);                  \
            const bf16* src;                                                      \
            size_t goff;                                                          \
            if (arr == 0)      { src = kh_g; goff = (size_t)((kt) * 64 + r) * D_ + c * 8; } \
            else if (arr == 1) { src = kl_g; goff = (size_t)((kt) * 64 + r) * D_ + c * 8; } \
            else if (arr == 2) { src = vh_g; goff = (size_t)r * S_ + (kt) * 64 + c * 8; }   \
            else               { src = vl_g; goff = (size_t)r * S_ + (kt) * 64 + c * 8; }   \
            cp_async16_sa(sbase + (tile * AT_W + r * AW + c * 4) * 4, src + goff); \
        }                                                                         \
        cp_commit();                                                              \
    }

    ATTN_LOAD_KV(0, 0);

    uint32_t qh[4][4], ql[4][4];
#pragma unroll
    for (int ch = 0; ch < 4; ch++) {
        const size_t e = (size_t)(wm + g) * D_ + ch * 16 + 2 * tg;
        qh[ch][0] = *reinterpret_cast<const uint32_t*>(qh_g + e);
        qh[ch][1] = *reinterpret_cast<const uint32_t*>(qh_g + e + 8 * D_);
        qh[ch][2] = *reinterpret_cast<const uint32_t*>(qh_g + e + 8);
        qh[ch][3] = *reinterpret_cast<const uint32_t*>(qh_g + e + 8 * D_ + 8);
        ql[ch][0] = *reinterpret_cast<const uint32_t*>(ql_g + e);
        ql[ch][1] = *reinterpret_cast<const uint32_t*>(ql_g + e + 8 * D_);
        ql[ch][2] = *reinterpret_cast<const uint32_t*>(ql_g + e + 8);
        ql[ch][3] = *reinterpret_cast<const uint32_t*>(ql_g + e + 8 * D_ + 8);
    }

    float oacc[8][4];
    float m0 = -1e30f, m1 = -1e30f, l0 = 0.f, l1 = 0.f;
#pragma unroll
    for (int ni = 0; ni < 8; ni++)
#pragma unroll
        for (int r = 0; r < 4; r++) oacc[ni][r] = 0.f;

    const int gq0 = q0 + wm + g;
    const int gq1 = gq0 + 8;

    for (int kt = 0; kt <= qtile; kt++) {
        const int cur = kt & 1;
        asm volatile("cp.async.wait_group 0;\n" ::: "memory");
        __syncthreads();
        if (kt + 1 <= qtile) ATTN_LOAD_KV(cur ^ 1, kt + 1);

        const uint32_t Kh_b = sbase + (0 + 2 * cur) * AT_W * 4;
        const uint32_t Kl_b = sbase + (1 + 2 * cur) * AT_W * 4;
        const uint32_t Vh_b = sbase + (4 + 2 * cur) * AT_W * 4;
        const uint32_t Vl_b = sbase + (5 + 2 * cur) * AT_W * 4;

        float sacc[8][4];
#pragma unroll
        for (int ni = 0; ni < 8; ni++)
#pragma unroll
            for (int r = 0; r < 4; r++) sacc[ni][r] = 0.f;

#pragma unroll
        for (int ch = 0; ch < 4; ch++) {
            const uint32_t kb = (uint32_t)(ch * 8 * 4);
#pragma unroll
            for (int p = 0; p < 4; p++) {
                uint32_t kh4[4], kl4[4];
                ldsm_x4(Kh_b + bk_off + (uint32_t)(p * 16 * AW * 4) + kb, kh4);
                ldsm_x4(Kl_b + bk_off + (uint32_t)(p * 16 * AW * 4) + kb, kl4);
#pragma unroll
                for (int s = 0; s < 2; s++) {
                    const int ni = 2 * p + s;
                    mma_bf16(sacc[ni], qh[ch], kh4[2 * s], kh4[2 * s + 1]);
                    mma_bf16(sacc[ni], ql[ch], kh4[2 * s], kh4[2 * s + 1]);
                    mma_bf16(sacc[ni], qh[ch], kl4[2 * s], kl4[2 * s + 1]);
                }
            }
        }

        if (kt == qtile) {
#pragma unroll
            for (int ni = 0; ni < 8; ni++) {
                const int col = kt * 64 + ni * 8 + 2 * tg;
                if (col     > gq0) sacc[ni][0] = -1e30f;
                if (col + 1 > gq0) sacc[ni][1] = -1e30f;
                if (col     > gq1) sacc[ni][2] = -1e30f;
                if (col + 1 > gq1) sacc[ni][3] = -1e30f;
            }
        }

        float mx0 = -1e30f, mx1 = -1e30f;
#pragma unroll
        for (int ni = 0; ni < 8; ni++) {
            mx0 = fmaxf(mx0, fmaxf(sacc[ni][0], sacc[ni][1]));
            mx1 = fmaxf(mx1, fmaxf(sacc[ni][2], sacc[ni][3]));
        }
        mx0 = fmaxf(mx0, __shfl_xor_sync(0xffffffffu, mx0, 1));
        mx0 = fmaxf(mx0, __shfl_xor_sync(0xffffffffu, mx0, 2));
        mx1 = fmaxf(mx1, __shfl_xor_sync(0xffffffffu, mx1, 1));
        mx1 = fmaxf(mx1, __shfl_xor_sync(0xffffffffu, mx1, 2));

        const float mn0 = fmaxf(m0, mx0);
        const float mn1 = fmaxf(m1, mx1);
        const float corr0 = __expf(m0 - mn0);
        const float corr1 = __expf(m1 - mn1);
        float rs0 = 0.f, rs1 = 0.f;
#pragma unroll
        for (int ni = 0; ni < 8; ni++) {
            float p0 = __expf(sacc[ni][0] - mn0);
            float p1 = __expf(sacc[ni][1] - mn0);
            float p2 = __expf(sacc[ni][2] - mn1);
            float p3 = __expf(sacc[ni][3] - mn1);
            sacc[ni][0] = p0; sacc[ni][1] = p1;
            sacc[ni][2] = p2; sacc[ni][3] = p3;
            rs0 += p0 + p1;
            rs1 += p2 + p3;
        }
        rs0 += __shfl_xor_sync(0xffffffffu, rs0, 1);
        rs0 += __shfl_xor_sync(0xffffffffu, rs0, 2);
        rs1 += __shfl_xor_sync(0xffffffffu, rs1, 1);
        rs1 += __shfl_xor_sync(0xffffffffu, rs1, 2);
        l0 = l0 * corr0 + rs0;
        l1 = l1 * corr1 + rs1;
        m0 = mn0;
        m1 = mn1;
#pragma unroll
        for (int ni = 0; ni < 8; ni++) {
            oacc[ni][0] *= corr0;
            oacc[ni][1] *= corr0;
            oacc[ni][2] *= corr1;
            oacc[ni][3] *= corr1;
        }

#pragma unroll
        for (int ch = 0; ch < 4; ch++) {
            const uint32_t kb = (uint32_t)(ch * 8 * 4);
            uint32_t ph[4], pl[4];
            split2(sacc[2 * ch][0],     sacc[2 * ch][1],     ph[0], pl[0]);
            split2(sacc[2 * ch][2],     sacc[2 * ch][3],     ph[1], pl[1]);
            split2(sacc[2 * ch + 1][0], sacc[2 * ch + 1][1], ph[2], pl[2]);
            split2(sacc[2 * ch + 1][2], sacc[2 * ch + 1][3], ph[3], pl[3]);
#pragma unroll
            for (int p = 0; p < 4; p++) {
                uint32_t vh4[4], vl4[4];
                ldsm_x4(Vh_b + bk_off + (uint32_t)(p * 16 * AW * 4) + kb, vh4);
                ldsm_x4(Vl_b + bk_off + (uint32_t)(p * 16 * AW * 4) + kb, vl4);
#pragma unroll
                for (int s = 0; s < 2; s++) {
                    const int ni = 2 * p + s;
                    mma_bf16(oacc[ni], ph, vh4[2 * s], vh4[2 * s + 1]);
                    mma_bf16(oacc[ni], pl, vh4[2 * s], vh4[2 * s + 1]);
                    mma_bf16(oacc[ni], ph, vl4[2 * s], vl4[2 * s + 1]);
                }
            }
        }
    }

    const float il0 = 1.0f / l0;
    const float il1 = 1.0f / l1;
    uint32_t* ch_w = reinterpret_cast<uint32_t*>(g_ctx_hi);
    uint32_t* cl_w = reinterpret_cast<uint32_t*>(g_ctx_lo);
    const size_t off0 = (((size_t)(b * S_ + gq0)) * (NH_ * D_) + h * D_) >> 1;
    const size_t off1 = (((size_t)(b * S_ + gq1)) * (NH_ * D_) + h * D_) >> 1;
#pragma unroll
    for (int ni = 0; ni < 8; ni++) {
        const int cw = ni * 4 + tg;
        uint32_t h0, L0, h1, L1;
        split2(oacc[ni][0] * il0, oacc[ni][1] * il0, h0, L0);
        split2(oacc[ni][2] * il1, oacc[ni][3] * il1, h1, L1);
        ch_w[off0 + cw] = h0;
        cl_w[off0 + cw] = L0;
        ch_w[off1 + cw] = h1;
        cl_w[off1 + cw] = L1;
    }
}

// ---------------------------------------------------------------------------
// Launch
// ---------------------------------------------------------------------------
extern "C" void kernel_launch(void* const* d_in, const int* in_sizes, int n_in,
                              void* d_out, int out_size) {
    const int*   positions = (const int*)d_in[0];
    const float* hidden    = (const float*)d_in[1];
    const float* Wqkv      = (const float*)d_in[2];
    const float* Wo        = (const float*)d_in[3];
    float* out = (float*)d_out;

    bf16 *hh, *hl, *wqh, *wql, *woh, *wol, *cth, *ctl;
    cudaGetSymbolAddress((void**)&hh,  g_hid_hi);
    cudaGetSymbolAddress((void**)&hl,  g_hid_lo);
    cudaGetSymbolAddress((void**)&wqh, g_wqkv_hi);
    cudaGetSymbolAddress((void**)&wql, g_wqkv_lo);
    cudaGetSymbolAddress((void**)&woh, g_wo_hi);
    cudaGetSymbolAddress((void**)&wol, g_wo_lo);
    cudaGetSymbolAddress((void**)&cth, g_ctx_hi);
    cudaGetSymbolAddress((void**)&ctl, g_ctx_lo);

    cudaFuncSetAttribute(gemm_bf16x3, cudaFuncAttributeMaxDynamicSharedMemorySize, GSMEM);
    cudaFuncSetAttribute(gemm_bf16x3, cudaFuncAttributePreferredSharedMemoryCarveout, 100);
    cudaFuncSetAttribute(gemm_qkv, cudaFuncAttributeMaxDynamicSharedMemorySize, GSMEM);
    cudaFuncSetAttribute(gemm_qkv, cudaFuncAttributePreferredSharedMemoryCarveout, 100);
    cudaFuncSetAttribute(attn_kernel, cudaFuncAttributeMaxDynamicSharedMemorySize, ATTN_SMEM);
    cudaFuncSetAttribute(attn_kernel, cudaFuncAttributePreferredSharedMemoryCarveout, 100);

    // 0. Fused pre-pass (split hidden + transpose both weights)
    prepass_kernel<<<NB_SPLIT + NB_WQ + NB_WO, 256>>>(hidden, Wqkv, Wo);

    // 1. QKV projection with fused RoPE + V-transpose epilogue
    gemm_qkv<<<dim3(QKVF / 128, (B_ * S_) / 128), 256, GSMEM>>>(
        hh, hl, wqh, wql, positions);

    // 2. Causal GQA flash attention
    attn_kernel<<<dim3(S_ / 64, NH_, B_), 128, ATTN_SMEM>>>(nullptr);

    // 3. Output projection
    gemm_bf16x3<<<dim3(H_ / 128, (B_ * S_) / 128), 256, GSMEM>>>(
        cth, ctl, woh, wol, out, B_ * S_, H_, NH_ * D_);
}